// round 8
// baseline (speedup 1.0000x reference)
#include <cuda_runtime.h>
#include <cuda_bf16.h>

typedef unsigned short u16;
typedef unsigned int   u32;
typedef unsigned long long u64;

#define NEGBIG (-1.0e9f)

#if defined(__CUDA_ARCH_FEAT_SM103_ALL) || defined(__CUDA_ARCH_FEAT_SM100_ALL)
#define HAS_TCGEN05 1
#else
#define HAS_TCGEN05 0
#endif

// ---------------- device scratch (allocation-free rule) --------------------
__device__ u16 g_wt_hi[4u*1024u*1024u];   // 4 weights, transposed [n][k]
__device__ u16 g_wt_lo[4u*1024u*1024u];
__device__ u16 g_a_hi[16777216];          // activation staging (reused q,k,v)
__device__ u16 g_a_lo[16777216];
__device__ u16 g_qh_hi[16777216];         // [bsh][l][64]
__device__ u16 g_qh_lo[16777216];
__device__ u16 g_kh_hi[16777216];
__device__ u16 g_kh_lo[16777216];
__device__ u16 g_vt_hi[16777216];         // [bsh][d=64][l=1024]
__device__ u16 g_vt_lo[16777216];
__device__ u16 g_p_hi[268435456];         // unnormalized exp probs bf16 hi/lo
__device__ u16 g_p_lo[268435456];
__device__ float g_psum[2097152];         // [bsh][row][8] partial row sums
__device__ float g_rinv[262144];          // [bsh][row] 1/rowsum
__device__ u16 g_ctx_hi[16777216];        // merged [bs*L+q][1024]
__device__ u16 g_ctx_lo[16777216];

// ---------------- helpers --------------------------------------------------
__device__ __forceinline__ u16 f2b(float x){
    return __bfloat16_as_ushort(__float2bfloat16_rn(x));
}
__device__ __forceinline__ float b2f(u16 u){
    return __bfloat162float(__ushort_as_bfloat16(u));
}
__device__ __forceinline__ u32 pack2(float a, float b){
    return (u32)f2b(a) | ((u32)f2b(b) << 16);
}
__device__ __forceinline__ unsigned smem_u32p(const void* p){
    unsigned a;
    asm("{ .reg .u64 t; cvta.to.shared.u64 t, %1; cvt.u32.u64 %0, t; }"
        : "=r"(a) : "l"(p));
    return a;
}
__device__ __forceinline__ void cpa16(unsigned dst, const void* src){
    asm volatile("cp.async.cg.shared.global [%0], [%1], 16;" :: "r"(dst), "l"(src));
}
#define CPA_COMMIT() asm volatile("cp.async.commit_group;" ::: "memory")
template<int N> __device__ __forceinline__ void cpa_wait(){
    asm volatile("cp.async.wait_group %0;" :: "n"(N) : "memory");
}

#if HAS_TCGEN05
__device__ __forceinline__ unsigned elect1(){
    unsigned p;
    asm volatile("{ .reg .pred P; elect.sync _|P, 0xFFFFFFFF; selp.b32 %0, 1, 0, P; }"
                 : "=r"(p));
    return p;
}
#define MBAR_INIT(a, c) \
    asm volatile("mbarrier.init.shared.b64 [%0], %1;" :: "r"(a), "r"(c) : "memory")
#define MBAR_INVAL(a) \
    asm volatile("mbarrier.inval.shared.b64 [%0];" :: "r"(a) : "memory")
__device__ __forceinline__ void mbar_wait(unsigned a, unsigned ph){
    asm volatile(
        "{\n\t.reg .pred P;\n"
        "W%=:\n\t"
        "mbarrier.try_wait.parity.acquire.cta.shared::cta.b64 P, [%0], %1, 0x989680;\n\t"
        "@P bra D%=;\n\t"
        "bra W%=;\n"
        "D%=:\n\t}"
        :: "r"(a), "r"(ph) : "memory");
}
#define TC_ALLOC(sa, n) \
    asm volatile("tcgen05.alloc.cta_group::1.sync.aligned.shared::cta.b32 [%0], %1;" \
                 :: "r"(sa), "r"(n) : "memory")
#define TC_DEALLOC(t, n) \
    asm volatile("tcgen05.dealloc.cta_group::1.sync.aligned.b32 %0, %1;" :: "r"(t), "r"(n))
#define TC_COMMIT(mb) \
    asm volatile("tcgen05.commit.cta_group::1.mbarrier::arrive::one.shared::cluster.b64 [%0];" \
                 :: "r"(mb) : "memory")
#define TC_FENCE_AFTER()  asm volatile("tcgen05.fence::after_thread_sync;" ::: "memory")
#define TC_FENCE_BEFORE() asm volatile("tcgen05.fence::before_thread_sync;" ::: "memory")
#define TC_WAITLD()       asm volatile("tcgen05.wait::ld.sync.aligned;" ::: "memory")
#define FENCE_ASYNC()     asm volatile("fence.proxy.async.shared::cta;" ::: "memory")

#define TC_LD32(r, addr) \
    asm volatile( \
        "tcgen05.ld.sync.aligned.32x32b.x32.b32 " \
        "{%0, %1, %2, %3, %4, %5, %6, %7, " \
        " %8, %9, %10, %11, %12, %13, %14, %15, " \
        " %16, %17, %18, %19, %20, %21, %22, %23, " \
        " %24, %25, %26, %27, %28, %29, %30, %31}, [%32];" \
        : "=r"((r)[0]),  "=r"((r)[1]),  "=r"((r)[2]),  "=r"((r)[3]), \
          "=r"((r)[4]),  "=r"((r)[5]),  "=r"((r)[6]),  "=r"((r)[7]), \
          "=r"((r)[8]),  "=r"((r)[9]),  "=r"((r)[10]), "=r"((r)[11]), \
          "=r"((r)[12]), "=r"((r)[13]), "=r"((r)[14]), "=r"((r)[15]), \
          "=r"((r)[16]), "=r"((r)[17]), "=r"((r)[18]), "=r"((r)[19]), \
          "=r"((r)[20]), "=r"((r)[21]), "=r"((r)[22]), "=r"((r)[23]), \
          "=r"((r)[24]), "=r"((r)[25]), "=r"((r)[26]), "=r"((r)[27]), \
          "=r"((r)[28]), "=r"((r)[29]), "=r"((r)[30]), "=r"((r)[31]) \
        : "r"(addr))

// SW128 K-major descriptor (LBO=1, SBO=64, version=1, layout=SW128)
__device__ __forceinline__ u64 mk_desc(unsigned addr){
    const u64 base = (2ull << 61) | (1ull << 46) | (64ull << 32) | (1ull << 16);
    return base | ((u64)(addr >> 4) & 0x3FFFull);
}
__device__ __forceinline__ void mma_ss(unsigned d, u64 a, u64 b, u32 idesc, u32 en){
    asm volatile(
        "{\n\t.reg .pred p;\n\t"
        "setp.ne.u32 p, %4, 0;\n\t"
        "tcgen05.mma.cta_group::1.kind::f16 [%0], %1, %2, %3, {%5, %5, %5, %5}, p;\n\t}"
        :: "r"(d), "l"(a), "l"(b), "r"(idesc), "r"(en), "r"(0u) : "memory");
}
#else
__device__ __forceinline__ void ldmx4(u32& r0, u32& r1, u32& r2, u32& r3, unsigned a){
    asm volatile("ldmatrix.sync.aligned.m8n8.x4.shared.b16 {%0,%1,%2,%3}, [%4];"
                 : "=r"(r0), "=r"(r1), "=r"(r2), "=r"(r3) : "r"(a));
}
__device__ __forceinline__ void mma16816(float* c, const u32* a, u32 b0, u32 b1){
    asm volatile(
        "mma.sync.aligned.m16n8k16.row.col.f32.bf16.bf16.f32 "
        "{%0,%1,%2,%3}, {%4,%5,%6,%7}, {%8,%9}, {%0,%1,%2,%3};"
        : "+f"(c[0]), "+f"(c[1]), "+f"(c[2]), "+f"(c[3])
        : "r"(a[0]), "r"(a[1]), "r"(a[2]), "r"(a[3]), "r"(b0), "r"(b1));
}
#endif

// ---------------------------------------------------------------------------
// GEMM, bf16 hi/lo 3-pass:  D[128 x BN] = A[128,K] . B[BN,K]^T
// A,B K-major bf16 hi/lo. Epilogue modes:
//   0: fp32 row-major + bias          1: hi/lo head-split [bs][h][l][d] + bias
//   2: hi/lo V-transpose [bsh][d][l] + bias
//   3: exp(acc*0.125 + mask*NEG) -> p hi/lo + row partial sums (no logits!)
//   4: hi/lo ctx merged [bs*L+q][1024], scaled by 1/rowsum; writes g_rinv
// tcgen05 path on sm_103a; mma.sync fallback otherwise (identical numerics).
// ---------------------------------------------------------------------------
template<int BN>
__global__ void __launch_bounds__(256) gemm_any(
    const u16* __restrict__ Ahi, const u16* __restrict__ Alo, size_t aZ,
    const u16* __restrict__ Bhi, const u16* __restrict__ Blo, size_t bZ,
    int K, int mode,
    float* __restrict__ outF, u16* __restrict__ oHi, u16* __restrict__ oLo,
    const float* __restrict__ aux)
{
    extern __shared__ char smem[];
    const int tid  = threadIdx.x;
    const int w    = tid >> 5;
    const int lane = tid & 31;
    const int m0   = blockIdx.y * 128;
    const int n0   = blockIdx.x * BN;
    const int z    = blockIdx.z;

    const u16* Ah = Ahi + (size_t)z * aZ;
    const u16* Al = Alo + (size_t)z * aZ;
    const u16* Bh = Bhi + (size_t)z * bZ;
    const u16* Bl = Blo + (size_t)z * bZ;

#if HAS_TCGEN05
    // ====================== tcgen05 path (sm_103a) =========================
    constexpr int ABYT  = 128 * 128;
    constexpr int BBYT  = BN * 128;
    constexpr int STAGE = 2 * ABYT + 2 * BBYT;
    constexpr u32 IDESC =
        (1u << 4) | (1u << 7) | (1u << 10) | ((u32)(BN / 8) << 17) | (8u << 24);
    constexpr int TCOLS = BN;

    const unsigned sb   = smem_u32p(smem);
    const unsigned mb0  = sb + 8;
    const unsigned mb1  = sb + 16;
    const unsigned buf0 = sb + 1024;

    if (w == 0){ TC_ALLOC(sb, TCOLS); }          // warp 0 only; no relinquish
    if (tid == 0){ MBAR_INIT(mb0, 1); MBAR_INIT(mb1, 1); }
    __syncthreads();
    unsigned tmem;
    asm volatile("ld.shared.b32 %0, [%1];" : "=r"(tmem) : "r"(sb));

    const int NS = K >> 6;

    auto load_stage = [&](int s){
        const unsigned bb = buf0 + (unsigned)(s & 1) * STAGE;
        const int k0 = s << 6;
#pragma unroll
        for (int it = 0; it < 4; it++){
            int idx = tid + it * 256;
            int r = idx >> 3, c = idx & 7;
            int off = r * 128 + c * 16;
            unsigned sw = (unsigned)(off ^ ((off >> 3) & 0x70));
            size_t g = (size_t)(m0 + r) * K + k0 + c * 8;
            cpa16(bb + sw,        Ah + g);
            cpa16(bb + ABYT + sw, Al + g);
        }
#pragma unroll
        for (int it = 0; it < (BN * 8) / 256; it++){
            int idx = tid + it * 256;
            int r = idx >> 3, c = idx & 7;
            int off = r * 128 + c * 16;
            unsigned sw = (unsigned)(off ^ ((off >> 3) & 0x70));
            size_t g = (size_t)(n0 + r) * K + k0 + c * 8;
            cpa16(bb + 2 * ABYT + sw,        Bh + g);
            cpa16(bb + 2 * ABYT + BBYT + sw, Bl + g);
        }
        CPA_COMMIT();
    };

    load_stage(0);
    if (NS > 1) load_stage(1);
    unsigned ph0 = 0, ph1 = 0;

    for (int s = 0; s < NS; s++){
        if (s == NS - 1) cpa_wait<0>(); else cpa_wait<1>();
        __syncthreads();

        if (w == 0 && elect1()){
            FENCE_ASYNC();
            const unsigned bb = buf0 + (unsigned)(s & 1) * STAGE;
            u64 ah = mk_desc(bb);
            u64 al = mk_desc(bb + ABYT);
            u64 bh = mk_desc(bb + 2 * ABYT);
            u64 bl = mk_desc(bb + 2 * ABYT + BBYT);
#pragma unroll
            for (int ks = 0; ks < 4; ks++)
                mma_ss(tmem, ah + 2 * ks, bh + 2 * ks, IDESC,
                       (s > 0 || ks > 0) ? 1u : 0u);
#pragma unroll
            for (int ks = 0; ks < 4; ks++)
                mma_ss(tmem, ah + 2 * ks, bl + 2 * ks, IDESC, 1u);
#pragma unroll
            for (int ks = 0; ks < 4; ks++)
                mma_ss(tmem, al + 2 * ks, bh + 2 * ks, IDESC, 1u);
            TC_COMMIT((s & 1) ? mb1 : mb0);
        }

        if (s + 2 < NS){
            if (s & 1){ mbar_wait(mb1, ph1); ph1 ^= 1; }
            else      { mbar_wait(mb0, ph0); ph0 ^= 1; }
            load_stage(s + 2);
        }
    }
    if ((NS - 1) & 1) mbar_wait(mb1, ph1);
    else              mbar_wait(mb0, ph0);
    TC_FENCE_AFTER();

    const int sub = w & 3;
    const int cb  = (BN == 128) ? (w >> 2) * 64 : 0;
    if (BN == 128 || w < 4){
        u32 dr[64];
        TC_LD32(dr,      tmem + cb);
        TC_LD32(dr + 32, tmem + cb + 32);
        TC_WAITLD();
        TC_FENCE_BEFORE();

        const int row = m0 + sub * 32 + lane;

        if (mode == 0){
            float* dst = outF + (size_t)row * 1024 + n0 + cb;
            const float* bias = aux + n0 + cb;
#pragma unroll
            for (int j = 0; j < 16; j++){
                float4 o;
                o.x = __uint_as_float(dr[j*4+0]) + bias[j*4+0];
                o.y = __uint_as_float(dr[j*4+1]) + bias[j*4+1];
                o.z = __uint_as_float(dr[j*4+2]) + bias[j*4+2];
                o.w = __uint_as_float(dr[j*4+3]) + bias[j*4+3];
                *(float4*)(dst + j*4) = o;
            }
        } else if (mode == 1){
            const int bs = row >> 10, l = row & 1023;
            const int h  = (n0 + cb) >> 6;
            const size_t base = (((size_t)(bs * 16 + h)) << 16) + ((size_t)l << 6);
            const float* bias = aux + n0 + cb;
#pragma unroll
            for (int j = 0; j < 32; j++){
                float va = __uint_as_float(dr[2*j])   + bias[2*j];
                float vb = __uint_as_float(dr[2*j+1]) + bias[2*j+1];
                *(u32*)(oHi + base + 2*j) = pack2(va, vb);
                *(u32*)(oLo + base + 2*j) =
                    pack2(va - b2f(f2b(va)), vb - b2f(f2b(vb)));
            }
        } else if (mode == 2){
            const int bs = row >> 10, l = row & 1023;
            const int h  = (n0 + cb) >> 6;
            const size_t base = ((size_t)(bs * 16 + h) * 64) * 1024 + l;
            const float* bias = aux + n0 + cb;
#pragma unroll
            for (int j = 0; j < 64; j++){
                float va = __uint_as_float(dr[j]) + bias[j];
                u16 hh = f2b(va);
                oHi[base + (size_t)j * 1024] = hh;
                oLo[base + (size_t)j * 1024] = f2b(va - b2f(hh));
            }
        } else if (mode == 3){
            // fused exp + probs write + partial row sums (no logits round-trip)
            const size_t mi = (((size_t)(z >> 4)) << 20) + ((size_t)row << 10) + n0 + cb;
            const size_t pb = ((size_t)z << 20) + ((size_t)row << 10) + n0 + cb;
            float part = 0.f;
#pragma unroll
            for (int j = 0; j < 32; j++){
                float2 m2 = *(const float2*)(aux + mi + 2*j);
                float ea = __expf(__uint_as_float(dr[2*j])   * 0.125f + m2.x * NEGBIG);
                float eb = __expf(__uint_as_float(dr[2*j+1]) * 0.125f + m2.y * NEGBIG);
                part += ea + eb;
                *(u32*)(g_p_hi + pb + 2*j) = pack2(ea, eb);
                *(u32*)(g_p_lo + pb + 2*j) =
                    pack2(ea - b2f(f2b(ea)), eb - b2f(f2b(eb)));
            }
            float* partbuf = (float*)(smem + 2048);     // stage bufs are dead now
            partbuf[(sub * 32 + lane) * 2 + (w >> 2)] = part;
            __syncthreads();
            if (w < 4){
                int rl = sub * 32 + lane;
                g_psum[((size_t)z * 1024 + row) * 8 + blockIdx.x] =
                    partbuf[rl * 2] + partbuf[rl * 2 + 1];
            }
        } else { // 4: ctx merged, normalized by rowsum; write rinv
            float ssum = 0.f;
            const float* ps = g_psum + ((size_t)z * 1024 + row) * 8;
#pragma unroll
            for (int t = 0; t < 8; t++) ssum += ps[t];
            const float inv = __frcp_rn(ssum);
            g_rinv[(size_t)z * 1024 + row] = inv;
            const size_t base =
                ((size_t)((z >> 4) * 1024 + row) << 10) + (size_t)(z & 15) * 64;
#pragma unroll
            for (int j = 0; j < 32; j++){
                float va = __uint_as_float(dr[2*j])   * inv;
                float vb = __uint_as_float(dr[2*j+1]) * inv;
                *(u32*)(oHi + base + 2*j) = pack2(va, vb);
                *(u32*)(oLo + base + 2*j) =
                    pack2(va - b2f(f2b(va)), vb - b2f(f2b(vb)));
            }
        }
    }
    __syncthreads();
    if (tid == 0){ MBAR_INVAL(mb0); MBAR_INVAL(mb1); }
    __syncthreads();
    if (w == 0) TC_DEALLOC(tmem, TCOLS);

#else
    // ====================== mma.sync fallback (R3-proven) ==================
    constexpr int WGM = (BN == 128) ? 2 : 4;
    constexpr int WGN = (BN == 128) ? 4 : 2;
    constexpr int PITCH = 40;
    constexpr int ASZ = 128 * PITCH;
    constexpr int BSZ = BN * PITCH;
    constexpr int STAGE = 2 * ASZ + 2 * BSZ;
    constexpr int WTM = 128 / WGM;
    constexpr int WTN = BN / WGN;
    constexpr int MT = WTM / 16;
    constexpr int NT16 = WTN / 16;

    const unsigned sbase = smem_u32p(smem);

    const int wm = (w / WGN) * WTM;
    const int wn = (w % WGN) * WTN;
    const int lrow = (lane & 7) + ((lane >> 3) & 1) * 8;
    const int lcol = (lane >> 4) * 8;

    float acc[MT][NT16 * 2][4];
#pragma unroll
    for (int i = 0; i < MT; i++)
#pragma unroll
        for (int j = 0; j < NT16 * 2; j++)
#pragma unroll
            for (int t = 0; t < 4; t++) acc[i][j][t] = 0.f;

    auto load_stage = [&](int s){
        const int k0 = s << 5;
        const unsigned sd = sbase + (unsigned)((s & 1) * STAGE) * 2u;
#pragma unroll
        for (int it = 0; it < 2; it++){
            int idx = tid + it * 256;
            int r = idx >> 2, c = idx & 3;
            size_t g = (size_t)(m0 + r) * K + k0 + c * 8;
            unsigned d = sd + (unsigned)(r * PITCH + c * 8) * 2u;
            cpa16(d, Ah + g);
            cpa16(d + ASZ * 2, Al + g);
        }
#pragma unroll
        for (int it = 0; it < (BN * 4) / 256; it++){
            int idx = tid + it * 256;
            int r = idx >> 2, c = idx & 3;
            size_t g = (size_t)(n0 + r) * K + k0 + c * 8;
            unsigned d = sd + (unsigned)(2 * ASZ + r * PITCH + c * 8) * 2u;
            cpa16(d, Bh + g);
            cpa16(d + BSZ * 2, Bl + g);
        }
        CPA_COMMIT();
    };

    const int NS = K >> 5;
    load_stage(0);

    for (int s = 0; s < NS; s++){
        if (s + 1 < NS){ load_stage(s + 1); cpa_wait<1>(); }
        else           { cpa_wait<0>(); }
        __syncthreads();

        const unsigned sd = sbase + (unsigned)((s & 1) * STAGE) * 2u;
#pragma unroll
        for (int k16 = 0; k16 < 2; k16++){
            const int kc = k16 * 16 + lcol;
            u32 ah[MT][4], al[MT][4], bh[NT16][4], bl[NT16][4];
#pragma unroll
            for (int mt = 0; mt < MT; mt++){
                unsigned a = sd + (unsigned)((wm + mt * 16 + lrow) * PITCH + kc) * 2u;
                ldmx4(ah[mt][0], ah[mt][1], ah[mt][2], ah[mt][3], a);
                ldmx4(al[mt][0], al[mt][1], al[mt][2], al[mt][3], a + ASZ * 2);
            }
#pragma unroll
            for (int nt = 0; nt < NT16; nt++){
                unsigned a = sd + (unsigned)(2 * ASZ + (wn + nt * 16 + lrow) * PITCH + kc) * 2u;
                ldmx4(bh[nt][0], bh[nt][1], bh[nt][2], bh[nt][3], a);
                ldmx4(bl[nt][0], bl[nt][1], bl[nt][2], bl[nt][3], a + BSZ * 2);
            }
#pragma unroll
            for (int mt = 0; mt < MT; mt++)
#pragma unroll
                for (int nt = 0; nt < NT16; nt++){
                    mma16816(acc[mt][2*nt],   ah[mt], bh[nt][0], bh[nt][2]);
                    mma16816(acc[mt][2*nt+1], ah[mt], bh[nt][1], bh[nt][3]);
                    mma16816(acc[mt][2*nt],   ah[mt], bl[nt][0], bl[nt][2]);
                    mma16816(acc[mt][2*nt+1], ah[mt], bl[nt][1], bl[nt][3]);
                    mma16816(acc[mt][2*nt],   al[mt], bh[nt][0], bh[nt][2]);
                    mma16816(acc[mt][2*nt+1], al[mt], bh[nt][1], bh[nt][3]);
                }
        }
        __syncthreads();
    }

    auto store_pair = [&](int row, int col, float va, float vb){
        if (mode == 0){
            float2 o; o.x = va + aux[col]; o.y = vb + aux[col + 1];
            *(float2*)(outF + (size_t)row * 1024 + col) = o;
        } else if (mode == 1){
            va += aux[col]; vb += aux[col + 1];
            int bs = row >> 10, l = row & 1023, h = col >> 6, d = col & 63;
            size_t idx = (((size_t)(bs * 16 + h)) << 16) + ((size_t)l << 6) + d;
            *(u32*)(oHi + idx) = pack2(va, vb);
            *(u32*)(oLo + idx) = pack2(va - b2f(f2b(va)), vb - b2f(f2b(vb)));
        } else if (mode == 2){
            va += aux[col]; vb += aux[col + 1];
            int bs = row >> 10, l = row & 1023, h = col >> 6, d = col & 63;
            size_t base = ((size_t)(bs * 16 + h) * 64 + d) * 1024 + l;
            u16 h0 = f2b(va), h1 = f2b(vb);
            oHi[base] = h0;        oHi[base + 1024] = h1;
            oLo[base] = f2b(va - b2f(h0));
            oLo[base + 1024] = f2b(vb - b2f(h1));
        } else if (mode == 3){
            size_t mi = (((size_t)(z >> 4)) << 20) + ((size_t)row << 10) + col;
            float2 m2 = *(const float2*)(aux + mi);
            float ea = __expf(va * 0.125f + m2.x * NEGBIG);
            float eb = __expf(vb * 0.125f + m2.y * NEGBIG);
            size_t pb = ((size_t)z << 20) + ((size_t)row << 10) + col;
            *(u32*)(g_p_hi + pb) = pack2(ea, eb);
            *(u32*)(g_p_lo + pb) = pack2(ea - b2f(f2b(ea)), eb - b2f(f2b(eb)));
            atomicAdd(&g_psum[((size_t)z * 1024 + row) * 8 + blockIdx.x], ea + eb);
        } else {
            float ssum = 0.f;
            const float* ps = g_psum + ((size_t)z * 1024 + row) * 8;
#pragma unroll
            for (int t = 0; t < 8; t++) ssum += ps[t];
            float inv = __frcp_rn(ssum);
            if (col == 0) g_rinv[(size_t)z * 1024 + row] = inv;
            va *= inv; vb *= inv;
            size_t idx = ((size_t)((z >> 4) * 1024 + row) << 10) + (size_t)(z & 15) * 64 + col;
            *(u32*)(oHi + idx) = pack2(va, vb);
            *(u32*)(oLo + idx) = pack2(va - b2f(f2b(va)), vb - b2f(f2b(vb)));
        }
    };

#pragma unroll
    for (int mt = 0; mt < MT; mt++)
#pragma unroll
        for (int nt8 = 0; nt8 < NT16 * 2; nt8++){
            int r0 = m0 + wm + mt * 16 + (lane >> 2);
            int c0 = n0 + wn + nt8 * 8 + (lane & 3) * 2;
            store_pair(r0,     c0, acc[mt][nt8][0], acc[mt][nt8][1]);
            store_pair(r0 + 8, c0, acc[mt][nt8][2], acc[mt][nt8][3]);
        }
#endif
}

// ---------------------------------------------------------------------------
// zero g_psum (needed only for the fallback's atomics; harmless otherwise)
// ---------------------------------------------------------------------------
__global__ __launch_bounds__(256) void zero_psum()
{
    const int i = blockIdx.x * 256 + threadIdx.x;
    ((float4*)g_psum)[i] = make_float4(0.f, 0.f, 0.f, 0.f);
}

// ---------------------------------------------------------------------------
// fp32 -> bf16 hi/lo
// ---------------------------------------------------------------------------
__global__ __launch_bounds__(256) void conv_act(
    const float* __restrict__ in, u16* __restrict__ hi, u16* __restrict__ lo)
{
    const int i = blockIdx.x * 256 + threadIdx.x;
    float4 v = ((const float4*)in)[i];
    u32 h0 = pack2(v.x, v.y), h1 = pack2(v.z, v.w);
    ((u32*)hi)[i * 2]     = h0;
    ((u32*)hi)[i * 2 + 1] = h1;
    ((u32*)lo)[i * 2]     = pack2(v.x - b2f((u16)h0), v.y - b2f((u16)(h0 >> 16)));
    ((u32*)lo)[i * 2 + 1] = pack2(v.z - b2f((u16)h1), v.w - b2f((u16)(h1 >> 16)));
}

// ---------------------------------------------------------------------------
// W[k][n] fp32 -> WT[n][k] bf16 hi/lo
// ---------------------------------------------------------------------------
__global__ __launch_bounds__(256) void conv_wT(
    const float* __restrict__ W, u16* __restrict__ hi, u16* __restrict__ lo)
{
    __shared__ float tile[32][33];
    const int tx = threadIdx.x, ty = threadIdx.y;
    const int kb = blockIdx.y * 32, nb = blockIdx.x * 32;
#pragma unroll
    for (int i = 0; i < 4; i++)
        tile[ty + i * 8][tx] = W[(size_t)(kb + ty + i * 8) * 1024 + nb + tx];
    __syncthreads();
#pragma unroll
    for (int i = 0; i < 4; i++){
        int n = nb + ty + i * 8, k = kb + tx;
        float v = tile[tx][ty + i * 8];
        u16 h = f2b(v);
        hi[(size_t)n * 1024 + k] = h;
        lo[(size_t)n * 1024 + k] = f2b(v - b2f(h));
    }
}

// ---------------------------------------------------------------------------
// attn_mean over heads: mean_h( p_h * rinv_h ) / 16
// ---------------------------------------------------------------------------
__global__ __launch_bounds__(256) void head_mean_kernel(float* __restrict__ outm)
{
    const int i = blockIdx.x * 256 + threadIdx.x;
    const int elem = i * 2;
    const int bs = elem >> 20, rem = elem & 0xFFFFF;
    const int q  = rem >> 10;
    float s0 = 0.f, s1 = 0.f;
#pragma unroll
    for (int h = 0; h < 16; h++){
        const int zz = bs * 16 + h;
        size_t u = ((size_t)zz << 19) + (rem >> 1);
        u32 uh = ((const u32*)g_p_hi)[u];
        u32 ul = ((const u32*)g_p_lo)[u];
        float inv = g_rinv[(size_t)zz * 1024 + q];
        s0 += (b2f((u16)uh) + b2f((u16)ul)) * inv;
        s1 += (b2f((u16)(uh >> 16)) + b2f((u16)(ul >> 16))) * inv;
    }
    float2 o; o.x = s0 * 0.0625f; o.y = s1 * 0.0625f;
    *(float2*)(outm + elem) = o;
}

// ---------------------------------------------------------------------------
extern "C" void kernel_launch(void* const* d_in, const int* in_sizes, int n_in,
                              void* d_out, int out_size)
{
    const float* q    = (const float*)d_in[0];
    const float* k    = (const float*)d_in[1];
    const float* v    = (const float*)d_in[2];
    const float* mask = (const float*)d_in[3];
    const float* wq   = (const float*)d_in[4];
    const float* bq   = (const float*)d_in[5];
    const float* wk   = (const float*)d_in[6];
    const float* bk   = (const float*)d_in[7];
    const float* wv   = (const float*)d_in[8];
    const float* bv   = (const float*)d_in[9];
    const float* wo   = (const float*)d_in[10];
    const float* bo   = (const float*)d_in[11];

    float* out       = (float*)d_out;
    float* attn_mean = out + 16777216;

    u16 *wtH, *wtL, *aH, *aL, *qhH, *qhL, *khH, *khL, *vtH, *vtL, *pH, *pL, *cxH, *cxL;
    cudaGetSymbolAddress((void**)&wtH, g_wt_hi);
    cudaGetSymbolAddress((void**)&wtL, g_wt_lo);
    cudaGetSymbolAddress((void**)&aH,  g_a_hi);
    cudaGetSymbolAddress((void**)&aL,  g_a_lo);
    cudaGetSymbolAddress((void**)&qhH, g_qh_hi);
    cudaGetSymbolAddress((void**)&qhL, g_qh_lo);
    cudaGetSymbolAddress((void**)&khH, g_kh_hi);
    cudaGetSymbolAddress((void**)&khL, g_kh_lo);
    cudaGetSymbolAddress((void**)&vtH, g_vt_hi);
    cudaGetSymbolAddress((void**)&vtL, g_vt_lo);
    cudaGetSymbolAddress((void**)&pH,  g_p_hi);
    cudaGetSymbolAddress((void**)&pL,  g_p_lo);
    cudaGetSymbolAddress((void**)&cxH, g_ctx_hi);
    cudaGetSymbolAddress((void**)&cxL, g_ctx_lo);

    constexpr int SMEM_BIG   = 1024 + 2 * (2 * 128 * 128 + 2 * 128 * 128); // 132096
    constexpr int SMEM_SMALL = 1024 + 2 * (2 * 128 * 128 + 2 * 64 * 128);  //  99328
    cudaFuncSetAttribute(gemm_any<128>,
                         cudaFuncAttributeMaxDynamicSharedMemorySize, SMEM_BIG);
    cudaFuncSetAttribute(gemm_any<64>,
                         cudaFuncAttributeMaxDynamicSharedMemorySize, SMEM_SMALL);

    dim3 wtg(32, 32);
    dim3 wtb(32, 8);
    conv_wT<<<wtg, wtb>>>(wq, wtH + 0u,       wtL + 0u);
    conv_wT<<<wtg, wtb>>>(wk, wtH + 1048576u, wtL + 1048576u);
    conv_wT<<<wtg, wtb>>>(wv, wtH + 2097152u, wtL + 2097152u);
    conv_wT<<<wtg, wtb>>>(wo, wtH + 3145728u, wtL + 3145728u);
    zero_psum<<<2048, 256>>>();

    dim3 projGrid(8, 128, 1);

    // Q projection -> head-split
    conv_act<<<16384, 256>>>(q, aH, aL);
    gemm_any<128><<<projGrid, 256, SMEM_BIG>>>(
        aH, aL, 0, wtH + 0u, wtL + 0u, 0, 1024, 1, nullptr, qhH, qhL, bq);
    // K projection
    conv_act<<<16384, 256>>>(k, aH, aL);
    gemm_any<128><<<projGrid, 256, SMEM_BIG>>>(
        aH, aL, 0, wtH + 1048576u, wtL + 1048576u, 0, 1024, 1, nullptr, khH, khL, bk);
    // V projection -> transposed [bsh][d][l]
    conv_act<<<16384, 256>>>(v, aH, aL);
    gemm_any<128><<<projGrid, 256, SMEM_BIG>>>(
        aH, aL, 0, wtH + 2097152u, wtL + 2097152u, 0, 1024, 2, nullptr, vtH, vtL, bv);

    // QK^T + exp + mask fused -> unnormalized probs + partial row sums
    gemm_any<128><<<dim3(8, 8, 256), 256, SMEM_BIG>>>(
        qhH, qhL, 65536, khH, khL, 65536, 64, 3, nullptr, nullptr, nullptr, mask);

    // ctx = (P @ V) * (1/rowsum); also writes g_rinv
    gemm_any<64><<<dim3(1, 8, 256), 256, SMEM_SMALL>>>(
        pH, pL, (size_t)1 << 20, vtH, vtL, 65536, 1024, 4, nullptr, cxH, cxL, nullptr);

    // attn_mean (needs g_rinv from PV)
    head_mean_kernel<<<32768, 256>>>(attn_mean);

    // out projection (fp32 + bias)
    gemm_any<128><<<projGrid, 256, SMEM_BIG>>>(
        cxH, cxL, 0, wtH + 3145728u, wtL + 3145728u, 0, 1024, 0, out, nullptr, nullptr, bo);
}

// round 9
// speedup vs baseline: 1.7183x; 1.7183x over previous
#include <cuda_runtime.h>
#include <cuda_bf16.h>
#include <cuda_fp16.h>

typedef unsigned short u16;
typedef unsigned int   u32;
typedef unsigned long long u64;

#define NEGBIG (-1.0e9f)

#if defined(__CUDA_ARCH_FEAT_SM103_ALL) || defined(__CUDA_ARCH_FEAT_SM100_ALL)
#define HAS_TCGEN05 1
#else
#define HAS_TCGEN05 0
#endif

// ---------------- device scratch (allocation-free rule) --------------------
__device__ u16 g_wt_hi[4u*1024u*1024u];   // 4 weights, transposed [n][k] bf16
__device__ u16 g_wt_lo[4u*1024u*1024u];
__device__ u16 g_a_hi[16777216];          // activation staging bf16 (reused)
__device__ u16 g_a_lo[16777216];
__device__ u16 g_qh_hi[16777216];         // [bsh][l][64] bf16
__device__ u16 g_qh_lo[16777216];
__device__ u16 g_kh_hi[16777216];
__device__ u16 g_kh_lo[16777216];
__device__ u16 g_vt_hi[16777216];         // [bsh][d=64][l=1024] fp16
__device__ u16 g_vt_lo[16777216];
__device__ u16 g_p[268435456];            // unnormalized exp probs fp16
__device__ float g_psum[2097152];         // [bsh][row][8] partial row sums
__device__ float g_rinv[262144];          // [bsh][row] 1/rowsum
__device__ u16 g_ctx_hi[16777216];        // merged [bs*L+q][1024] bf16
__device__ u16 g_ctx_lo[16777216];

// ---------------- helpers --------------------------------------------------
__device__ __forceinline__ u16 f2b(float x){
    return __bfloat16_as_ushort(__float2bfloat16_rn(x));
}
__device__ __forceinline__ float b2f(u16 u){
    return __bfloat162float(__ushort_as_bfloat16(u));
}
__device__ __forceinline__ u32 pack2(float a, float b){
    return (u32)f2b(a) | ((u32)f2b(b) << 16);
}
__device__ __forceinline__ u16 f2h(float x){
    return __half_as_ushort(__float2half_rn(x));
}
__device__ __forceinline__ float h2f(u16 u){
    return __half2float(__ushort_as_half(u));
}
__device__ __forceinline__ u32 pack2h(float a, float b){
    return (u32)f2h(a) | ((u32)f2h(b) << 16);
}
__device__ __forceinline__ unsigned smem_u32p(const void* p){
    unsigned a;
    asm("{ .reg .u64 t; cvta.to.shared.u64 t, %1; cvt.u32.u64 %0, t; }"
        : "=r"(a) : "l"(p));
    return a;
}
__device__ __forceinline__ void cpa16(unsigned dst, const void* src){
    asm volatile("cp.async.cg.shared.global [%0], [%1], 16;" :: "r"(dst), "l"(src));
}
#define CPA_COMMIT() asm volatile("cp.async.commit_group;" ::: "memory")
template<int N> __device__ __forceinline__ void cpa_wait(){
    asm volatile("cp.async.wait_group %0;" :: "n"(N) : "memory");
}

#if HAS_TCGEN05
__device__ __forceinline__ unsigned elect1(){
    unsigned p;
    asm volatile("{ .reg .pred P; elect.sync _|P, 0xFFFFFFFF; selp.b32 %0, 1, 0, P; }"
                 : "=r"(p));
    return p;
}
#define MBAR_INIT(a, c) \
    asm volatile("mbarrier.init.shared.b64 [%0], %1;" :: "r"(a), "r"(c) : "memory")
#define MBAR_INVAL(a) \
    asm volatile("mbarrier.inval.shared.b64 [%0];" :: "r"(a) : "memory")
__device__ __forceinline__ void mbar_wait(unsigned a, unsigned ph){
    asm volatile(
        "{\n\t.reg .pred P;\n"
        "W%=:\n\t"
        "mbarrier.try_wait.parity.acquire.cta.shared::cta.b64 P, [%0], %1, 0x989680;\n\t"
        "@P bra D%=;\n\t"
        "bra W%=;\n"
        "D%=:\n\t}"
        :: "r"(a), "r"(ph) : "memory");
}
#define TC_ALLOC(sa, n) \
    asm volatile("tcgen05.alloc.cta_group::1.sync.aligned.shared::cta.b32 [%0], %1;" \
                 :: "r"(sa), "r"(n) : "memory")
#define TC_DEALLOC(t, n) \
    asm volatile("tcgen05.dealloc.cta_group::1.sync.aligned.b32 %0, %1;" :: "r"(t), "r"(n))
#define TC_COMMIT(mb) \
    asm volatile("tcgen05.commit.cta_group::1.mbarrier::arrive::one.shared::cluster.b64 [%0];" \
                 :: "r"(mb) : "memory")
#define TC_FENCE_AFTER()  asm volatile("tcgen05.fence::after_thread_sync;" ::: "memory")
#define TC_FENCE_BEFORE() asm volatile("tcgen05.fence::before_thread_sync;" ::: "memory")
#define TC_WAITLD()       asm volatile("tcgen05.wait::ld.sync.aligned;" ::: "memory")
#define FENCE_ASYNC()     asm volatile("fence.proxy.async.shared::cta;" ::: "memory")

#define TC_LD32(r, addr) \
    asm volatile( \
        "tcgen05.ld.sync.aligned.32x32b.x32.b32 " \
        "{%0, %1, %2, %3, %4, %5, %6, %7, " \
        " %8, %9, %10, %11, %12, %13, %14, %15, " \
        " %16, %17, %18, %19, %20, %21, %22, %23, " \
        " %24, %25, %26, %27, %28, %29, %30, %31}, [%32];" \
        : "=r"((r)[0]),  "=r"((r)[1]),  "=r"((r)[2]),  "=r"((r)[3]), \
          "=r"((r)[4]),  "=r"((r)[5]),  "=r"((r)[6]),  "=r"((r)[7]), \
          "=r"((r)[8]),  "=r"((r)[9]),  "=r"((r)[10]), "=r"((r)[11]), \
          "=r"((r)[12]), "=r"((r)[13]), "=r"((r)[14]), "=r"((r)[15]), \
          "=r"((r)[16]), "=r"((r)[17]), "=r"((r)[18]), "=r"((r)[19]), \
          "=r"((r)[20]), "=r"((r)[21]), "=r"((r)[22]), "=r"((r)[23]), \
          "=r"((r)[24]), "=r"((r)[25]), "=r"((r)[26]), "=r"((r)[27]), \
          "=r"((r)[28]), "=r"((r)[29]), "=r"((r)[30]), "=r"((r)[31]) \
        : "r"(addr))

// SW128 K-major descriptor (LBO=1, SBO=64, version=1, layout=SW128)
__device__ __forceinline__ u64 mk_desc(unsigned addr){
    const u64 base = (2ull << 61) | (1ull << 46) | (64ull << 32) | (1ull << 16);
    return base | ((u64)(addr >> 4) & 0x3FFFull);
}
__device__ __forceinline__ void mma_ss(unsigned d, u64 a, u64 b, u32 idesc, u32 en){
    asm volatile(
        "{\n\t.reg .pred p;\n\t"
        "setp.ne.u32 p, %4, 0;\n\t"
        "tcgen05.mma.cta_group::1.kind::f16 [%0], %1, %2, %3, {%5, %5, %5, %5}, p;\n\t}"
        :: "r"(d), "l"(a), "l"(b), "r"(idesc), "r"(en), "r"(0u) : "memory");
}
#else
__device__ __forceinline__ void ldmx4(u32& r0, u32& r1, u32& r2, u32& r3, unsigned a){
    asm volatile("ldmatrix.sync.aligned.m8n8.x4.shared.b16 {%0,%1,%2,%3}, [%4];"
                 : "=r"(r0), "=r"(r1), "=r"(r2), "=r"(r3) : "r"(a));
}
__device__ __forceinline__ void mma16816(float* c, const u32* a, u32 b0, u32 b1){
    asm volatile(
        "mma.sync.aligned.m16n8k16.row.col.f32.bf16.bf16.f32 "
        "{%0,%1,%2,%3}, {%4,%5,%6,%7}, {%8,%9}, {%0,%1,%2,%3};"
        : "+f"(c[0]), "+f"(c[1]), "+f"(c[2]), "+f"(c[3])
        : "r"(a[0]), "r"(a[1]), "r"(a[2]), "r"(a[3]), "r"(b0), "r"(b1));
}
#endif

// ---------------------------------------------------------------------------
// GEMM:  D[128 x BN] = A[128,K] . B[BN,K]^T   (K-major operands)
// DT: 1=bf16 operands, 0=fp16 operands.
// APASS: 2 = A hi/lo (3-pass hh+hl+lh), 1 = A single (2-pass A*Bh + A*Bl).
// Epilogue modes:
//   0: fp32 row-major + bias          1: bf16 hi/lo head-split + bias (staged)
//   2: fp16 hi/lo V-transpose [bsh][d][l] + bias (naturally coalesced)
//   3: exp(acc*0.125+mask*NEG) -> fp16 probs (staged) + row partial sums
//   4: bf16 hi/lo ctx merged, scaled by 1/rowsum (staged); writes g_rinv
// ---------------------------------------------------------------------------
template<int BN, int DT, int APASS>
__global__ void __launch_bounds__(256) gemm_any(
    const u16* __restrict__ Ahi, const u16* __restrict__ Alo, size_t aZ,
    const u16* __restrict__ Bhi, const u16* __restrict__ Blo, size_t bZ,
    int K, int mode,
    float* __restrict__ outF, u16* __restrict__ oHi, u16* __restrict__ oLo,
    const float* __restrict__ aux)
{
    extern __shared__ char smem[];
    const int tid  = threadIdx.x;
    const int w    = tid >> 5;
    const int lane = tid & 31;
    const int m0   = blockIdx.y * 128;
    const int n0   = blockIdx.x * BN;
    const int z    = blockIdx.z;

    const u16* Ah = Ahi + (size_t)z * aZ;
    const u16* Al = (APASS == 2) ? (Alo + (size_t)z * aZ) : Ahi;
    const u16* Bh = Bhi + (size_t)z * bZ;
    const u16* Bl = Blo + (size_t)z * bZ;

#if HAS_TCGEN05
    // ====================== tcgen05 path (sm_103a) =========================
    constexpr int ABYT  = 128 * 128;
    constexpr int BBYT  = BN * 128;
    constexpr int BOFF  = APASS * ABYT;
    constexpr int STAGE = APASS * ABYT + 2 * BBYT;
    constexpr u32 IDESC =
        (1u << 4) | ((u32)DT << 7) | ((u32)DT << 10)
        | ((u32)(BN / 8) << 17) | (8u << 24);
    constexpr int TCOLS = BN;

    const unsigned sb   = smem_u32p(smem);
    const unsigned mb0  = sb + 8;
    const unsigned mb1  = sb + 16;
    const unsigned buf0 = sb + 1024;

    if (w == 0){ TC_ALLOC(sb, TCOLS); }          // warp 0 only; no relinquish
    if (tid == 0){ MBAR_INIT(mb0, 1); MBAR_INIT(mb1, 1); }
    __syncthreads();
    unsigned tmem;
    asm volatile("ld.shared.b32 %0, [%1];" : "=r"(tmem) : "r"(sb));

    const int NS = K >> 6;

    auto load_stage = [&](int s){
        const unsigned bb = buf0 + (unsigned)(s & 1) * STAGE;
        const int k0 = s << 6;
#pragma unroll
        for (int it = 0; it < 4; it++){
            int idx = tid + it * 256;
            int r = idx >> 3, c = idx & 7;
            int off = r * 128 + c * 16;
            unsigned sw = (unsigned)(off ^ ((off >> 3) & 0x70));
            size_t g = (size_t)(m0 + r) * K + k0 + c * 8;
            cpa16(bb + sw, Ah + g);
            if (APASS == 2) cpa16(bb + ABYT + sw, Al + g);
        }
#pragma unroll
        for (int it = 0; it < (BN * 8) / 256; it++){
            int idx = tid + it * 256;
            int r = idx >> 3, c = idx & 7;
            int off = r * 128 + c * 16;
            unsigned sw = (unsigned)(off ^ ((off >> 3) & 0x70));
            size_t g = (size_t)(n0 + r) * K + k0 + c * 8;
            cpa16(bb + BOFF + sw,        Bh + g);
            cpa16(bb + BOFF + BBYT + sw, Bl + g);
        }
        CPA_COMMIT();
    };

    load_stage(0);
    if (NS > 1) load_stage(1);
    unsigned ph0 = 0, ph1 = 0;

    for (int s = 0; s < NS; s++){
        if (s == NS - 1) cpa_wait<0>(); else cpa_wait<1>();
        __syncthreads();

        if (w == 0 && elect1()){
            FENCE_ASYNC();
            const unsigned bb = buf0 + (unsigned)(s & 1) * STAGE;
            u64 ah = mk_desc(bb);
            u64 al = mk_desc(bb + ABYT);
            u64 bh = mk_desc(bb + BOFF);
            u64 bl = mk_desc(bb + BOFF + BBYT);
#pragma unroll
            for (int ks = 0; ks < 4; ks++)
                mma_ss(tmem, ah + 2 * ks, bh + 2 * ks, IDESC,
                       (s > 0 || ks > 0) ? 1u : 0u);
#pragma unroll
            for (int ks = 0; ks < 4; ks++)
                mma_ss(tmem, ah + 2 * ks, bl + 2 * ks, IDESC, 1u);
            if (APASS == 2){
#pragma unroll
                for (int ks = 0; ks < 4; ks++)
                    mma_ss(tmem, al + 2 * ks, bh + 2 * ks, IDESC, 1u);
            }
            TC_COMMIT((s & 1) ? mb1 : mb0);
        }

        if (s + 2 < NS){
            if (s & 1){ mbar_wait(mb1, ph1); ph1 ^= 1; }
            else      { mbar_wait(mb0, ph0); ph0 ^= 1; }
            load_stage(s + 2);
        }
    }
    if ((NS - 1) & 1) mbar_wait(mb1, ph1);
    else              mbar_wait(mb0, ph0);
    TC_FENCE_AFTER();

    // ---- epilogue (stage buffers are dead; reuse for coalescing) ----
    const int sub = w & 3;
    const int cb  = (BN == 128) ? (w >> 2) * 64 : 0;
    u32* sbuf = (u32*)(smem + 1024) + (size_t)w * (32 * 33);   // per-warp 32x33
    float* partbuf = (float*)(smem + 1024 + 8 * 32 * 33 * 4);

    if (BN == 128 || w < 4){
        u32 dr[64];
        TC_LD32(dr,      tmem + cb);
        TC_LD32(dr + 32, tmem + cb + 32);
        TC_WAITLD();
        TC_FENCE_BEFORE();

        const int row0 = m0 + sub * 32;
        const int row  = row0 + lane;

        if (mode == 0){
            float* dst = outF + (size_t)row * 1024 + n0 + cb;
            const float* bias = aux + n0 + cb;
#pragma unroll
            for (int j = 0; j < 16; j++){
                float4 o;
                o.x = __uint_as_float(dr[j*4+0]) + bias[j*4+0];
                o.y = __uint_as_float(dr[j*4+1]) + bias[j*4+1];
                o.z = __uint_as_float(dr[j*4+2]) + bias[j*4+2];
                o.w = __uint_as_float(dr[j*4+3]) + bias[j*4+3];
                *(float4*)(dst + j*4) = o;
            }
        } else if (mode == 1){
            const float* bias = aux + n0 + cb;
            const int h = (n0 + cb) >> 6;
            u32 hiw[32], low[32];
#pragma unroll
            for (int j = 0; j < 32; j++){
                float va = __uint_as_float(dr[2*j])   + bias[2*j];
                float vb = __uint_as_float(dr[2*j+1]) + bias[2*j+1];
                hiw[j] = pack2(va, vb);
                low[j] = pack2(va - b2f(f2b(va)), vb - b2f(f2b(vb)));
            }
#pragma unroll
            for (int j = 0; j < 32; j++) sbuf[lane * 33 + j] = hiw[j];
            __syncwarp();
#pragma unroll
            for (int i = 0; i < 32; i++){
                int r = row0 + i, bs = r >> 10, l = r & 1023;
                size_t wb = (((size_t)(bs * 16 + h)) << 15) + ((size_t)l << 5);
                ((u32*)oHi)[wb + lane] = sbuf[i * 33 + lane];
            }
            __syncwarp();
#pragma unroll
            for (int j = 0; j < 32; j++) sbuf[lane * 33 + j] = low[j];
            __syncwarp();
#pragma unroll
            for (int i = 0; i < 32; i++){
                int r = row0 + i, bs = r >> 10, l = r & 1023;
                size_t wb = (((size_t)(bs * 16 + h)) << 15) + ((size_t)l << 5);
                ((u32*)oLo)[wb + lane] = sbuf[i * 33 + lane];
            }
        } else if (mode == 2){
            // lanes map to consecutive l -> already coalesced
            const int bs = row >> 10, l = row & 1023;
            const int h  = (n0 + cb) >> 6;
            const size_t base = ((size_t)(bs * 16 + h) * 64) * 1024 + l;
            const float* bias = aux + n0 + cb;
#pragma unroll
            for (int j = 0; j < 64; j++){
                float va = __uint_as_float(dr[j]) + bias[j];
                u16 hh = f2h(va);
                oHi[base + (size_t)j * 1024] = hh;
                oLo[base + (size_t)j * 1024] = f2h(va - h2f(hh));
            }
        } else if (mode == 3){
            const size_t mi = (((size_t)(z >> 4)) << 20) + ((size_t)row << 10) + n0 + cb;
            float part = 0.f;
            u32 pw[32];
#pragma unroll
            for (int j = 0; j < 32; j++){
                float2 m2 = *(const float2*)(aux + mi + 2*j);
                float ea = __expf(__uint_as_float(dr[2*j])   * 0.125f + m2.x * NEGBIG);
                float eb = __expf(__uint_as_float(dr[2*j+1]) * 0.125f + m2.y * NEGBIG);
                part += ea + eb;
                pw[j] = pack2h(ea, eb);
            }
#pragma unroll
            for (int j = 0; j < 32; j++) sbuf[lane * 33 + j] = pw[j];
            __syncwarp();
#pragma unroll
            for (int i = 0; i < 32; i++){
                size_t wb = ((size_t)z << 19) + ((size_t)(row0 + i) << 9)
                          + (size_t)((n0 + cb) >> 1);
                ((u32*)g_p)[wb + lane] = sbuf[i * 33 + lane];
            }
            partbuf[(sub * 32 + lane) * 2 + (w >> 2)] = part;
            __syncthreads();
            if (w < 4){
                int rl = sub * 32 + lane;
                g_psum[((size_t)z * 1024 + row) * 8 + blockIdx.x] =
                    partbuf[rl * 2] + partbuf[rl * 2 + 1];
            }
        } else { // 4: ctx merged, normalized; write rinv
            float ssum = 0.f;
            const float* ps = g_psum + ((size_t)z * 1024 + row) * 8;
#pragma unroll
            for (int t = 0; t < 8; t++) ssum += ps[t];
            const float inv = __frcp_rn(ssum);
            g_rinv[(size_t)z * 1024 + row] = inv;
            u32 hiw[32], low[32];
#pragma unroll
            for (int j = 0; j < 32; j++){
                float va = __uint_as_float(dr[2*j])   * inv;
                float vb = __uint_as_float(dr[2*j+1]) * inv;
                hiw[j] = pack2(va, vb);
                low[j] = pack2(va - b2f(f2b(va)), vb - b2f(f2b(vb)));
            }
#pragma unroll
            for (int j = 0; j < 32; j++) sbuf[lane * 33 + j] = hiw[j];
            __syncwarp();
#pragma unroll
            for (int i = 0; i < 32; i++){
                size_t wb = (((size_t)((z >> 4) * 1024 + row0 + i)) << 9)
                          + (size_t)(z & 15) * 32;
                ((u32*)oHi)[wb + lane] = sbuf[i * 33 + lane];
            }
            __syncwarp();
#pragma unroll
            for (int j = 0; j < 32; j++) sbuf[lane * 33 + j] = low[j];
            __syncwarp();
#pragma unroll
            for (int i = 0; i < 32; i++){
                size_t wb = (((size_t)((z >> 4) * 1024 + row0 + i)) << 9)
                          + (size_t)(z & 15) * 32;
                ((u32*)oLo)[wb + lane] = sbuf[i * 33 + lane];
            }
        }
    } else if (mode == 3){
        __syncthreads();   // match the mode-3 barrier from active warps
    }
    __syncthreads();
    if (tid == 0){ MBAR_INVAL(mb0); MBAR_INVAL(mb1); }
    __syncthreads();
    if (w == 0) TC_DEALLOC(tmem, TCOLS);

#else
    // ====================== mma.sync fallback (compile-only on non-a pass) ==
    constexpr int WGM = (BN == 128) ? 2 : 4;
    constexpr int WGN = (BN == 128) ? 4 : 2;
    constexpr int PITCH = 40;
    constexpr int ASZ = 128 * PITCH;
    constexpr int BSZ = BN * PITCH;
    constexpr int STAGE = 2 * ASZ + 2 * BSZ;
    constexpr int WTM = 128 / WGM;
    constexpr int WTN = BN / WGN;
    constexpr int MT = WTM / 16;
    constexpr int NT16 = WTN / 16;

    const unsigned sbase = smem_u32p(smem);

    const int wm = (w / WGN) * WTM;
    const int wn = (w % WGN) * WTN;
    const int lrow = (lane & 7) + ((lane >> 3) & 1) * 8;
    const int lcol = (lane >> 4) * 8;

    float acc[MT][NT16 * 2][4];
#pragma unroll
    for (int i = 0; i < MT; i++)
#pragma unroll
        for (int j = 0; j < NT16 * 2; j++)
#pragma unroll
            for (int t = 0; t < 4; t++) acc[i][j][t] = 0.f;

    auto load_stage = [&](int s){
        const int k0 = s << 5;
        const unsigned sd = sbase + (unsigned)((s & 1) * STAGE) * 2u;
#pragma unroll
        for (int it = 0; it < 2; it++){
            int idx = tid + it * 256;
            int r = idx >> 2, c = idx & 3;
            size_t g = (size_t)(m0 + r) * K + k0 + c * 8;
            unsigned d = sd + (unsigned)(r * PITCH + c * 8) * 2u;
            cpa16(d, Ah + g);
            cpa16(d + ASZ * 2, Al + g);
        }
#pragma unroll
        for (int it = 0; it < (BN * 4) / 256; it++){
            int idx = tid + it * 256;
            int r = idx >> 2, c = idx & 3;
            size_t g = (size_t)(n0 + r) * K + k0 + c * 8;
            unsigned d = sd + (unsigned)(2 * ASZ + r * PITCH + c * 8) * 2u;
            cpa16(d, Bh + g);
            cpa16(d + BSZ * 2, Bl + g);
        }
        CPA_COMMIT();
    };

    const int NS = K >> 5;
    load_stage(0);

    for (int s = 0; s < NS; s++){
        if (s + 1 < NS){ load_stage(s + 1); cpa_wait<1>(); }
        else           { cpa_wait<0>(); }
        __syncthreads();

        const unsigned sd = sbase + (unsigned)((s & 1) * STAGE) * 2u;
#pragma unroll
        for (int k16 = 0; k16 < 2; k16++){
            const int kc = k16 * 16 + lcol;
            u32 ah[MT][4], al[MT][4], bh[NT16][4], bl[NT16][4];
#pragma unroll
            for (int mt = 0; mt < MT; mt++){
                unsigned a = sd + (unsigned)((wm + mt * 16 + lrow) * PITCH + kc) * 2u;
                ldmx4(ah[mt][0], ah[mt][1], ah[mt][2], ah[mt][3], a);
                ldmx4(al[mt][0], al[mt][1], al[mt][2], al[mt][3], a + ASZ * 2);
            }
#pragma unroll
            for (int nt = 0; nt < NT16; nt++){
                unsigned a = sd + (unsigned)(2 * ASZ + (wn + nt * 16 + lrow) * PITCH + kc) * 2u;
                ldmx4(bh[nt][0], bh[nt][1], bh[nt][2], bh[nt][3], a);
                ldmx4(bl[nt][0], bl[nt][1], bl[nt][2], bl[nt][3], a + BSZ * 2);
            }
#pragma unroll
            for (int mt = 0; mt < MT; mt++)
#pragma unroll
                for (int nt = 0; nt < NT16; nt++){
                    mma16816(acc[mt][2*nt],   ah[mt], bh[nt][0], bh[nt][2]);
                    mma16816(acc[mt][2*nt+1], ah[mt], bh[nt][1], bh[nt][3]);
                    mma16816(acc[mt][2*nt],   ah[mt], bl[nt][0], bl[nt][2]);
                    mma16816(acc[mt][2*nt+1], ah[mt], bl[nt][1], bl[nt][3]);
                    if (APASS == 2){
                        mma16816(acc[mt][2*nt],   al[mt], bh[nt][0], bh[nt][2]);
                        mma16816(acc[mt][2*nt+1], al[mt], bh[nt][1], bh[nt][3]);
                    }
                }
        }
        __syncthreads();
    }

    auto store_pair = [&](int row, int col, float va, float vb){
        if (mode == 0){
            float2 o; o.x = va + aux[col]; o.y = vb + aux[col + 1];
            *(float2*)(outF + (size_t)row * 1024 + col) = o;
        } else if (mode == 1){
            va += aux[col]; vb += aux[col + 1];
            int bs = row >> 10, l = row & 1023, h = col >> 6, d = col & 63;
            size_t idx = (((size_t)(bs * 16 + h)) << 16) + ((size_t)l << 6) + d;
            *(u32*)(oHi + idx) = pack2(va, vb);
            *(u32*)(oLo + idx) = pack2(va - b2f(f2b(va)), vb - b2f(f2b(vb)));
        } else if (mode == 2){
            va += aux[col]; vb += aux[col + 1];
            int bs = row >> 10, l = row & 1023, h = col >> 6, d = col & 63;
            size_t base = ((size_t)(bs * 16 + h) * 64 + d) * 1024 + l;
            u16 h0 = f2h(va), h1 = f2h(vb);
            oHi[base] = h0;        oHi[base + 1024] = h1;
            oLo[base] = f2h(va - h2f(h0));
            oLo[base + 1024] = f2h(vb - h2f(h1));
        } else if (mode == 3){
            size_t mi = (((size_t)(z >> 4)) << 20) + ((size_t)row << 10) + col;
            float2 m2 = *(const float2*)(aux + mi);
            float ea = __expf(va * 0.125f + m2.x * NEGBIG);
            float eb = __expf(vb * 0.125f + m2.y * NEGBIG);
            size_t pb = ((size_t)z << 20) + ((size_t)row << 10) + col;
            *(u32*)(g_p + pb) = pack2h(ea, eb);
            atomicAdd(&g_psum[((size_t)z * 1024 + row) * 8 + blockIdx.x], ea + eb);
        } else {
            float ssum = 0.f;
            const float* ps = g_psum + ((size_t)z * 1024 + row) * 8;
#pragma unroll
            for (int t = 0; t < 8; t++) ssum += ps[t];
            float inv = __frcp_rn(ssum);
            if (col == 0) g_rinv[(size_t)z * 1024 + row] = inv;
            va *= inv; vb *= inv;
            size_t idx = ((size_t)((z >> 4) * 1024 + row) << 10) + (size_t)(z & 15) * 64 + col;
            *(u32*)(oHi + idx) = pack2(va, vb);
            *(u32*)(oLo + idx) = pack2(va - b2f(f2b(va)), vb - b2f(f2b(vb)));
        }
    };

#pragma unroll
    for (int mt = 0; mt < MT; mt++)
#pragma unroll
        for (int nt8 = 0; nt8 < NT16 * 2; nt8++){
            int r0 = m0 + wm + mt * 16 + (lane >> 2);
            int c0 = n0 + wn + nt8 * 8 + (lane & 3) * 2;
            store_pair(r0,     c0, acc[mt][nt8][0], acc[mt][nt8][1]);
            store_pair(r0 + 8, c0, acc[mt][nt8][2], acc[mt][nt8][3]);
        }
#endif
}

// ---------------------------------------------------------------------------
// zero g_psum (needed for fallback atomics; cheap)
// ---------------------------------------------------------------------------
__global__ __launch_bounds__(256) void zero_psum()
{
    const int i = blockIdx.x * 256 + threadIdx.x;
    ((float4*)g_psum)[i] = make_float4(0.f, 0.f, 0.f, 0.f);
}

// ---------------------------------------------------------------------------
// fp32 -> bf16 hi/lo
// ---------------------------------------------------------------------------
__global__ __launch_bounds__(256) void conv_act(
    const float* __restrict__ in, u16* __restrict__ hi, u16* __restrict__ lo)
{
    const int i = blockIdx.x * 256 + threadIdx.x;
    float4 v = ((const float4*)in)[i];
    u32 h0 = pack2(v.x, v.y), h1 = pack2(v.z, v.w);
    ((u32*)hi)[i * 2]     = h0;
    ((u32*)hi)[i * 2 + 1] = h1;
    ((u32*)lo)[i * 2]     = pack2(v.x - b2f((u16)h0), v.y - b2f((u16)(h0 >> 16)));
    ((u32*)lo)[i * 2 + 1] = pack2(v.z - b2f((u16)h1), v.w - b2f((u16)(h1 >> 16)));
}

// ---------------------------------------------------------------------------
// W[k][n] fp32 -> WT[n][k] bf16 hi/lo
// ---------------------------------------------------------------------------
__global__ __launch_bounds__(256) void conv_wT(
    const float* __restrict__ W, u16* __restrict__ hi, u16* __restrict__ lo)
{
    __shared__ float tile[32][33];
    const int tx = threadIdx.x, ty = threadIdx.y;
    const int kb = blockIdx.y * 32, nb = blockIdx.x * 32;
#pragma unroll
    for (int i = 0; i < 4; i++)
        tile[ty + i * 8][tx] = W[(size_t)(kb + ty + i * 8) * 1024 + nb + tx];
    __syncthreads();
#pragma unroll
    for (int i = 0; i < 4; i++){
        int n = nb + ty + i * 8, k = kb + tx;
        float v = tile[tx][ty + i * 8];
        u16 h = f2b(v);
        hi[(size_t)n * 1024 + k] = h;
        lo[(size_t)n * 1024 + k] = f2b(v - b2f(h));
    }
}

// ---------------------------------------------------------------------------
// attn_mean over heads: mean_h( p_h * rinv_h )
// ---------------------------------------------------------------------------
__global__ __launch_bounds__(256) void head_mean_kernel(float* __restrict__ outm)
{
    const int i = blockIdx.x * 256 + threadIdx.x;
    const int elem = i * 2;
    const int bs = elem >> 20, rem = elem & 0xFFFFF;
    const int q  = rem >> 10;
    float s0 = 0.f, s1 = 0.f;
#pragma unroll
    for (int h = 0; h < 16; h++){
        const int zz = bs * 16 + h;
        u32 up = ((const u32*)g_p)[((size_t)zz << 19) + (rem >> 1)];
        float inv = g_rinv[(size_t)zz * 1024 + q];
        s0 += h2f((u16)up) * inv;
        s1 += h2f((u16)(up >> 16)) * inv;
    }
    float2 o; o.x = s0 * 0.0625f; o.y = s1 * 0.0625f;
    *(float2*)(outm + elem) = o;
}

// ---------------------------------------------------------------------------
extern "C" void kernel_launch(void* const* d_in, const int* in_sizes, int n_in,
                              void* d_out, int out_size)
{
    const float* q    = (const float*)d_in[0];
    const float* k    = (const float*)d_in[1];
    const float* v    = (const float*)d_in[2];
    const float* mask = (const float*)d_in[3];
    const float* wq   = (const float*)d_in[4];
    const float* bq   = (const float*)d_in[5];
    const float* wk   = (const float*)d_in[6];
    const float* bk   = (const float*)d_in[7];
    const float* wv   = (const float*)d_in[8];
    const float* bv   = (const float*)d_in[9];
    const float* wo   = (const float*)d_in[10];
    const float* bo   = (const float*)d_in[11];

    float* out       = (float*)d_out;
    float* attn_mean = out + 16777216;

    u16 *wtH, *wtL, *aH, *aL, *qhH, *qhL, *khH, *khL, *vtH, *vtL, *pP, *cxH, *cxL;
    cudaGetSymbolAddress((void**)&wtH, g_wt_hi);
    cudaGetSymbolAddress((void**)&wtL, g_wt_lo);
    cudaGetSymbolAddress((void**)&aH,  g_a_hi);
    cudaGetSymbolAddress((void**)&aL,  g_a_lo);
    cudaGetSymbolAddress((void**)&qhH, g_qh_hi);
    cudaGetSymbolAddress((void**)&qhL, g_qh_lo);
    cudaGetSymbolAddress((void**)&khH, g_kh_hi);
    cudaGetSymbolAddress((void**)&khL, g_kh_lo);
    cudaGetSymbolAddress((void**)&vtH, g_vt_hi);
    cudaGetSymbolAddress((void**)&vtL, g_vt_lo);
    cudaGetSymbolAddress((void**)&pP,  g_p);
    cudaGetSymbolAddress((void**)&cxH, g_ctx_hi);
    cudaGetSymbolAddress((void**)&cxL, g_ctx_lo);

    constexpr int SMEM_BIG   = 1024 + 2 * (2 * 128 * 128 + 2 * 128 * 128); // 132096
    constexpr int SMEM_SMALL = 1024 + 2 * (1 * 128 * 128 + 2 * 64 * 128);  //  66560
    cudaFuncSetAttribute(gemm_any<128,1,2>,
                         cudaFuncAttributeMaxDynamicSharedMemorySize, SMEM_BIG);
    cudaFuncSetAttribute(gemm_any<64,0,1>,
                         cudaFuncAttributeMaxDynamicSharedMemorySize, SMEM_SMALL);

    dim3 wtg(32, 32);
    dim3 wtb(32, 8);
    conv_wT<<<wtg, wtb>>>(wq, wtH + 0u,       wtL + 0u);
    conv_wT<<<wtg, wtb>>>(wk, wtH + 1048576u, wtL + 1048576u);
    conv_wT<<<wtg, wtb>>>(wv, wtH + 2097152u, wtL + 2097152u);
    conv_wT<<<wtg, wtb>>>(wo, wtH + 3145728u, wtL + 3145728u);
    zero_psum<<<2048, 256>>>();

    dim3 projGrid(8, 128, 1);

    // Q projection -> head-split (bf16 hi/lo)
    conv_act<<<16384, 256>>>(q, aH, aL);
    gemm_any<128,1,2><<<projGrid, 256, SMEM_BIG>>>(
        aH, aL, 0, wtH + 0u, wtL + 0u, 0, 1024, 1, nullptr, qhH, qhL, bq);
    // K projection
    conv_act<<<16384, 256>>>(k, aH, aL);
    gemm_any<128,1,2><<<projGrid, 256, SMEM_BIG>>>(
        aH, aL, 0, wtH + 1048576u, wtL + 1048576u, 0, 1024, 1, nullptr, khH, khL, bk);
    // V projection -> transposed [bsh][d][l] (fp16 hi/lo)
    conv_act<<<16384, 256>>>(v, aH, aL);
    gemm_any<128,1,2><<<projGrid, 256, SMEM_BIG>>>(
        aH, aL, 0, wtH + 2097152u, wtL + 2097152u, 0, 1024, 2, nullptr, vtH, vtL, bv);

    // QK^T + exp + mask fused -> fp16 probs + partial row sums (staged stores)
    gemm_any<128,1,2><<<dim3(8, 8, 256), 256, SMEM_BIG>>>(
        qhH, qhL, 65536, khH, khL, 65536, 64, 3, nullptr, nullptr, nullptr, mask);

    // ctx = (P @ V) * (1/rowsum); fp16 probs A (2-pass); writes g_rinv
    gemm_any<64,0,1><<<dim3(1, 8, 256), 256, SMEM_SMALL>>>(
        pP, nullptr, (size_t)1 << 20, vtH, vtL, 65536, 1024, 4,
        nullptr, cxH, cxL, nullptr);

    // attn_mean
    head_mean_kernel<<<32768, 256>>>(attn_mean);

    // out projection (fp32 + bias)
    gemm_any<128,1,2><<<projGrid, 256, SMEM_BIG>>>(
        cxH, cxL, 0, wtH + 3145728u, wtL + 3145728u, 0, 1024, 0, out, nullptr, nullptr, bo);
}

// round 10
// speedup vs baseline: 2.4151x; 1.4055x over previous
#include <cuda_runtime.h>
#include <cuda_bf16.h>
#include <cuda_fp16.h>

typedef unsigned short u16;
typedef unsigned int   u32;
typedef unsigned long long u64;

#if defined(__CUDA_ARCH_FEAT_SM103_ALL) || defined(__CUDA_ARCH_FEAT_SM100_ALL)
#define HAS_TCGEN05 1
#else
#define HAS_TCGEN05 0
#endif

// ---------------- device scratch (allocation-free rule) --------------------
__device__ u16 g_wt_hi[4u*1024u*1024u];   // 4 weights, transposed [n][k] bf16
__device__ u16 g_wt_lo[4u*1024u*1024u];
__device__ u16 g_a_hi[16777216];          // activation staging bf16 (reused)
__device__ u16 g_a_lo[16777216];
__device__ u16 g_qh_hi[16777216];         // [bsh][l][64] bf16
__device__ u16 g_qh_lo[16777216];
__device__ u16 g_kh_hi[16777216];
__device__ u16 g_kh_lo[16777216];
__device__ u16 g_vt_hi[16777216];         // [bsh][d=64][l=1024] fp16
__device__ u16 g_vt_lo[16777216];
__device__ u16 g_p[268435456];            // unnormalized exp probs fp16
__device__ u32 g_mbits[524288];           // mask bitmask: [bs][row][32 words]
__device__ float g_rsum[262144];          // [bsh][row] row sums
__device__ float g_rinv[262144];          // [bsh][row] 1/rowsum
__device__ u16 g_ctx_hi[16777216];        // merged [bs*L+q][1024] bf16
__device__ u16 g_ctx_lo[16777216];

// ---------------- helpers --------------------------------------------------
__device__ __forceinline__ u16 f2b(float x){
    return __bfloat16_as_ushort(__float2bfloat16_rn(x));
}
__device__ __forceinline__ float b2f(u16 u){
    return __bfloat162float(__ushort_as_bfloat16(u));
}
__device__ __forceinline__ u32 pack2(float a, float b){
    return (u32)f2b(a) | ((u32)f2b(b) << 16);
}
__device__ __forceinline__ u16 f2h(float x){
    return __half_as_ushort(__float2half_rn(x));
}
__device__ __forceinline__ float h2f(u16 u){
    return __half2float(__ushort_as_half(u));
}
__device__ __forceinline__ u32 pack2h(float a, float b){
    return (u32)f2h(a) | ((u32)f2h(b) << 16);
}
__device__ __forceinline__ unsigned smem_u32p(const void* p){
    unsigned a;
    asm("{ .reg .u64 t; cvta.to.shared.u64 t, %1; cvt.u32.u64 %0, t; }"
        : "=r"(a) : "l"(p));
    return a;
}
__device__ __forceinline__ void cpa16(unsigned dst, const void* src){
    asm volatile("cp.async.cg.shared.global [%0], [%1], 16;" :: "r"(dst), "l"(src));
}
#define CPA_COMMIT() asm volatile("cp.async.commit_group;" ::: "memory")
template<int N> __device__ __forceinline__ void cpa_wait(){
    asm volatile("cp.async.wait_group %0;" :: "n"(N) : "memory");
}

#if HAS_TCGEN05
__device__ __forceinline__ unsigned elect1(){
    unsigned p;
    asm volatile("{ .reg .pred P; elect.sync _|P, 0xFFFFFFFF; selp.b32 %0, 1, 0, P; }"
                 : "=r"(p));
    return p;
}
#define MBAR_INIT(a, c) \
    asm volatile("mbarrier.init.shared.b64 [%0], %1;" :: "r"(a), "r"(c) : "memory")
#define MBAR_INVAL(a) \
    asm volatile("mbarrier.inval.shared.b64 [%0];" :: "r"(a) : "memory")
__device__ __forceinline__ void mbar_wait(unsigned a, unsigned ph){
    asm volatile(
        "{\n\t.reg .pred P;\n"
        "W%=:\n\t"
        "mbarrier.try_wait.parity.acquire.cta.shared::cta.b64 P, [%0], %1, 0x989680;\n\t"
        "@P bra D%=;\n\t"
        "bra W%=;\n"
        "D%=:\n\t}"
        :: "r"(a), "r"(ph) : "memory");
}
#define TC_ALLOC(sa, n) \
    asm volatile("tcgen05.alloc.cta_group::1.sync.aligned.shared::cta.b32 [%0], %1;" \
                 :: "r"(sa), "r"(n) : "memory")
#define TC_DEALLOC(t, n) \
    asm volatile("tcgen05.dealloc.cta_group::1.sync.aligned.b32 %0, %1;" :: "r"(t), "r"(n))
#define TC_COMMIT(mb) \
    asm volatile("tcgen05.commit.cta_group::1.mbarrier::arrive::one.shared::cluster.b64 [%0];" \
                 :: "r"(mb) : "memory")
#define TC_FENCE_AFTER()  asm volatile("tcgen05.fence::after_thread_sync;" ::: "memory")
#define TC_FENCE_BEFORE() asm volatile("tcgen05.fence::before_thread_sync;" ::: "memory")
#define TC_WAITLD()       asm volatile("tcgen05.wait::ld.sync.aligned;" ::: "memory")
#define FENCE_ASYNC()     asm volatile("fence.proxy.async.shared::cta;" ::: "memory")

#define TC_LD32(r, addr) \
    asm volatile( \
        "tcgen05.ld.sync.aligned.32x32b.x32.b32 " \
        "{%0, %1, %2, %3, %4, %5, %6, %7, " \
        " %8, %9, %10, %11, %12, %13, %14, %15, " \
        " %16, %17, %18, %19, %20, %21, %22, %23, " \
        " %24, %25, %26, %27, %28, %29, %30, %31}, [%32];" \
        : "=r"((r)[0]),  "=r"((r)[1]),  "=r"((r)[2]),  "=r"((r)[3]), \
          "=r"((r)[4]),  "=r"((r)[5]),  "=r"((r)[6]),  "=r"((r)[7]), \
          "=r"((r)[8]),  "=r"((r)[9]),  "=r"((r)[10]), "=r"((r)[11]), \
          "=r"((r)[12]), "=r"((r)[13]), "=r"((r)[14]), "=r"((r)[15]), \
          "=r"((r)[16]), "=r"((r)[17]), "=r"((r)[18]), "=r"((r)[19]), \
          "=r"((r)[20]), "=r"((r)[21]), "=r"((r)[22]), "=r"((r)[23]), \
          "=r"((r)[24]), "=r"((r)[25]), "=r"((r)[26]), "=r"((r)[27]), \
          "=r"((r)[28]), "=r"((r)[29]), "=r"((r)[30]), "=r"((r)[31]) \
        : "r"(addr))

// SW128 K-major descriptor (LBO=1, SBO=64, version=1, layout=SW128)
__device__ __forceinline__ u64 mk_desc(unsigned addr){
    const u64 base = (2ull << 61) | (1ull << 46) | (64ull << 32) | (1ull << 16);
    return base | ((u64)(addr >> 4) & 0x3FFFull);
}
__device__ __forceinline__ void mma_ss(unsigned d, u64 a, u64 b, u32 idesc, u32 en){
    asm volatile(
        "{\n\t.reg .pred p;\n\t"
        "setp.ne.u32 p, %4, 0;\n\t"
        "tcgen05.mma.cta_group::1.kind::f16 [%0], %1, %2, %3, {%5, %5, %5, %5}, p;\n\t}"
        :: "r"(d), "l"(a), "l"(b), "r"(idesc), "r"(en), "r"(0u) : "memory");
}
#else
__device__ __forceinline__ void ldmx4(u32& r0, u32& r1, u32& r2, u32& r3, unsigned a){
    asm volatile("ldmatrix.sync.aligned.m8n8.x4.shared.b16 {%0,%1,%2,%3}, [%4];"
                 : "=r"(r0), "=r"(r1), "=r"(r2), "=r"(r3) : "r"(a));
}
__device__ __forceinline__ void mma16816(float* c, const u32* a, u32 b0, u32 b1){
    asm volatile(
        "mma.sync.aligned.m16n8k16.row.col.f32.bf16.bf16.f32 "
        "{%0,%1,%2,%3}, {%4,%5,%6,%7}, {%8,%9}, {%0,%1,%2,%3};"
        : "+f"(c[0]), "+f"(c[1]), "+f"(c[2]), "+f"(c[3])
        : "r"(a[0]), "r"(a[1]), "r"(a[2]), "r"(a[3]), "r"(b0), "r"(b1));
}
#endif

// ---------------------------------------------------------------------------
// Generic GEMM:  D[128 x BN] = A[128,K] . B[BN,K]^T
// DT: 1=bf16, 0=fp16 operands.  APASS: 2 = A hi/lo (3-pass), 1 = A single.
// Epilogue modes:
//   0: fp32 row-major + bias          1: bf16 hi/lo head-split + bias (staged)
//   2: fp16 hi/lo V-transpose [bsh][d][l] + bias
//   4: bf16 hi/lo ctx merged, scaled by g_rinv (staged)
// ---------------------------------------------------------------------------
template<int BN, int DT, int APASS>
__global__ void __launch_bounds__(256) gemm_any(
    const u16* __restrict__ Ahi, const u16* __restrict__ Alo, size_t aZ,
    const u16* __restrict__ Bhi, const u16* __restrict__ Blo, size_t bZ,
    int K, int mode,
    float* __restrict__ outF, u16* __restrict__ oHi, u16* __restrict__ oLo,
    const float* __restrict__ aux)
{
    extern __shared__ char smem[];
    const int tid  = threadIdx.x;
    const int w    = tid >> 5;
    const int lane = tid & 31;
    const int m0   = blockIdx.y * 128;
    const int n0   = blockIdx.x * BN;
    const int z    = blockIdx.z;

    const u16* Ah = Ahi + (size_t)z * aZ;
    const u16* Al = (APASS == 2) ? (Alo + (size_t)z * aZ) : Ahi;
    const u16* Bh = Bhi + (size_t)z * bZ;
    const u16* Bl = Blo + (size_t)z * bZ;

#if HAS_TCGEN05
    constexpr int ABYT  = 128 * 128;
    constexpr int BBYT  = BN * 128;
    constexpr int BOFF  = APASS * ABYT;
    constexpr int STAGE = APASS * ABYT + 2 * BBYT;
    constexpr u32 IDESC =
        (1u << 4) | ((u32)DT << 7) | ((u32)DT << 10)
        | ((u32)(BN / 8) << 17) | (8u << 24);
    constexpr int TCOLS = BN;

    const unsigned sb   = smem_u32p(smem);
    const unsigned mb0  = sb + 8;
    const unsigned mb1  = sb + 16;
    const unsigned buf0 = sb + 1024;

    if (w == 0){ TC_ALLOC(sb, TCOLS); }
    if (tid == 0){ MBAR_INIT(mb0, 1); MBAR_INIT(mb1, 1); }
    __syncthreads();
    unsigned tmem;
    asm volatile("ld.shared.b32 %0, [%1];" : "=r"(tmem) : "r"(sb));

    const int NS = K >> 6;

    auto load_stage = [&](int s){
        const unsigned bb = buf0 + (unsigned)(s & 1) * STAGE;
        const int k0 = s << 6;
#pragma unroll
        for (int it = 0; it < 4; it++){
            int idx = tid + it * 256;
            int r = idx >> 3, c = idx & 7;
            int off = r * 128 + c * 16;
            unsigned sw = (unsigned)(off ^ ((off >> 3) & 0x70));
            size_t g = (size_t)(m0 + r) * K + k0 + c * 8;
            cpa16(bb + sw, Ah + g);
            if (APASS == 2) cpa16(bb + ABYT + sw, Al + g);
        }
#pragma unroll
        for (int it = 0; it < (BN * 8) / 256; it++){
            int idx = tid + it * 256;
            int r = idx >> 3, c = idx & 7;
            int off = r * 128 + c * 16;
            unsigned sw = (unsigned)(off ^ ((off >> 3) & 0x70));
            size_t g = (size_t)(n0 + r) * K + k0 + c * 8;
            cpa16(bb + BOFF + sw,        Bh + g);
            cpa16(bb + BOFF + BBYT + sw, Bl + g);
        }
        CPA_COMMIT();
    };

    load_stage(0);
    if (NS > 1) load_stage(1);
    unsigned ph0 = 0, ph1 = 0;

    for (int s = 0; s < NS; s++){
        if (s == NS - 1) cpa_wait<0>(); else cpa_wait<1>();
        __syncthreads();

        if (w == 0 && elect1()){
            FENCE_ASYNC();
            const unsigned bb = buf0 + (unsigned)(s & 1) * STAGE;
            u64 ah = mk_desc(bb);
            u64 al = mk_desc(bb + ABYT);
            u64 bh = mk_desc(bb + BOFF);
            u64 bl = mk_desc(bb + BOFF + BBYT);
#pragma unroll
            for (int ks = 0; ks < 4; ks++)
                mma_ss(tmem, ah + 2 * ks, bh + 2 * ks, IDESC,
                       (s > 0 || ks > 0) ? 1u : 0u);
#pragma unroll
            for (int ks = 0; ks < 4; ks++)
                mma_ss(tmem, ah + 2 * ks, bl + 2 * ks, IDESC, 1u);
            if (APASS == 2){
#pragma unroll
                for (int ks = 0; ks < 4; ks++)
                    mma_ss(tmem, al + 2 * ks, bh + 2 * ks, IDESC, 1u);
            }
            TC_COMMIT((s & 1) ? mb1 : mb0);
        }

        if (s + 2 < NS){
            if (s & 1){ mbar_wait(mb1, ph1); ph1 ^= 1; }
            else      { mbar_wait(mb0, ph0); ph0 ^= 1; }
            load_stage(s + 2);
        }
    }
    if ((NS - 1) & 1) mbar_wait(mb1, ph1);
    else              mbar_wait(mb0, ph0);
    TC_FENCE_AFTER();

    const int sub = w & 3;
    const int cb  = (BN == 128) ? (w >> 2) * 64 : 0;
    u32* sbuf = (u32*)(smem + 1024) + (size_t)w * (32 * 33);

    if (BN == 128 || w < 4){
        u32 dr[64];
        TC_LD32(dr,      tmem + cb);
        TC_LD32(dr + 32, tmem + cb + 32);
        TC_WAITLD();
        TC_FENCE_BEFORE();

        const int row0 = m0 + sub * 32;
        const int row  = row0 + lane;

        if (mode == 0){
            float* dst = outF + (size_t)row * 1024 + n0 + cb;
            const float* bias = aux + n0 + cb;
#pragma unroll
            for (int j = 0; j < 16; j++){
                float4 o;
                o.x = __uint_as_float(dr[j*4+0]) + bias[j*4+0];
                o.y = __uint_as_float(dr[j*4+1]) + bias[j*4+1];
                o.z = __uint_as_float(dr[j*4+2]) + bias[j*4+2];
                o.w = __uint_as_float(dr[j*4+3]) + bias[j*4+3];
                *(float4*)(dst + j*4) = o;
            }
        } else if (mode == 1){
            const float* bias = aux + n0 + cb;
            const int h = (n0 + cb) >> 6;
            u32 hiw[32], low[32];
#pragma unroll
            for (int j = 0; j < 32; j++){
                float va = __uint_as_float(dr[2*j])   + bias[2*j];
                float vb = __uint_as_float(dr[2*j+1]) + bias[2*j+1];
                hiw[j] = pack2(va, vb);
                low[j] = pack2(va - b2f(f2b(va)), vb - b2f(f2b(vb)));
            }
#pragma unroll
            for (int j = 0; j < 32; j++) sbuf[lane * 33 + j] = hiw[j];
            __syncwarp();
#pragma unroll
            for (int i = 0; i < 32; i++){
                int r = row0 + i, bs = r >> 10, l = r & 1023;
                size_t wb = (((size_t)(bs * 16 + h)) << 15) + ((size_t)l << 5);
                ((u32*)oHi)[wb + lane] = sbuf[i * 33 + lane];
            }
            __syncwarp();
#pragma unroll
            for (int j = 0; j < 32; j++) sbuf[lane * 33 + j] = low[j];
            __syncwarp();
#pragma unroll
            for (int i = 0; i < 32; i++){
                int r = row0 + i, bs = r >> 10, l = r & 1023;
                size_t wb = (((size_t)(bs * 16 + h)) << 15) + ((size_t)l << 5);
                ((u32*)oLo)[wb + lane] = sbuf[i * 33 + lane];
            }
        } else if (mode == 2){
            const int bs = row >> 10, l = row & 1023;
            const int h  = (n0 + cb) >> 6;
            const size_t base = ((size_t)(bs * 16 + h) * 64) * 1024 + l;
            const float* bias = aux + n0 + cb;
#pragma unroll
            for (int j = 0; j < 64; j++){
                float va = __uint_as_float(dr[j]) + bias[j];
                u16 hh = f2h(va);
                oHi[base + (size_t)j * 1024] = hh;
                oLo[base + (size_t)j * 1024] = f2h(va - h2f(hh));
            }
        } else { // 4: ctx merged, normalized via g_rinv
            const float inv = g_rinv[(size_t)z * 1024 + row];
            u32 hiw[32], low[32];
#pragma unroll
            for (int j = 0; j < 32; j++){
                float va = __uint_as_float(dr[2*j])   * inv;
                float vb = __uint_as_float(dr[2*j+1]) * inv;
                hiw[j] = pack2(va, vb);
                low[j] = pack2(va - b2f(f2b(va)), vb - b2f(f2b(vb)));
            }
#pragma unroll
            for (int j = 0; j < 32; j++) sbuf[lane * 33 + j] = hiw[j];
            __syncwarp();
#pragma unroll
            for (int i = 0; i < 32; i++){
                size_t wb = (((size_t)((z >> 4) * 1024 + row0 + i)) << 9)
                          + (size_t)(z & 15) * 32;
                ((u32*)oHi)[wb + lane] = sbuf[i * 33 + lane];
            }
            __syncwarp();
#pragma unroll
            for (int j = 0; j < 32; j++) sbuf[lane * 33 + j] = low[j];
            __syncwarp();
#pragma unroll
            for (int i = 0; i < 32; i++){
                size_t wb = (((size_t)((z >> 4) * 1024 + row0 + i)) << 9)
                          + (size_t)(z & 15) * 32;
                ((u32*)oLo)[wb + lane] = sbuf[i * 33 + lane];
            }
        }
    }
    __syncthreads();
    if (tid == 0){ MBAR_INVAL(mb0); MBAR_INVAL(mb1); }
    __syncthreads();
    if (w == 0) TC_DEALLOC(tmem, TCOLS);

#else
    // ---------- mma.sync fallback (compile-only; driver picks sm_103a) -----
    constexpr int WGM = (BN == 128) ? 2 : 4;
    constexpr int WGN = (BN == 128) ? 4 : 2;
    constexpr int PITCH = 40;
    constexpr int ASZ = 128 * PITCH;
    constexpr int BSZ = BN * PITCH;
    constexpr int STAGE = 2 * ASZ + 2 * BSZ;
    constexpr int WTM = 128 / WGM;
    constexpr int WTN = BN / WGN;
    constexpr int MT = WTM / 16;
    constexpr int NT16 = WTN / 16;

    const unsigned sbase = smem_u32p(smem);
    const int wm = (w / WGN) * WTM;
    const int wn = (w % WGN) * WTN;
    const int lrow = (lane & 7) + ((lane >> 3) & 1) * 8;
    const int lcol = (lane >> 4) * 8;

    float acc[MT][NT16 * 2][4];
#pragma unroll
    for (int i = 0; i < MT; i++)
#pragma unroll
        for (int j = 0; j < NT16 * 2; j++)
#pragma unroll
            for (int t = 0; t < 4; t++) acc[i][j][t] = 0.f;

    auto load_stage = [&](int s){
        const int k0 = s << 5;
        const unsigned sd = sbase + (unsigned)((s & 1) * STAGE) * 2u;
#pragma unroll
        for (int it = 0; it < 2; it++){
            int idx = tid + it * 256;
            int r = idx >> 2, c = idx & 3;
            size_t g = (size_t)(m0 + r) * K + k0 + c * 8;
            unsigned d = sd + (unsigned)(r * PITCH + c * 8) * 2u;
            cpa16(d, Ah + g);
            cpa16(d + ASZ * 2, Al + g);
        }
#pragma unroll
        for (int it = 0; it < (BN * 4) / 256; it++){
            int idx = tid + it * 256;
            int r = idx >> 2, c = idx & 3;
            size_t g = (size_t)(n0 + r) * K + k0 + c * 8;
            unsigned d = sd + (unsigned)(2 * ASZ + r * PITCH + c * 8) * 2u;
            cpa16(d, Bh + g);
            cpa16(d + BSZ * 2, Bl + g);
        }
        CPA_COMMIT();
    };

    const int NS = K >> 5;
    load_stage(0);

    for (int s = 0; s < NS; s++){
        if (s + 1 < NS){ load_stage(s + 1); cpa_wait<1>(); }
        else           { cpa_wait<0>(); }
        __syncthreads();

        const unsigned sd = sbase + (unsigned)((s & 1) * STAGE) * 2u;
#pragma unroll
        for (int k16 = 0; k16 < 2; k16++){
            const int kc = k16 * 16 + lcol;
            u32 ah[MT][4], al[MT][4], bh[NT16][4], bl[NT16][4];
#pragma unroll
            for (int mt = 0; mt < MT; mt++){
                unsigned a = sd + (unsigned)((wm + mt * 16 + lrow) * PITCH + kc) * 2u;
                ldmx4(ah[mt][0], ah[mt][1], ah[mt][2], ah[mt][3], a);
                ldmx4(al[mt][0], al[mt][1], al[mt][2], al[mt][3], a + ASZ * 2);
            }
#pragma unroll
            for (int nt = 0; nt < NT16; nt++){
                unsigned a = sd + (unsigned)(2 * ASZ + (wn + nt * 16 + lrow) * PITCH + kc) * 2u;
                ldmx4(bh[nt][0], bh[nt][1], bh[nt][2], bh[nt][3], a);
                ldmx4(bl[nt][0], bl[nt][1], bl[nt][2], bl[nt][3], a + BSZ * 2);
            }
#pragma unroll
            for (int mt = 0; mt < MT; mt++)
#pragma unroll
                for (int nt = 0; nt < NT16; nt++){
                    mma16816(acc[mt][2*nt],   ah[mt], bh[nt][0], bh[nt][2]);
                    mma16816(acc[mt][2*nt+1], ah[mt], bh[nt][1], bh[nt][3]);
                    mma16816(acc[mt][2*nt],   ah[mt], bl[nt][0], bl[nt][2]);
                    mma16816(acc[mt][2*nt+1], ah[mt], bl[nt][1], bl[nt][3]);
                    if (APASS == 2){
                        mma16816(acc[mt][2*nt],   al[mt], bh[nt][0], bh[nt][2]);
                        mma16816(acc[mt][2*nt+1], al[mt], bh[nt][1], bh[nt][3]);
                    }
                }
        }
        __syncthreads();
    }

    auto store_pair = [&](int row, int col, float va, float vb){
        if (mode == 0){
            float2 o; o.x = va + aux[col]; o.y = vb + aux[col + 1];
            *(float2*)(outF + (size_t)row * 1024 + col) = o;
        } else if (mode == 1){
            va += aux[col]; vb += aux[col + 1];
            int bs = row >> 10, l = row & 1023, h = col >> 6, d = col & 63;
            size_t idx = (((size_t)(bs * 16 + h)) << 16) + ((size_t)l << 6) + d;
            *(u32*)(oHi + idx) = pack2(va, vb);
            *(u32*)(oLo + idx) = pack2(va - b2f(f2b(va)), vb - b2f(f2b(vb)));
        } else if (mode == 2){
            va += aux[col]; vb += aux[col + 1];
            int bs = row >> 10, l = row & 1023, h = col >> 6, d = col & 63;
            size_t base = ((size_t)(bs * 16 + h) * 64 + d) * 1024 + l;
            u16 h0 = f2h(va), h1 = f2h(vb);
            oHi[base] = h0;        oHi[base + 1024] = h1;
            oLo[base] = f2h(va - h2f(h0));
            oLo[base + 1024] = f2h(vb - h2f(h1));
        } else {
            float inv = g_rinv[(size_t)z * 1024 + row];
            va *= inv; vb *= inv;
            size_t idx = ((size_t)((z >> 4) * 1024 + row) << 10) + (size_t)(z & 15) * 64 + col;
            *(u32*)(oHi + idx) = pack2(va, vb);
            *(u32*)(oLo + idx) = pack2(va - b2f(f2b(va)), vb - b2f(f2b(vb)));
        }
    };

#pragma unroll
    for (int mt = 0; mt < MT; mt++)
#pragma unroll
        for (int nt8 = 0; nt8 < NT16 * 2; nt8++){
            int r0 = m0 + wm + mt * 16 + (lane >> 2);
            int c0 = n0 + wn + nt8 * 8 + (lane & 3) * 2;
            store_pair(r0,     c0, acc[mt][nt8][0], acc[mt][nt8][1]);
            store_pair(r0 + 8, c0, acc[mt][nt8][2], acc[mt][nt8][3]);
        }
#endif
}

// ---------------------------------------------------------------------------
// Fused QK kernel: per CTA (q-tile 128, z), loops over 8 k-tiles of 128.
// Q loaded once; K double-buffered. Writes fp16 probs (exp, mask via bits)
// and full row sums to g_rsum. bf16 hi/lo 3-pass numerics.
// ---------------------------------------------------------------------------
__global__ void __launch_bounds__(256) qk_tc(
    const u16* __restrict__ qhH, const u16* __restrict__ qhL,
    const u16* __restrict__ khH, const u16* __restrict__ khL)
{
    extern __shared__ char smem[];
    const int tid  = threadIdx.x;
    const int w    = tid >> 5;
    const int lane = tid & 31;
    const int m0   = blockIdx.x * 128;
    const int z    = blockIdx.y;
    const int bs   = z >> 4;

    const u16* Qh = qhH + (size_t)z * 65536;
    const u16* Ql = qhL + (size_t)z * 65536;
    const u16* Kh = khH + (size_t)z * 65536;
    const u16* Kl = khL + (size_t)z * 65536;

#if HAS_TCGEN05
    constexpr u32 IDESC =
        (1u << 4) | (1u << 7) | (1u << 10) | (16u << 17) | (8u << 24);

    const unsigned sb   = smem_u32p(smem);
    const unsigned mb0  = sb + 8;
    const unsigned mb1  = sb + 16;
    const unsigned qbuf = sb + 1024;          // Qhi 16K + Qlo 16K
    const unsigned kbuf = qbuf + 32768;       // 2 x (Khi 16K + Klo 16K)

    if (w == 0){ TC_ALLOC(sb, 128); }
    if (tid == 0){ MBAR_INIT(mb0, 1); MBAR_INIT(mb1, 1); }
    __syncthreads();
    unsigned tmem;
    asm volatile("ld.shared.b32 %0, [%1];" : "=r"(tmem) : "r"(sb));

    auto loadK = [&](int kt){
        const unsigned bb = kbuf + (unsigned)(kt & 1) * 32768;
#pragma unroll
        for (int it = 0; it < 4; it++){
            int idx = tid + it * 256;
            int r = idx >> 3, c = idx & 7;
            int off = r * 128 + c * 16;
            unsigned sw = (unsigned)(off ^ ((off >> 3) & 0x70));
            size_t g = (size_t)(kt * 128 + r) * 64 + c * 8;
            cpa16(bb + sw,         Kh + g);
            cpa16(bb + 16384 + sw, Kl + g);
        }
        CPA_COMMIT();
    };

    // group 0: Q + K0;  group 1: K1
    {
#pragma unroll
        for (int it = 0; it < 4; it++){
            int idx = tid + it * 256;
            int r = idx >> 3, c = idx & 7;
            int off = r * 128 + c * 16;
            unsigned sw = (unsigned)(off ^ ((off >> 3) & 0x70));
            size_t g = (size_t)(m0 + r) * 64 + c * 8;
            cpa16(qbuf + sw,         Qh + g);
            cpa16(qbuf + 16384 + sw, Ql + g);
        }
        const unsigned bb = kbuf;
#pragma unroll
        for (int it = 0; it < 4; it++){
            int idx = tid + it * 256;
            int r = idx >> 3, c = idx & 7;
            int off = r * 128 + c * 16;
            unsigned sw = (unsigned)(off ^ ((off >> 3) & 0x70));
            size_t g = (size_t)r * 64 + c * 8;
            cpa16(bb + sw,         Kh + g);
            cpa16(bb + 16384 + sw, Kl + g);
        }
        CPA_COMMIT();
        loadK(1);
    }

    const int sub = w & 3;
    const int cb  = (w >> 2) * 64;
    const int row0 = m0 + sub * 32;
    const int row  = row0 + lane;
    u32* sbuf = (u32*)(smem + 99328) + (size_t)w * (32 * 33);
    float rs = 0.f;
    unsigned ph0 = 0, ph1 = 0;

    for (int kt = 0; kt < 8; kt++){
        if (kt == 7) cpa_wait<0>(); else cpa_wait<1>();
        __syncthreads();

        if (w == 0 && elect1()){
            TC_FENCE_AFTER();
            FENCE_ASYNC();
            u64 qd  = mk_desc(qbuf);
            u64 qld = mk_desc(qbuf + 16384);
            const unsigned bb = kbuf + (unsigned)(kt & 1) * 32768;
            u64 kd  = mk_desc(bb);
            u64 kld = mk_desc(bb + 16384);
#pragma unroll
            for (int ks = 0; ks < 4; ks++)
                mma_ss(tmem, qd + 2 * ks, kd + 2 * ks, IDESC, ks > 0 ? 1u : 0u);
#pragma unroll
            for (int ks = 0; ks < 4; ks++)
                mma_ss(tmem, qd + 2 * ks, kld + 2 * ks, IDESC, 1u);
#pragma unroll
            for (int ks = 0; ks < 4; ks++)
                mma_ss(tmem, qld + 2 * ks, kd + 2 * ks, IDESC, 1u);
            TC_COMMIT((kt & 1) ? mb1 : mb0);
        }
        if (kt & 1){ mbar_wait(mb1, ph1); ph1 ^= 1; }
        else       { mbar_wait(mb0, ph0); ph0 ^= 1; }
        TC_FENCE_AFTER();

        if (kt + 2 < 8) loadK(kt + 2);

        // epilogue for this k-tile
        u32 dr[64];
        TC_LD32(dr,      tmem + cb);
        TC_LD32(dr + 32, tmem + cb + 32);
        TC_WAITLD();
        TC_FENCE_BEFORE();

        const int c0 = kt * 128 + cb;
        const size_t widx = ((size_t)bs << 15) + ((size_t)row << 5) + (c0 >> 5);
        const u32 w0 = g_mbits[widx];
        const u32 w1 = g_mbits[widx + 1];

        float part = 0.f;
        u32 pw[32];
#pragma unroll
        for (int j = 0; j < 32; j++){
            int c = 2 * j;
            u32 wa = (c < 32) ? w0 : w1;
            u32 wbq = (c + 1 < 32) ? w0 : w1;
            float ea = ((wa >> (c & 31)) & 1) ? 0.f
                     : __expf(__uint_as_float(dr[2*j]) * 0.125f);
            float eb = ((wbq >> ((c + 1) & 31)) & 1) ? 0.f
                     : __expf(__uint_as_float(dr[2*j+1]) * 0.125f);
            part += ea + eb;
            pw[j] = pack2h(ea, eb);
        }
        rs += part;
#pragma unroll
        for (int j = 0; j < 32; j++) sbuf[lane * 33 + j] = pw[j];
        __syncwarp();
#pragma unroll
        for (int i = 0; i < 32; i++){
            size_t wb = ((size_t)z << 19) + ((size_t)(row0 + i) << 9)
                      + (size_t)(c0 >> 1);
            ((u32*)g_p)[wb + lane] = sbuf[i * 33 + lane];
        }
        __syncwarp();
    }

    // combine the two column-half partial sums and write g_rsum
    __syncthreads();
    float* fs = (float*)(smem + 99328);
    fs[(w >> 2) * 128 + sub * 32 + lane] = rs;
    __syncthreads();
    if (w < 4){
        int rl = w * 32 + lane;
        g_rsum[(size_t)z * 1024 + m0 + rl] = fs[rl] + fs[128 + rl];
    }
    __syncthreads();
    if (tid == 0){ MBAR_INVAL(mb0); MBAR_INVAL(mb1); }
    __syncthreads();
    if (w == 0) TC_DEALLOC(tmem, 128);

#else
    // naive fallback (compile-only; sm_103a cubin is selected at runtime)
    for (int idx = tid; idx < 128 * 1024; idx += 256){
        int r = m0 + (idx >> 10);
        int c = idx & 1023;
        u32 wm_ = g_mbits[((size_t)bs << 15) + ((size_t)r << 5) + (c >> 5)];
        float p = 0.f;
        if (!((wm_ >> (c & 31)) & 1)){
            float s = 0.f;
            for (int d = 0; d < 64; d++){
                float qv = b2f(Qh[(size_t)r * 64 + d]) + b2f(Ql[(size_t)r * 64 + d]);
                float kv = b2f(Kh[(size_t)c * 64 + d]) + b2f(Kl[(size_t)c * 64 + d]);
                s += qv * kv;
            }
            p = __expf(s * 0.125f);
        }
        g_p[((size_t)z << 20) + ((size_t)r << 10) + c] = f2h(p);
        atomicAdd(&g_rsum[(size_t)z * 1024 + r], p);
    }
#endif
}

// ---------------------------------------------------------------------------
// mask fp32 -> bitmask (1 bit per element)
// ---------------------------------------------------------------------------
__global__ __launch_bounds__(256) void mask_bits_kernel(const float* __restrict__ mask)
{
    const int warpid = (blockIdx.x * 256 + threadIdx.x) >> 5;
    const int lane = threadIdx.x & 31;
    const size_t base = (size_t)warpid * 1024;
#pragma unroll
    for (int b = 0; b < 32; b++){
        float v = mask[base + b * 32 + lane];
        u32 bits = __ballot_sync(0xFFFFFFFFu, v > 0.5f);
        if (lane == b) g_mbits[base / 32 + b] = bits;
    }
}

__global__ __launch_bounds__(256) void zero_rsum()
{
    const int i = blockIdx.x * 256 + threadIdx.x;
    ((float4*)g_rsum)[i] = make_float4(0.f, 0.f, 0.f, 0.f);
}

__global__ __launch_bounds__(256) void invert_rsum()
{
    const int i = blockIdx.x * 256 + threadIdx.x;
    g_rinv[i] = __frcp_rn(g_rsum[i]);
}

// ---------------------------------------------------------------------------
// fp32 -> bf16 hi/lo
// ---------------------------------------------------------------------------
__global__ __launch_bounds__(256) void conv_act(
    const float* __restrict__ in, u16* __restrict__ hi, u16* __restrict__ lo)
{
    const int i = blockIdx.x * 256 + threadIdx.x;
    float4 v = ((const float4*)in)[i];
    u32 h0 = pack2(v.x, v.y), h1 = pack2(v.z, v.w);
    ((u32*)hi)[i * 2]     = h0;
    ((u32*)hi)[i * 2 + 1] = h1;
    ((u32*)lo)[i * 2]     = pack2(v.x - b2f((u16)h0), v.y - b2f((u16)(h0 >> 16)));
    ((u32*)lo)[i * 2 + 1] = pack2(v.z - b2f((u16)h1), v.w - b2f((u16)(h1 >> 16)));
}

// ---------------------------------------------------------------------------
// W[k][n] fp32 -> WT[n][k] bf16 hi/lo
// ---------------------------------------------------------------------------
__global__ __launch_bounds__(256) void conv_wT(
    const float* __restrict__ W, u16* __restrict__ hi, u16* __restrict__ lo)
{
    __shared__ float tile[32][33];
    const int tx = threadIdx.x, ty = threadIdx.y;
    const int kb = blockIdx.y * 32, nb = blockIdx.x * 32;
#pragma unroll
    for (int i = 0; i < 4; i++)
        tile[ty + i * 8][tx] = W[(size_t)(kb + ty + i * 8) * 1024 + nb + tx];
    __syncthreads();
#pragma unroll
    for (int i = 0; i < 4; i++){
        int n = nb + ty + i * 8, k = kb + tx;
        float v = tile[tx][ty + i * 8];
        u16 h = f2b(v);
        hi[(size_t)n * 1024 + k] = h;
        lo[(size_t)n * 1024 + k] = f2b(v - b2f(h));
    }
}

// ---------------------------------------------------------------------------
// attn_mean over heads: mean_h( p_h * rinv_h )
// ---------------------------------------------------------------------------
__global__ __launch_bounds__(256) void head_mean_kernel(float* __restrict__ outm)
{
    const int i = blockIdx.x * 256 + threadIdx.x;
    const int elem = i * 2;
    const int bs = elem >> 20, rem = elem & 0xFFFFF;
    const int q  = rem >> 10;
    float s0 = 0.f, s1 = 0.f;
#pragma unroll
    for (int h = 0; h < 16; h++){
        const int zz = bs * 16 + h;
        u32 up = ((const u32*)g_p)[((size_t)zz << 19) + (rem >> 1)];
        float inv = g_rinv[(size_t)zz * 1024 + q];
        s0 += h2f((u16)up) * inv;
        s1 += h2f((u16)(up >> 16)) * inv;
    }
    float2 o; o.x = s0 * 0.0625f; o.y = s1 * 0.0625f;
    *(float2*)(outm + elem) = o;
}

// ---------------------------------------------------------------------------
extern "C" void kernel_launch(void* const* d_in, const int* in_sizes, int n_in,
                              void* d_out, int out_size)
{
    const float* q    = (const float*)d_in[0];
    const float* k    = (const float*)d_in[1];
    const float* v    = (const float*)d_in[2];
    const float* mask = (const float*)d_in[3];
    const float* wq   = (const float*)d_in[4];
    const float* bq   = (const float*)d_in[5];
    const float* wk   = (const float*)d_in[6];
    const float* bk   = (const float*)d_in[7];
    const float* wv   = (const float*)d_in[8];
    const float* bv   = (const float*)d_in[9];
    const float* wo   = (const float*)d_in[10];
    const float* bo   = (const float*)d_in[11];

    float* out       = (float*)d_out;
    float* attn_mean = out + 16777216;

    u16 *wtH, *wtL, *aH, *aL, *qhH, *qhL, *khH, *khL, *vtH, *vtL, *pP, *cxH, *cxL;
    cudaGetSymbolAddress((void**)&wtH, g_wt_hi);
    cudaGetSymbolAddress((void**)&wtL, g_wt_lo);
    cudaGetSymbolAddress((void**)&aH,  g_a_hi);
    cudaGetSymbolAddress((void**)&aL,  g_a_lo);
    cudaGetSymbolAddress((void**)&qhH, g_qh_hi);
    cudaGetSymbolAddress((void**)&qhL, g_qh_lo);
    cudaGetSymbolAddress((void**)&khH, g_kh_hi);
    cudaGetSymbolAddress((void**)&khL, g_kh_lo);
    cudaGetSymbolAddress((void**)&vtH, g_vt_hi);
    cudaGetSymbolAddress((void**)&vtL, g_vt_lo);
    cudaGetSymbolAddress((void**)&pP,  g_p);
    cudaGetSymbolAddress((void**)&cxH, g_ctx_hi);
    cudaGetSymbolAddress((void**)&cxL, g_ctx_lo);

    constexpr int SMEM_BIG   = 1024 + 2 * (2 * 128 * 128 + 2 * 128 * 128); // 132096
    constexpr int SMEM_SMALL = 1024 + 2 * (1 * 128 * 128 + 2 * 64 * 128);  //  66560
    constexpr int SMEM_QK    = 1024 + 32768 + 65536 + 33792;               // 133120
    cudaFuncSetAttribute(gemm_any<128,1,2>,
                         cudaFuncAttributeMaxDynamicSharedMemorySize, SMEM_BIG);
    cudaFuncSetAttribute(gemm_any<64,0,1>,
                         cudaFuncAttributeMaxDynamicSharedMemorySize, SMEM_SMALL);
    cudaFuncSetAttribute(qk_tc,
                         cudaFuncAttributeMaxDynamicSharedMemorySize, SMEM_QK);

    dim3 wtg(32, 32);
    dim3 wtb(32, 8);
    conv_wT<<<wtg, wtb>>>(wq, wtH + 0u,       wtL + 0u);
    conv_wT<<<wtg, wtb>>>(wk, wtH + 1048576u, wtL + 1048576u);
    conv_wT<<<wtg, wtb>>>(wv, wtH + 2097152u, wtL + 2097152u);
    conv_wT<<<wtg, wtb>>>(wo, wtH + 3145728u, wtL + 3145728u);
    mask_bits_kernel<<<2048, 256>>>(mask);
    zero_rsum<<<256, 256>>>();

    dim3 projGrid(8, 128, 1);

    // Q projection -> head-split (bf16 hi/lo)
    conv_act<<<16384, 256>>>(q, aH, aL);
    gemm_any<128,1,2><<<projGrid, 256, SMEM_BIG>>>(
        aH, aL, 0, wtH + 0u, wtL + 0u, 0, 1024, 1, nullptr, qhH, qhL, bq);
    // K projection
    conv_act<<<16384, 256>>>(k, aH, aL);
    gemm_any<128,1,2><<<projGrid, 256, SMEM_BIG>>>(
        aH, aL, 0, wtH + 1048576u, wtL + 1048576u, 0, 1024, 1, nullptr, khH, khL, bk);
    // V projection -> transposed [bsh][d][l] (fp16 hi/lo)
    conv_act<<<16384, 256>>>(v, aH, aL);
    gemm_any<128,1,2><<<projGrid, 256, SMEM_BIG>>>(
        aH, aL, 0, wtH + 2097152u, wtL + 2097152u, 0, 1024, 2, nullptr, vtH, vtL, bv);

    // fused QK: probs (fp16, masked via bits) + full row sums
    qk_tc<<<dim3(8, 256), 256, SMEM_QK>>>(qhH, qhL, khH, khL);
    invert_rsum<<<1024, 256>>>();

    // ctx = (P @ V) * rinv
    gemm_any<64,0,1><<<dim3(1, 8, 256), 256, SMEM_SMALL>>>(
        pP, nullptr, (size_t)1 << 20, vtH, vtL, 65536, 1024, 4,
        nullptr, cxH, cxL, nullptr);

    // attn_mean
    head_mean_kernel<<<32768, 256>>>(attn_mean);

    // out projection (fp32 + bias)
    gemm_any<128,1,2><<<projGrid, 256, SMEM_BIG>>>(
        cxH, cxL, 0, wtH + 3145728u, wtL + 3145728u, 0, 1024, 0, out, nullptr, nullptr, bo);
}

// round 12
// speedup vs baseline: 2.4513x; 1.0150x over previous
#include <cuda_runtime.h>
#include <cuda_bf16.h>
#include <cuda_fp16.h>

typedef unsigned short u16;
typedef unsigned int   u32;
typedef unsigned long long u64;

#if defined(__CUDA_ARCH_FEAT_SM103_ALL) || defined(__CUDA_ARCH_FEAT_SM100_ALL)
#define HAS_TCGEN05 1
#else
#define HAS_TCGEN05 0
#endif

// ---------------- device scratch (allocation-free rule) --------------------
__device__ u16 g_wt_hi[4u*1024u*1024u];   // 4 weights, transposed [n][k] bf16
__device__ u16 g_wt_lo[4u*1024u*1024u];
__device__ u16 g_a_hi[16777216];          // activation staging bf16 (reused)
__device__ u16 g_a_lo[16777216];
__device__ u16 g_qh_hi[16777216];         // [bsh][l][64] bf16
__device__ u16 g_qh_lo[16777216];
__device__ u16 g_kh_hi[16777216];
__device__ u16 g_kh_lo[16777216];
__device__ u16 g_vt_hi[16777216];         // [bsh][d=64][l=1024] fp16
__device__ u16 g_vt_lo[16777216];
__device__ u16 g_p[268435456];            // unnormalized exp probs fp16
__device__ u32 g_mbits[524288];           // mask bitmask: [bs][row][32 words]
__device__ float g_rsum[262144];          // [bsh][row] row sums
__device__ float g_rinv[262144];          // [bsh][row] 1/rowsum
__device__ u16 g_ctx_hi[16777216];        // merged [bs*L+q][1024] bf16
__device__ u16 g_ctx_lo[16777216];
__device__ float g_attn2[16777216];       // head-mean partial (heads 8-15)

// ---------------- helpers --------------------------------------------------
__device__ __forceinline__ u16 f2b(float x){
    return __bfloat16_as_ushort(__float2bfloat16_rn(x));
}
__device__ __forceinline__ float b2f(u16 u){
    return __bfloat162float(__ushort_as_bfloat16(u));
}
__device__ __forceinline__ u32 pack2(float a, float b){
    return (u32)f2b(a) | ((u32)f2b(b) << 16);
}
__device__ __forceinline__ u16 f2h(float x){
    return __half_as_ushort(__float2half_rn(x));
}
__device__ __forceinline__ float h2f(u16 u){
    return __half2float(__ushort_as_half(u));
}
__device__ __forceinline__ u32 pack2h(float a, float b){
    return (u32)f2h(a) | ((u32)f2h(b) << 16);
}
__device__ __forceinline__ unsigned smem_u32p(const void* p){
    unsigned a;
    asm("{ .reg .u64 t; cvta.to.shared.u64 t, %1; cvt.u32.u64 %0, t; }"
        : "=r"(a) : "l"(p));
    return a;
}
__device__ __forceinline__ void cpa16(unsigned dst, const void* src){
    asm volatile("cp.async.cg.shared.global [%0], [%1], 16;" :: "r"(dst), "l"(src));
}
#define CPA_COMMIT() asm volatile("cp.async.commit_group;" ::: "memory")
template<int N> __device__ __forceinline__ void cpa_wait(){
    asm volatile("cp.async.wait_group %0;" :: "n"(N) : "memory");
}

#if HAS_TCGEN05
__device__ __forceinline__ unsigned elect1(){
    unsigned p;
    asm volatile("{ .reg .pred P; elect.sync _|P, 0xFFFFFFFF; selp.b32 %0, 1, 0, P; }"
                 : "=r"(p));
    return p;
}
#define MBAR_INIT(a, c) \
    asm volatile("mbarrier.init.shared.b64 [%0], %1;" :: "r"(a), "r"(c) : "memory")
#define MBAR_INVAL(a) \
    asm volatile("mbarrier.inval.shared.b64 [%0];" :: "r"(a) : "memory")
__device__ __forceinline__ void mbar_wait(unsigned a, unsigned ph){
    asm volatile(
        "{\n\t.reg .pred P;\n"
        "W%=:\n\t"
        "mbarrier.try_wait.parity.acquire.cta.shared::cta.b64 P, [%0], %1, 0x989680;\n\t"
        "@P bra D%=;\n\t"
        "bra W%=;\n"
        "D%=:\n\t}"
        :: "r"(a), "r"(ph) : "memory");
}
#define TC_ALLOC(sa, n) \
    asm volatile("tcgen05.alloc.cta_group::1.sync.aligned.shared::cta.b32 [%0], %1;" \
                 :: "r"(sa), "r"(n) : "memory")
#define TC_DEALLOC(t, n) \
    asm volatile("tcgen05.dealloc.cta_group::1.sync.aligned.b32 %0, %1;" :: "r"(t), "r"(n))
#define TC_COMMIT(mb) \
    asm volatile("tcgen05.commit.cta_group::1.mbarrier::arrive::one.shared::cluster.b64 [%0];" \
                 :: "r"(mb) : "memory")
#define TC_FENCE_AFTER()  asm volatile("tcgen05.fence::after_thread_sync;" ::: "memory")
#define TC_FENCE_BEFORE() asm volatile("tcgen05.fence::before_thread_sync;" ::: "memory")
#define TC_WAITLD()       asm volatile("tcgen05.wait::ld.sync.aligned;" ::: "memory")
#define FENCE_ASYNC()     asm volatile("fence.proxy.async.shared::cta;" ::: "memory")

#define TC_LD32(r, addr) \
    asm volatile( \
        "tcgen05.ld.sync.aligned.32x32b.x32.b32 " \
        "{%0, %1, %2, %3, %4, %5, %6, %7, " \
        " %8, %9, %10, %11, %12, %13, %14, %15, " \
        " %16, %17, %18, %19, %20, %21, %22, %23, " \
        " %24, %25, %26, %27, %28, %29, %30, %31}, [%32];" \
        : "=r"((r)[0]),  "=r"((r)[1]),  "=r"((r)[2]),  "=r"((r)[3]), \
          "=r"((r)[4]),  "=r"((r)[5]),  "=r"((r)[6]),  "=r"((r)[7]), \
          "=r"((r)[8]),  "=r"((r)[9]),  "=r"((r)[10]), "=r"((r)[11]), \
          "=r"((r)[12]), "=r"((r)[13]), "=r"((r)[14]), "=r"((r)[15]), \
          "=r"((r)[16]), "=r"((r)[17]), "=r"((r)[18]), "=r"((r)[19]), \
          "=r"((r)[20]), "=r"((r)[21]), "=r"((r)[22]), "=r"((r)[23]), \
          "=r"((r)[24]), "=r"((r)[25]), "=r"((r)[26]), "=r"((r)[27]), \
          "=r"((r)[28]), "=r"((r)[29]), "=r"((r)[30]), "=r"((r)[31]) \
        : "r"(addr))

// SW128 K-major descriptor (LBO=1, SBO=64, version=1, layout=SW128)
__device__ __forceinline__ u64 mk_desc(unsigned addr){
    const u64 base = (2ull << 61) | (1ull << 46) | (64ull << 32) | (1ull << 16);
    return base | ((u64)(addr >> 4) & 0x3FFFull);
}
__device__ __forceinline__ void mma_ss(unsigned d, u64 a, u64 b, u32 idesc, u32 en){
    asm volatile(
        "{\n\t.reg .pred p;\n\t"
        "setp.ne.u32 p, %4, 0;\n\t"
        "tcgen05.mma.cta_group::1.kind::f16 [%0], %1, %2, %3, {%5, %5, %5, %5}, p;\n\t}"
        :: "r"(d), "l"(a), "l"(b), "r"(idesc), "r"(en), "r"(0u) : "memory");
}
#else
__device__ __forceinline__ void ldmx4(u32& r0, u32& r1, u32& r2, u32& r3, unsigned a){
    asm volatile("ldmatrix.sync.aligned.m8n8.x4.shared.b16 {%0,%1,%2,%3}, [%4];"
                 : "=r"(r0), "=r"(r1), "=r"(r2), "=r"(r3) : "r"(a));
}
__device__ __forceinline__ void mma16816(float* c, const u32* a, u32 b0, u32 b1){
    asm volatile(
        "mma.sync.aligned.m16n8k16.row.col.f32.bf16.bf16.f32 "
        "{%0,%1,%2,%3}, {%4,%5,%6,%7}, {%8,%9}, {%0,%1,%2,%3};"
        : "+f"(c[0]), "+f"(c[1]), "+f"(c[2]), "+f"(c[3])
        : "r"(a[0]), "r"(a[1]), "r"(a[2]), "r"(a[3]), "r"(b0), "r"(b1));
}
#endif

// ---------------------------------------------------------------------------
// Generic GEMM:  D[128 x BN] = A[128,K] . B[BN,K]^T
// DT: 1=bf16, 0=fp16 operands.  APASS: 2 = A hi/lo (3-pass), 1 = A single.
// Epilogue modes:
//   0: fp32 row-major + bias          1: bf16 hi/lo head-split + bias (staged)
//   2: fp16 hi/lo V-transpose [bsh][d][l] + bias
// ---------------------------------------------------------------------------
template<int BN, int DT, int APASS>
__global__ void __launch_bounds__(256) gemm_any(
    const u16* __restrict__ Ahi, const u16* __restrict__ Alo, size_t aZ,
    const u16* __restrict__ Bhi, const u16* __restrict__ Blo, size_t bZ,
    int K, int mode,
    float* __restrict__ outF, u16* __restrict__ oHi, u16* __restrict__ oLo,
    const float* __restrict__ aux)
{
    extern __shared__ char smem[];
    const int tid  = threadIdx.x;
    const int w    = tid >> 5;
    const int lane = tid & 31;
    const int m0   = blockIdx.y * 128;
    const int n0   = blockIdx.x * BN;
    const int z    = blockIdx.z;

    const u16* Ah = Ahi + (size_t)z * aZ;
    const u16* Al = (APASS == 2) ? (Alo + (size_t)z * aZ) : Ahi;
    const u16* Bh = Bhi + (size_t)z * bZ;
    const u16* Bl = Blo + (size_t)z * bZ;

#if HAS_TCGEN05
    constexpr int ABYT  = 128 * 128;
    constexpr int BBYT  = BN * 128;
    constexpr int BOFF  = APASS * ABYT;
    constexpr int STAGE = APASS * ABYT + 2 * BBYT;
    constexpr u32 IDESC =
        (1u << 4) | ((u32)DT << 7) | ((u32)DT << 10)
        | ((u32)(BN / 8) << 17) | (8u << 24);
    constexpr int TCOLS = BN;

    const unsigned sb   = smem_u32p(smem);
    const unsigned mb0  = sb + 8;
    const unsigned mb1  = sb + 16;
    const unsigned buf0 = sb + 1024;

    if (w == 0){ TC_ALLOC(sb, TCOLS); }
    if (tid == 0){ MBAR_INIT(mb0, 1); MBAR_INIT(mb1, 1); }
    __syncthreads();
    unsigned tmem;
    asm volatile("ld.shared.b32 %0, [%1];" : "=r"(tmem) : "r"(sb));

    const int NS = K >> 6;

    auto load_stage = [&](int s){
        const unsigned bb = buf0 + (unsigned)(s & 1) * STAGE;
        const int k0 = s << 6;
#pragma unroll
        for (int it = 0; it < 4; it++){
            int idx = tid + it * 256;
            int r = idx >> 3, c = idx & 7;
            int off = r * 128 + c * 16;
            unsigned sw = (unsigned)(off ^ ((off >> 3) & 0x70));
            size_t g = (size_t)(m0 + r) * K + k0 + c * 8;
            cpa16(bb + sw, Ah + g);
            if (APASS == 2) cpa16(bb + ABYT + sw, Al + g);
        }
#pragma unroll
        for (int it = 0; it < (BN * 8) / 256; it++){
            int idx = tid + it * 256;
            int r = idx >> 3, c = idx & 7;
            int off = r * 128 + c * 16;
            unsigned sw = (unsigned)(off ^ ((off >> 3) & 0x70));
            size_t g = (size_t)(n0 + r) * K + k0 + c * 8;
            cpa16(bb + BOFF + sw,        Bh + g);
            cpa16(bb + BOFF + BBYT + sw, Bl + g);
        }
        CPA_COMMIT();
    };

    load_stage(0);
    if (NS > 1) load_stage(1);
    unsigned ph0 = 0, ph1 = 0;

    for (int s = 0; s < NS; s++){
        if (s == NS - 1) cpa_wait<0>(); else cpa_wait<1>();
        __syncthreads();

        if (w == 0 && elect1()){
            FENCE_ASYNC();
            const unsigned bb = buf0 + (unsigned)(s & 1) * STAGE;
            u64 ah = mk_desc(bb);
            u64 al = mk_desc(bb + ABYT);
            u64 bh = mk_desc(bb + BOFF);
            u64 bl = mk_desc(bb + BOFF + BBYT);
#pragma unroll
            for (int ks = 0; ks < 4; ks++)
                mma_ss(tmem, ah + 2 * ks, bh + 2 * ks, IDESC,
                       (s > 0 || ks > 0) ? 1u : 0u);
#pragma unroll
            for (int ks = 0; ks < 4; ks++)
                mma_ss(tmem, ah + 2 * ks, bl + 2 * ks, IDESC, 1u);
            if (APASS == 2){
#pragma unroll
                for (int ks = 0; ks < 4; ks++)
                    mma_ss(tmem, al + 2 * ks, bh + 2 * ks, IDESC, 1u);
            }
            TC_COMMIT((s & 1) ? mb1 : mb0);
        }

        if (s + 2 < NS){
            if (s & 1){ mbar_wait(mb1, ph1); ph1 ^= 1; }
            else      { mbar_wait(mb0, ph0); ph0 ^= 1; }
            load_stage(s + 2);
        }
    }
    if ((NS - 1) & 1) mbar_wait(mb1, ph1);
    else              mbar_wait(mb0, ph0);
    TC_FENCE_AFTER();

    const int sub = w & 3;
    const int cb  = (BN == 128) ? (w >> 2) * 64 : 0;
    u32* sbuf = (u32*)(smem + 1024) + (size_t)w * (32 * 33);

    if (BN == 128 || w < 4){
        u32 dr[64];
        TC_LD32(dr,      tmem + cb);
        TC_LD32(dr + 32, tmem + cb + 32);
        TC_WAITLD();
        TC_FENCE_BEFORE();

        const int row0 = m0 + sub * 32;
        const int row  = row0 + lane;

        if (mode == 0){
            float* dst = outF + (size_t)row * 1024 + n0 + cb;
            const float* bias = aux + n0 + cb;
#pragma unroll
            for (int j = 0; j < 16; j++){
                float4 o;
                o.x = __uint_as_float(dr[j*4+0]) + bias[j*4+0];
                o.y = __uint_as_float(dr[j*4+1]) + bias[j*4+1];
                o.z = __uint_as_float(dr[j*4+2]) + bias[j*4+2];
                o.w = __uint_as_float(dr[j*4+3]) + bias[j*4+3];
                *(float4*)(dst + j*4) = o;
            }
        } else if (mode == 1){
            const float* bias = aux + n0 + cb;
            const int h = (n0 + cb) >> 6;
            u32 hiw[32], low[32];
#pragma unroll
            for (int j = 0; j < 32; j++){
                float va = __uint_as_float(dr[2*j])   + bias[2*j];
                float vb = __uint_as_float(dr[2*j+1]) + bias[2*j+1];
                hiw[j] = pack2(va, vb);
                low[j] = pack2(va - b2f(f2b(va)), vb - b2f(f2b(vb)));
            }
#pragma unroll
            for (int j = 0; j < 32; j++) sbuf[lane * 33 + j] = hiw[j];
            __syncwarp();
#pragma unroll
            for (int i = 0; i < 32; i++){
                int r = row0 + i, bs = r >> 10, l = r & 1023;
                size_t wb = (((size_t)(bs * 16 + h)) << 15) + ((size_t)l << 5);
                ((u32*)oHi)[wb + lane] = sbuf[i * 33 + lane];
            }
            __syncwarp();
#pragma unroll
            for (int j = 0; j < 32; j++) sbuf[lane * 33 + j] = low[j];
            __syncwarp();
#pragma unroll
            for (int i = 0; i < 32; i++){
                int r = row0 + i, bs = r >> 10, l = r & 1023;
                size_t wb = (((size_t)(bs * 16 + h)) << 15) + ((size_t)l << 5);
                ((u32*)oLo)[wb + lane] = sbuf[i * 33 + lane];
            }
        } else if (mode == 2){
            const int bs = row >> 10, l = row & 1023;
            const int h  = (n0 + cb) >> 6;
            const size_t base = ((size_t)(bs * 16 + h) * 64) * 1024 + l;
            const float* bias = aux + n0 + cb;
#pragma unroll
            for (int j = 0; j < 64; j++){
                float va = __uint_as_float(dr[j]) + bias[j];
                u16 hh = f2h(va);
                oHi[base + (size_t)j * 1024] = hh;
                oLo[base + (size_t)j * 1024] = f2h(va - h2f(hh));
            }
        }
    }
    __syncthreads();
    if (tid == 0){ MBAR_INVAL(mb0); MBAR_INVAL(mb1); }
    __syncthreads();
    if (w == 0) TC_DEALLOC(tmem, TCOLS);

#else
    // ---------- mma.sync fallback (compile-only; driver picks sm_103a) -----
    constexpr int WGM = 2, WGN = 4, PITCH = 40;
    constexpr int ASZ = 128 * PITCH;
    constexpr int BSZ = BN * PITCH;
    constexpr int STAGE = 2 * ASZ + 2 * BSZ;
    constexpr int WTM = 128 / WGM;
    constexpr int WTN = BN / WGN;
    constexpr int MT = WTM / 16;
    constexpr int NT16 = WTN / 16;

    const unsigned sbase = smem_u32p(smem);
    const int wm = (w / WGN) * WTM;
    const int wn = (w % WGN) * WTN;
    const int lrow = (lane & 7) + ((lane >> 3) & 1) * 8;
    const int lcol = (lane >> 4) * 8;

    float acc[MT][NT16 * 2][4];
#pragma unroll
    for (int i = 0; i < MT; i++)
#pragma unroll
        for (int j = 0; j < NT16 * 2; j++)
#pragma unroll
            for (int t = 0; t < 4; t++) acc[i][j][t] = 0.f;

    auto load_stage = [&](int s){
        const int k0 = s << 5;
        const unsigned sd = sbase + (unsigned)((s & 1) * STAGE) * 2u;
#pragma unroll
        for (int it = 0; it < 2; it++){
            int idx = tid + it * 256;
            int r = idx >> 2, c = idx & 3;
            size_t g = (size_t)(m0 + r) * K + k0 + c * 8;
            unsigned d = sd + (unsigned)(r * PITCH + c * 8) * 2u;
            cpa16(d, Ah + g);
            cpa16(d + ASZ * 2, Al + g);
        }
#pragma unroll
        for (int it = 0; it < (BN * 4) / 256; it++){
            int idx = tid + it * 256;
            int r = idx >> 2, c = idx & 3;
            size_t g = (size_t)(n0 + r) * K + k0 + c * 8;
            unsigned d = sd + (unsigned)(2 * ASZ + r * PITCH + c * 8) * 2u;
            cpa16(d, Bh + g);
            cpa16(d + BSZ * 2, Bl + g);
        }
        CPA_COMMIT();
    };

    const int NS = K >> 5;
    load_stage(0);

    for (int s = 0; s < NS; s++){
        if (s + 1 < NS){ load_stage(s + 1); cpa_wait<1>(); }
        else           { cpa_wait<0>(); }
        __syncthreads();

        const unsigned sd = sbase + (unsigned)((s & 1) * STAGE) * 2u;
#pragma unroll
        for (int k16 = 0; k16 < 2; k16++){
            const int kc = k16 * 16 + lcol;
            u32 ah[MT][4], al[MT][4], bh[NT16][4], bl[NT16][4];
#pragma unroll
            for (int mt = 0; mt < MT; mt++){
                unsigned a = sd + (unsigned)((wm + mt * 16 + lrow) * PITCH + kc) * 2u;
                ldmx4(ah[mt][0], ah[mt][1], ah[mt][2], ah[mt][3], a);
                ldmx4(al[mt][0], al[mt][1], al[mt][2], al[mt][3], a + ASZ * 2);
            }
#pragma unroll
            for (int nt = 0; nt < NT16; nt++){
                unsigned a = sd + (unsigned)(2 * ASZ + (wn + nt * 16 + lrow) * PITCH + kc) * 2u;
                ldmx4(bh[nt][0], bh[nt][1], bh[nt][2], bh[nt][3], a);
                ldmx4(bl[nt][0], bl[nt][1], bl[nt][2], bl[nt][3], a + BSZ * 2);
            }
#pragma unroll
            for (int mt = 0; mt < MT; mt++)
#pragma unroll
                for (int nt = 0; nt < NT16; nt++){
                    mma16816(acc[mt][2*nt],   ah[mt], bh[nt][0], bh[nt][2]);
                    mma16816(acc[mt][2*nt+1], ah[mt], bh[nt][1], bh[nt][3]);
                    mma16816(acc[mt][2*nt],   ah[mt], bl[nt][0], bl[nt][2]);
                    mma16816(acc[mt][2*nt+1], ah[mt], bl[nt][1], bl[nt][3]);
                    if (APASS == 2){
                        mma16816(acc[mt][2*nt],   al[mt], bh[nt][0], bh[nt][2]);
                        mma16816(acc[mt][2*nt+1], al[mt], bh[nt][1], bh[nt][3]);
                    }
                }
        }
        __syncthreads();
    }

    auto store_pair = [&](int row, int col, float va, float vb){
        if (mode == 0){
            float2 o; o.x = va + aux[col]; o.y = vb + aux[col + 1];
            *(float2*)(outF + (size_t)row * 1024 + col) = o;
        } else if (mode == 1){
            va += aux[col]; vb += aux[col + 1];
            int bs = row >> 10, l = row & 1023, h = col >> 6, d = col & 63;
            size_t idx = (((size_t)(bs * 16 + h)) << 16) + ((size_t)l << 6) + d;
            *(u32*)(oHi + idx) = pack2(va, vb);
            *(u32*)(oLo + idx) = pack2(va - b2f(f2b(va)), vb - b2f(f2b(vb)));
        } else if (mode == 2){
            va += aux[col]; vb += aux[col + 1];
            int bs = row >> 10, l = row & 1023, h = col >> 6, d = col & 63;
            size_t base = ((size_t)(bs * 16 + h) * 64 + d) * 1024 + l;
            u16 h0 = f2h(va), h1 = f2h(vb);
            oHi[base] = h0;        oHi[base + 1024] = h1;
            oLo[base] = f2h(va - h2f(h0));
            oLo[base + 1024] = f2h(vb - h2f(h1));
        }
    };

#pragma unroll
    for (int mt = 0; mt < MT; mt++)
#pragma unroll
        for (int nt8 = 0; nt8 < NT16 * 2; nt8++){
            int r0 = m0 + wm + mt * 16 + (lane >> 2);
            int c0 = n0 + wn + nt8 * 8 + (lane & 3) * 2;
            store_pair(r0,     c0, acc[mt][nt8][0], acc[mt][nt8][1]);
            store_pair(r0 + 8, c0, acc[mt][nt8][2], acc[mt][nt8][3]);
        }
#endif
}

// ---------------------------------------------------------------------------
// Fused QK kernel (unchanged from R10): per CTA (q-tile 128, z), 8 k-tiles.
// Writes fp16 probs (exp, mask bits) and full row sums to g_rsum.
// ---------------------------------------------------------------------------
__global__ void __launch_bounds__(256) qk_tc(
    const u16* __restrict__ qhH, const u16* __restrict__ qhL,
    const u16* __restrict__ khH, const u16* __restrict__ khL)
{
    extern __shared__ char smem[];
    const int tid  = threadIdx.x;
    const int w    = tid >> 5;
    const int lane = tid & 31;
    const int m0   = blockIdx.x * 128;
    const int z    = blockIdx.y;
    const int bs   = z >> 4;

    const u16* Qh = qhH + (size_t)z * 65536;
    const u16* Ql = qhL + (size_t)z * 65536;
    const u16* Kh = khH + (size_t)z * 65536;
    const u16* Kl = khL + (size_t)z * 65536;

#if HAS_TCGEN05
    constexpr u32 IDESC =
        (1u << 4) | (1u << 7) | (1u << 10) | (16u << 17) | (8u << 24);

    const unsigned sb   = smem_u32p(smem);
    const unsigned mb0  = sb + 8;
    const unsigned mb1  = sb + 16;
    const unsigned qbuf = sb + 1024;
    const unsigned kbuf = qbuf + 32768;

    if (w == 0){ TC_ALLOC(sb, 128); }
    if (tid == 0){ MBAR_INIT(mb0, 1); MBAR_INIT(mb1, 1); }
    __syncthreads();
    unsigned tmem;
    asm volatile("ld.shared.b32 %0, [%1];" : "=r"(tmem) : "r"(sb));

    auto loadK = [&](int kt){
        const unsigned bb = kbuf + (unsigned)(kt & 1) * 32768;
#pragma unroll
        for (int it = 0; it < 4; it++){
            int idx = tid + it * 256;
            int r = idx >> 3, c = idx & 7;
            int off = r * 128 + c * 16;
            unsigned sw = (unsigned)(off ^ ((off >> 3) & 0x70));
            size_t g = (size_t)(kt * 128 + r) * 64 + c * 8;
            cpa16(bb + sw,         Kh + g);
            cpa16(bb + 16384 + sw, Kl + g);
        }
        CPA_COMMIT();
    };

    {
#pragma unroll
        for (int it = 0; it < 4; it++){
            int idx = tid + it * 256;
            int r = idx >> 3, c = idx & 7;
            int off = r * 128 + c * 16;
            unsigned sw = (unsigned)(off ^ ((off >> 3) & 0x70));
            size_t g = (size_t)(m0 + r) * 64 + c * 8;
            cpa16(qbuf + sw,         Qh + g);
            cpa16(qbuf + 16384 + sw, Ql + g);
        }
        const unsigned bb = kbuf;
#pragma unroll
        for (int it = 0; it < 4; it++){
            int idx = tid + it * 256;
            int r = idx >> 3, c = idx & 7;
            int off = r * 128 + c * 16;
            unsigned sw = (unsigned)(off ^ ((off >> 3) & 0x70));
            size_t g = (size_t)r * 64 + c * 8;
            cpa16(bb + sw,         Kh + g);
            cpa16(bb + 16384 + sw, Kl + g);
        }
        CPA_COMMIT();
        loadK(1);
    }

    const int sub = w & 3;
    const int cb  = (w >> 2) * 64;
    const int row0 = m0 + sub * 32;
    const int row  = row0 + lane;
    u32* sbuf = (u32*)(smem + 99328) + (size_t)w * (32 * 33);
    float rs = 0.f;
    unsigned ph0 = 0, ph1 = 0;

    for (int kt = 0; kt < 8; kt++){
        if (kt == 7) cpa_wait<0>(); else cpa_wait<1>();
        __syncthreads();

        if (w == 0 && elect1()){
            TC_FENCE_AFTER();
            FENCE_ASYNC();
            u64 qd  = mk_desc(qbuf);
            u64 qld = mk_desc(qbuf + 16384);
            const unsigned bb = kbuf + (unsigned)(kt & 1) * 32768;
            u64 kd  = mk_desc(bb);
            u64 kld = mk_desc(bb + 16384);
#pragma unroll
            for (int ks = 0; ks < 4; ks++)
                mma_ss(tmem, qd + 2 * ks, kd + 2 * ks, IDESC, ks > 0 ? 1u : 0u);
#pragma unroll
            for (int ks = 0; ks < 4; ks++)
                mma_ss(tmem, qd + 2 * ks, kld + 2 * ks, IDESC, 1u);
#pragma unroll
            for (int ks = 0; ks < 4; ks++)
                mma_ss(tmem, qld + 2 * ks, kd + 2 * ks, IDESC, 1u);
            TC_COMMIT((kt & 1) ? mb1 : mb0);
        }
        if (kt & 1){ mbar_wait(mb1, ph1); ph1 ^= 1; }
        else       { mbar_wait(mb0, ph0); ph0 ^= 1; }
        TC_FENCE_AFTER();

        if (kt + 2 < 8) loadK(kt + 2);

        u32 dr[64];
        TC_LD32(dr,      tmem + cb);
        TC_LD32(dr + 32, tmem + cb + 32);
        TC_WAITLD();
        TC_FENCE_BEFORE();

        const int c0 = kt * 128 + cb;
        const size_t widx = ((size_t)bs << 15) + ((size_t)row << 5) + (c0 >> 5);
        const u32 w0 = g_mbits[widx];
        const u32 w1 = g_mbits[widx + 1];

        float part = 0.f;
        u32 pw[32];
#pragma unroll
        for (int j = 0; j < 32; j++){
            int c = 2 * j;
            u32 wa = (c < 32) ? w0 : w1;
            u32 wbq = (c + 1 < 32) ? w0 : w1;
            float ea = ((wa >> (c & 31)) & 1) ? 0.f
                     : __expf(__uint_as_float(dr[2*j]) * 0.125f);
            float eb = ((wbq >> ((c + 1) & 31)) & 1) ? 0.f
                     : __expf(__uint_as_float(dr[2*j+1]) * 0.125f);
            part += ea + eb;
            pw[j] = pack2h(ea, eb);
        }
        rs += part;
#pragma unroll
        for (int j = 0; j < 32; j++) sbuf[lane * 33 + j] = pw[j];
        __syncwarp();
#pragma unroll
        for (int i = 0; i < 32; i++){
            size_t wb = ((size_t)z << 19) + ((size_t)(row0 + i) << 9)
                      + (size_t)(c0 >> 1);
            ((u32*)g_p)[wb + lane] = sbuf[i * 33 + lane];
        }
        __syncwarp();
    }

    __syncthreads();
    float* fs = (float*)(smem + 99328);
    fs[(w >> 2) * 128 + sub * 32 + lane] = rs;
    __syncthreads();
    if (w < 4){
        int rl = w * 32 + lane;
        g_rsum[(size_t)z * 1024 + m0 + rl] = fs[rl] + fs[128 + rl];
    }
    __syncthreads();
    if (tid == 0){ MBAR_INVAL(mb0); MBAR_INVAL(mb1); }
    __syncthreads();
    if (w == 0) TC_DEALLOC(tmem, 128);

#else
    for (int idx = tid; idx < 128 * 1024; idx += 256){
        int r = m0 + (idx >> 10);
        int c = idx & 1023;
        u32 wm_ = g_mbits[((size_t)bs << 15) + ((size_t)r << 5) + (c >> 5)];
        float p = 0.f;
        if (!((wm_ >> (c & 31)) & 1)){
            float s = 0.f;
            for (int d = 0; d < 64; d++){
                float qv = b2f(Qh[(size_t)r * 64 + d]) + b2f(Ql[(size_t)r * 64 + d]);
                float kv = b2f(Kh[(size_t)c * 64 + d]) + b2f(Kl[(size_t)c * 64 + d]);
                s += qv * kv;
            }
            p = __expf(s * 0.125f);
        }
        g_p[((size_t)z << 20) + ((size_t)r << 10) + c] = f2h(p);
        atomicAdd(&g_rsum[(size_t)z * 1024 + r], p);
    }
#endif
}

// ---------------------------------------------------------------------------
// Fused PV + head-mean: grid (8 q-tiles, 16 bs, 2 halves).
// CTA loops kc(16) x h(8): MMA ctx_h (TMEM cols h*64), and accumulates
// sum_h p*rinv into registers -> head-mean partial (half0->attn_mean, 1->g_attn2).
// Ctx written normalized (x rinv) in staged-coalesced form.
// ---------------------------------------------------------------------------
__global__ void __launch_bounds__(256) pv_tc(
    float* __restrict__ attn0, float* __restrict__ attn1)
{
    extern __shared__ char smem[];
    const int tid  = threadIdx.x;
    const int w    = tid >> 5;
    const int lane = tid & 31;
    const int m0   = blockIdx.x * 128;
    const int bs   = blockIdx.y;
    const int half = blockIdx.z;
    const int zb   = bs * 16 + half * 8;

#if HAS_TCGEN05
    constexpr u32 IDESC =           // fp16, N=64, M=128
        (1u << 4) | (8u << 17) | (8u << 24);

    const unsigned sb   = smem_u32p(smem);
    const unsigned mb0  = sb + 8;
    const unsigned mb1  = sb + 16;
    const unsigned buf0 = sb + 1024;     // stage: p 16K + Vhi 8K + Vlo 8K = 32K, x2

    if (w == 0){ TC_ALLOC(sb, 512); }
    if (tid == 0){ MBAR_INIT(mb0, 1); MBAR_INIT(mb1, 1); }
    __syncthreads();
    unsigned tmem;
    asm volatile("ld.shared.b32 %0, [%1];" : "=r"(tmem) : "r"(sb));

    auto load_stage = [&](int s){
        const int h = s & 7, kc = s >> 3;
        const int z = zb + h;
        const unsigned bb = buf0 + (unsigned)(s & 1) * 32768;
#pragma unroll
        for (int it = 0; it < 4; it++){        // p: 128 rows x 128B
            int idx = tid + it * 256;
            int r = idx >> 3, c = idx & 7;
            int off = r * 128 + c * 16;
            unsigned sw = (unsigned)(off ^ ((off >> 3) & 0x70));
            const u16* src = g_p + ((size_t)z << 20)
                           + (size_t)(m0 + r) * 1024 + kc * 64 + c * 8;
            cpa16(bb + sw, src);
        }
#pragma unroll
        for (int it = 0; it < 2; it++){        // V hi/lo: 64 rows x 128B
            int idx = tid + it * 256;
            int r = idx >> 3, c = idx & 7;
            int off = r * 128 + c * 16;
            unsigned sw = (unsigned)(off ^ ((off >> 3) & 0x70));
            size_t g = (size_t)z * 65536 + (size_t)r * 1024 + kc * 64 + c * 8;
            cpa16(bb + 16384 + sw, g_vt_hi + g);
            cpa16(bb + 24576 + sw, g_vt_lo + g);
        }
        CPA_COMMIT();
    };

    const int ar = tid >> 1;            // attn row 0..127
    const int ac = (tid & 1) * 32;      // attn col base within 64-chunk
    float rv8[8];
#pragma unroll
    for (int h = 0; h < 8; h++)
        rv8[h] = g_rinv[(size_t)(zb + h) * 1024 + m0 + ar];
    float aacc[32];
#pragma unroll
    for (int j = 0; j < 32; j++) aacc[j] = 0.f;

    load_stage(0);
    load_stage(1);
    unsigned ph0 = 0, ph1 = 0;

    for (int s = 0; s < 128; s++){
        if (s == 127) cpa_wait<0>(); else cpa_wait<1>();
        __syncthreads();

        const int h = s & 7, kc = s >> 3;
        const unsigned bb = buf0 + (unsigned)(s & 1) * 32768;

        if (w == 0 && elect1()){
            FENCE_ASYNC();
            u64 pd = mk_desc(bb);
            u64 vh = mk_desc(bb + 16384);
            u64 vl = mk_desc(bb + 24576);
            const unsigned dst = tmem + (unsigned)h * 64;
#pragma unroll
            for (int ks = 0; ks < 4; ks++)
                mma_ss(dst, pd + 2 * ks, vh + 2 * ks, IDESC,
                       (kc > 0 || ks > 0) ? 1u : 0u);
#pragma unroll
            for (int ks = 0; ks < 4; ks++)
                mma_ss(dst, pd + 2 * ks, vl + 2 * ks, IDESC, 1u);
            TC_COMMIT((s & 1) ? mb1 : mb0);
        }

        // head-mean accumulation from the smem p tile
        {
            const float rv = rv8[h];
#pragma unroll
            for (int g = 0; g < 4; g++){
                int off = ar * 128 + (ac + g * 8) * 2;
                unsigned sw = (unsigned)(off ^ ((off >> 3) & 0x70));
                u32 x0, x1, x2, x3;
                asm volatile("ld.shared.v4.u32 {%0,%1,%2,%3}, [%4];"
                             : "=r"(x0), "=r"(x1), "=r"(x2), "=r"(x3)
                             : "r"(bb + sw));
                aacc[g*8+0] += h2f((u16)x0) * rv;
                aacc[g*8+1] += h2f((u16)(x0 >> 16)) * rv;
                aacc[g*8+2] += h2f((u16)x1) * rv;
                aacc[g*8+3] += h2f((u16)(x1 >> 16)) * rv;
                aacc[g*8+4] += h2f((u16)x2) * rv;
                aacc[g*8+5] += h2f((u16)(x2 >> 16)) * rv;
                aacc[g*8+6] += h2f((u16)x3) * rv;
                aacc[g*8+7] += h2f((u16)(x3 >> 16)) * rv;
            }
        }
        if (h == 7){
            float* dst = (half ? attn1 : attn0)
                       + ((size_t)bs << 20) + ((size_t)(m0 + ar) << 10)
                       + kc * 64 + ac;
#pragma unroll
            for (int j4 = 0; j4 < 8; j4++){
                float4 o;
                o.x = aacc[j4*4+0] * 0.0625f;
                o.y = aacc[j4*4+1] * 0.0625f;
                o.z = aacc[j4*4+2] * 0.0625f;
                o.w = aacc[j4*4+3] * 0.0625f;
                *(float4*)(dst + j4 * 4) = o;
            }
#pragma unroll
            for (int j = 0; j < 32; j++) aacc[j] = 0.f;
        }
        __syncthreads();                 // p reads done before buffer reuse

        if (s + 2 < 128){
            if (s & 1){ mbar_wait(mb1, ph1); ph1 ^= 1; }
            else      { mbar_wait(mb0, ph0); ph0 ^= 1; }
            load_stage(s + 2);
        }
    }
    mbar_wait(mb0, ph0);                 // s=126 (different TMEM cols!)
    mbar_wait(mb1, ph1);                 // s=127
    TC_FENCE_AFTER();

    // ctx epilogue: 8 heads, two warp-groups handle 4 each
    const int sub = w & 3;
    const int row0 = m0 + sub * 32;
    const int row  = row0 + lane;
    u32* sbuf = (u32*)(smem + 1024) + (size_t)w * (32 * 33);

#pragma unroll
    for (int it = 0; it < 4; it++){
        const int h = (w >> 2) * 4 + it;
        u32 dr[64];
        TC_LD32(dr,      tmem + h * 64);
        TC_LD32(dr + 32, tmem + h * 64 + 32);
        TC_WAITLD();
        TC_FENCE_BEFORE();
        const float inv = g_rinv[(size_t)(zb + h) * 1024 + row];
        const int hg = half * 8 + h;
        u32 hiw[32], low[32];
#pragma unroll
        for (int j = 0; j < 32; j++){
            float va = __uint_as_float(dr[2*j])   * inv;
            float vb = __uint_as_float(dr[2*j+1]) * inv;
            hiw[j] = pack2(va, vb);
            low[j] = pack2(va - b2f(f2b(va)), vb - b2f(f2b(vb)));
        }
#pragma unroll
        for (int j = 0; j < 32; j++) sbuf[lane * 33 + j] = hiw[j];
        __syncwarp();
#pragma unroll
        for (int i = 0; i < 32; i++){
            size_t wb = (((size_t)(bs * 1024 + row0 + i)) << 9) + (size_t)hg * 32;
            ((u32*)g_ctx_hi)[wb + lane] = sbuf[i * 33 + lane];
        }
        __syncwarp();
#pragma unroll
        for (int j = 0; j < 32; j++) sbuf[lane * 33 + j] = low[j];
        __syncwarp();
#pragma unroll
        for (int i = 0; i < 32; i++){
            size_t wb = (((size_t)(bs * 1024 + row0 + i)) << 9) + (size_t)hg * 32;
            ((u32*)g_ctx_lo)[wb + lane] = sbuf[i * 33 + lane];
        }
        __syncwarp();
    }
    __syncthreads();
    if (tid == 0){ MBAR_INVAL(mb0); MBAR_INVAL(mb1); }
    __syncthreads();
    if (w == 0) TC_DEALLOC(tmem, 512);

#else
    // naive fallback (compile-only; sm_103a cubin is selected at runtime)
    for (int h = 0; h < 8; h++){
        const int z = zb + h;
        for (int idx = tid; idx < 128 * 64; idx += 256){
            int r = idx >> 6, d = idx & 63;
            float acc = 0.f;
            for (int k = 0; k < 1024; k++)
                acc += h2f(g_p[((size_t)z << 20) + (size_t)(m0 + r) * 1024 + k]) *
                       (h2f(g_vt_hi[(size_t)z * 65536 + (size_t)d * 1024 + k]) +
                        h2f(g_vt_lo[(size_t)z * 65536 + (size_t)d * 1024 + k]));
            float inv = g_rinv[(size_t)z * 1024 + m0 + r];
            float va = acc * inv;
            size_t o = (((size_t)(bs * 1024 + m0 + r)) << 10) + (half * 8 + h) * 64 + d;
            u16 hh = f2b(va);
            g_ctx_hi[o] = hh;
            g_ctx_lo[o] = f2b(va - b2f(hh));
        }
    }
    for (int idx = tid; idx < 128 * 1024; idx += 256){
        int r = idx >> 10, k = idx & 1023;
        float s = 0.f;
        for (int h = 0; h < 8; h++){
            const int z = zb + h;
            s += h2f(g_p[((size_t)z << 20) + (size_t)(m0 + r) * 1024 + k]) *
                 g_rinv[(size_t)z * 1024 + m0 + r];
        }
        (half ? attn1 : attn0)[((size_t)bs << 20) + ((size_t)(m0 + r) << 10) + k]
            = s * 0.0625f;
    }
#endif
}

// ---------------------------------------------------------------------------
__global__ __launch_bounds__(256) void combine_attn(float* __restrict__ am)
{
    const int i = blockIdx.x * 256 + threadIdx.x;
    float4 a = ((float4*)am)[i];
    float4 b = ((const float4*)g_attn2)[i];
    a.x += b.x; a.y += b.y; a.z += b.z; a.w += b.w;
    ((float4*)am)[i] = a;
}

// ---------------------------------------------------------------------------
__global__ __launch_bounds__(256) void mask_bits_kernel(const float* __restrict__ mask)
{
    const int warpid = (blockIdx.x * 256 + threadIdx.x) >> 5;
    const int lane = threadIdx.x & 31;
    const size_t base = (size_t)warpid * 1024;
#pragma unroll
    for (int b = 0; b < 32; b++){
        float v = mask[base + b * 32 + lane];
        u32 bits = __ballot_sync(0xFFFFFFFFu, v > 0.5f);
        if (lane == b) g_mbits[base / 32 + b] = bits;
    }
}

__global__ __launch_bounds__(256) void zero_rsum()
{
    const int i = blockIdx.x * 256 + threadIdx.x;
    ((float4*)g_rsum)[i] = make_float4(0.f, 0.f, 0.f, 0.f);
}

__global__ __launch_bounds__(256) void invert_rsum()
{
    const int i = blockIdx.x * 256 + threadIdx.x;
    g_rinv[i] = __frcp_rn(g_rsum[i]);
}

// ---------------------------------------------------------------------------
__global__ __launch_bounds__(256) void conv_act(
    const float* __restrict__ in, u16* __restrict__ hi, u16* __restrict__ lo)
{
    const int i = blockIdx.x * 256 + threadIdx.x;
    float4 v = ((const float4*)in)[i];
    u32 h0 = pack2(v.x, v.y), h1 = pack2(v.z, v.w);
    ((u32*)hi)[i * 2]     = h0;
    ((u32*)hi)[i * 2 + 1] = h1;
    ((u32*)lo)[i * 2]     = pack2(v.x - b2f((u16)h0), v.y - b2f((u16)(h0 >> 16)));
    ((u32*)lo)[i * 2 + 1] = pack2(v.z - b2f((u16)h1), v.w - b2f((u16)(h1 >> 16)));
}

// ---------------------------------------------------------------------------
__global__ __launch_bounds__(256) void conv_wT(
    const float* __restrict__ W, u16* __restrict__ hi, u16* __restrict__ lo)
{
    __shared__ float tile[32][33];
    const int tx = threadIdx.x, ty = threadIdx.y;
    const int kb = blockIdx.y * 32, nb = blockIdx.x * 32;
#pragma unroll
    for (int i = 0; i < 4; i++)
        tile[ty + i * 8][tx] = W[(size_t)(kb + ty + i * 8) * 1024 + nb + tx];
    __syncthreads();
#pragma unroll
    for (int i = 0; i < 4; i++){
        int n = nb + ty + i * 8, k = kb + tx;
        float v = tile[tx][ty + i * 8];
        u16 h = f2b(v);
        hi[(size_t)n * 1024 + k] = h;
        lo[(size_t)n * 1024 + k] = f2b(v - b2f(h));
    }
}

// ---------------------------------------------------------------------------
extern "C" void kernel_launch(void* const* d_in, const int* in_sizes, int n_in,
                              void* d_out, int out_size)
{
    const float* q    = (const float*)d_in[0];
    const float* k    = (const float*)d_in[1];
    const float* v    = (const float*)d_in[2];
    const float* mask = (const float*)d_in[3];
    const float* wq   = (const float*)d_in[4];
    const float* bq   = (const float*)d_in[5];
    const float* wk   = (const float*)d_in[6];
    const float* bk   = (const float*)d_in[7];
    const float* wv   = (const float*)d_in[8];
    const float* bv   = (const float*)d_in[9];
    const float* wo   = (const float*)d_in[10];
    const float* bo   = (const float*)d_in[11];

    float* out       = (float*)d_out;
    float* attn_mean = out + 16777216;

    u16 *wtH, *wtL, *aH, *aL, *qhH, *qhL, *khH, *khL, *vtH, *vtL, *cxH, *cxL;
    float* a2;
    cudaGetSymbolAddress((void**)&wtH, g_wt_hi);
    cudaGetSymbolAddress((void**)&wtL, g_wt_lo);
    cudaGetSymbolAddress((void**)&aH,  g_a_hi);
    cudaGetSymbolAddress((void**)&aL,  g_a_lo);
    cudaGetSymbolAddress((void**)&qhH, g_qh_hi);
    cudaGetSymbolAddress((void**)&qhL, g_qh_lo);
    cudaGetSymbolAddress((void**)&khH, g_kh_hi);
    cudaGetSymbolAddress((void**)&khL, g_kh_lo);
    cudaGetSymbolAddress((void**)&vtH, g_vt_hi);
    cudaGetSymbolAddress((void**)&vtL, g_vt_lo);
    cudaGetSymbolAddress((void**)&cxH, g_ctx_hi);
    cudaGetSymbolAddress((void**)&cxL, g_ctx_lo);
    cudaGetSymbolAddress((void**)&a2,  g_attn2);

    constexpr int SMEM_BIG = 1024 + 2 * (2 * 128 * 128 + 2 * 128 * 128); // 132096
    constexpr int SMEM_QK  = 1024 + 32768 + 65536 + 33792;               // 133120
    constexpr int SMEM_PV  = 1024 + 2 * 32768;                           //  66560
    cudaFuncSetAttribute(gemm_any<128,1,2>,
                         cudaFuncAttributeMaxDynamicSharedMemorySize, SMEM_BIG);
    cudaFuncSetAttribute(qk_tc,
                         cudaFuncAttributeMaxDynamicSharedMemorySize, SMEM_QK);
    cudaFuncSetAttribute(pv_tc,
                         cudaFuncAttributeMaxDynamicSharedMemorySize, SMEM_PV);

    dim3 wtg(32, 32);
    dim3 wtb(32, 8);
    conv_wT<<<wtg, wtb>>>(wq, wtH + 0u,       wtL + 0u);
    conv_wT<<<wtg, wtb>>>(wk, wtH + 1048576u, wtL + 1048576u);
    conv_wT<<<wtg, wtb>>>(wv, wtH + 2097152u, wtL + 2097152u);
    conv_wT<<<wtg, wtb>>>(wo, wtH + 3145728u, wtL + 3145728u);
    mask_bits_kernel<<<2048, 256>>>(mask);
    zero_rsum<<<256, 256>>>();

    dim3 projGrid(8, 128, 1);

    conv_act<<<16384, 256>>>(q, aH, aL);
    gemm_any<128,1,2><<<projGrid, 256, SMEM_BIG>>>(
        aH, aL, 0, wtH + 0u, wtL + 0u, 0, 1024, 1, nullptr, qhH, qhL, bq);
    conv_act<<<16384, 256>>>(k, aH, aL);
    gemm_any<128,1,2><<<projGrid, 256, SMEM_BIG>>>(
        aH, aL, 0, wtH + 1048576u, wtL + 1048576u, 0, 1024, 1, nullptr, khH, khL, bk);
    conv_act<<<16384, 256>>>(v, aH, aL);
    gemm_any<128,1,2><<<projGrid, 256, SMEM_BIG>>>(
        aH, aL, 0, wtH + 2097152u, wtL + 2097152u, 0, 1024, 2, nullptr, vtH, vtL, bv);

    // fused QK: probs + row sums
    qk_tc<<<dim3(8, 256), 256, SMEM_QK>>>(qhH, qhL, khH, khL);
    invert_rsum<<<1024, 256>>>();

    // fused PV + head-mean partials
    pv_tc<<<dim3(8, 16, 2), 256, SMEM_PV>>>(attn_mean, a2);
    combine_attn<<<16384, 256>>>(attn_mean);

    // out projection
    gemm_any<128,1,2><<<projGrid, 256, SMEM_BIG>>>(
        cxH, cxL, 0, wtH + 3145728u, wtL + 3145728u, 0, 1024, 0, out, nullptr, nullptr, bo);
}

// round 13
// speedup vs baseline: 2.6170x; 1.0676x over previous
#include <cuda_runtime.h>
#include <cuda_bf16.h>
#include <cuda_fp16.h>

typedef unsigned short u16;
typedef unsigned int   u32;
typedef unsigned long long u64;

#if defined(__CUDA_ARCH_FEAT_SM103_ALL) || defined(__CUDA_ARCH_FEAT_SM100_ALL)
#define HAS_TCGEN05 1
#else
#define HAS_TCGEN05 0
#endif

// ---------------- device scratch (allocation-free rule) --------------------
__device__ u16 g_wt_hi[4u*1024u*1024u];   // 4 weights, transposed [n][k] bf16
__device__ u16 g_wt_lo[4u*1024u*1024u];
__device__ u16 g_a_hi[16777216];          // activation staging bf16 (reused)
__device__ u16 g_a_lo[16777216];
__device__ u16 g_qh_hi[16777216];         // [bsh][l][64] bf16
__device__ u16 g_qh_lo[16777216];
__device__ u16 g_kh_hi[16777216];
__device__ u16 g_kh_lo[16777216];
__device__ u16 g_vt_hi[16777216];         // [bsh][d=64][l=1024] fp16
__device__ u16 g_vt_lo[16777216];
__device__ u16 g_p[268435456];            // unnormalized exp probs fp16
__device__ u32 g_mbits[524288];           // mask bitmask: [bs][row][32 words]
__device__ float g_rsum[262144];          // [bsh][row] row sums
__device__ float g_rinv[262144];          // [bsh][row] 1/rowsum
__device__ u16 g_ctx_hi[16777216];        // merged [bs*L+q][1024] bf16
__device__ u16 g_ctx_lo[16777216];
__device__ float g_attn2[16777216];       // head-mean partial (heads 8-15)

// ---------------- helpers --------------------------------------------------
__device__ __forceinline__ u16 f2b(float x){
    return __bfloat16_as_ushort(__float2bfloat16_rn(x));
}
__device__ __forceinline__ float b2f(u16 u){
    return __bfloat162float(__ushort_as_bfloat16(u));
}
__device__ __forceinline__ u32 pack2(float a, float b){
    return (u32)f2b(a) | ((u32)f2b(b) << 16);
}
__device__ __forceinline__ u16 f2h(float x){
    return __half_as_ushort(__float2half_rn(x));
}
__device__ __forceinline__ float h2f(u16 u){
    return __half2float(__ushort_as_half(u));
}
__device__ __forceinline__ u32 pack2h(float a, float b){
    return (u32)f2h(a) | ((u32)f2h(b) << 16);
}
__device__ __forceinline__ unsigned smem_u32p(const void* p){
    unsigned a;
    asm("{ .reg .u64 t; cvta.to.shared.u64 t, %1; cvt.u32.u64 %0, t; }"
        : "=r"(a) : "l"(p));
    return a;
}
__device__ __forceinline__ void cpa16(unsigned dst, const void* src){
    asm volatile("cp.async.cg.shared.global [%0], [%1], 16;" :: "r"(dst), "l"(src));
}
#define CPA_COMMIT() asm volatile("cp.async.commit_group;" ::: "memory")
template<int N> __device__ __forceinline__ void cpa_wait(){
    asm volatile("cp.async.wait_group %0;" :: "n"(N) : "memory");
}

#if HAS_TCGEN05
__device__ __forceinline__ unsigned elect1(){
    unsigned p;
    asm volatile("{ .reg .pred P; elect.sync _|P, 0xFFFFFFFF; selp.b32 %0, 1, 0, P; }"
                 : "=r"(p));
    return p;
}
#define MBAR_INIT(a, c) \
    asm volatile("mbarrier.init.shared.b64 [%0], %1;" :: "r"(a), "r"(c) : "memory")
#define MBAR_INVAL(a) \
    asm volatile("mbarrier.inval.shared.b64 [%0];" :: "r"(a) : "memory")
__device__ __forceinline__ void mbar_wait(unsigned a, unsigned ph){
    asm volatile(
        "{\n\t.reg .pred P;\n"
        "W%=:\n\t"
        "mbarrier.try_wait.parity.acquire.cta.shared::cta.b64 P, [%0], %1, 0x989680;\n\t"
        "@P bra D%=;\n\t"
        "bra W%=;\n"
        "D%=:\n\t}"
        :: "r"(a), "r"(ph) : "memory");
}
#define TC_ALLOC(sa, n) \
    asm volatile("tcgen05.alloc.cta_group::1.sync.aligned.shared::cta.b32 [%0], %1;" \
                 :: "r"(sa), "r"(n) : "memory")
#define TC_DEALLOC(t, n) \
    asm volatile("tcgen05.dealloc.cta_group::1.sync.aligned.b32 %0, %1;" :: "r"(t), "r"(n))
#define TC_COMMIT(mb) \
    asm volatile("tcgen05.commit.cta_group::1.mbarrier::arrive::one.shared::cluster.b64 [%0];" \
                 :: "r"(mb) : "memory")
#define TC_FENCE_AFTER()  asm volatile("tcgen05.fence::after_thread_sync;" ::: "memory")
#define TC_FENCE_BEFORE() asm volatile("tcgen05.fence::before_thread_sync;" ::: "memory")
#define TC_WAITLD()       asm volatile("tcgen05.wait::ld.sync.aligned;" ::: "memory")
#define FENCE_ASYNC()     asm volatile("fence.proxy.async.shared::cta;" ::: "memory")

#define TC_LD32(r, addr) \
    asm volatile( \
        "tcgen05.ld.sync.aligned.32x32b.x32.b32 " \
        "{%0, %1, %2, %3, %4, %5, %6, %7, " \
        " %8, %9, %10, %11, %12, %13, %14, %15, " \
        " %16, %17, %18, %19, %20, %21, %22, %23, " \
        " %24, %25, %26, %27, %28, %29, %30, %31}, [%32];" \
        : "=r"((r)[0]),  "=r"((r)[1]),  "=r"((r)[2]),  "=r"((r)[3]), \
          "=r"((r)[4]),  "=r"((r)[5]),  "=r"((r)[6]),  "=r"((r)[7]), \
          "=r"((r)[8]),  "=r"((r)[9]),  "=r"((r)[10]), "=r"((r)[11]), \
          "=r"((r)[12]), "=r"((r)[13]), "=r"((r)[14]), "=r"((r)[15]), \
          "=r"((r)[16]), "=r"((r)[17]), "=r"((r)[18]), "=r"((r)[19]), \
          "=r"((r)[20]), "=r"((r)[21]), "=r"((r)[22]), "=r"((r)[23]), \
          "=r"((r)[24]), "=r"((r)[25]), "=r"((r)[26]), "=r"((r)[27]), \
          "=r"((r)[28]), "=r"((r)[29]), "=r"((r)[30]), "=r"((r)[31]) \
        : "r"(addr))

// SW128 K-major descriptor (LBO=1, SBO=64, version=1, layout=SW128)
__device__ __forceinline__ u64 mk_desc(unsigned addr){
    const u64 base = (2ull << 61) | (1ull << 46) | (64ull << 32) | (1ull << 16);
    return base | ((u64)(addr >> 4) & 0x3FFFull);
}
__device__ __forceinline__ void mma_ss(unsigned d, u64 a, u64 b, u32 idesc, u32 en){
    asm volatile(
        "{\n\t.reg .pred p;\n\t"
        "setp.ne.u32 p, %4, 0;\n\t"
        "tcgen05.mma.cta_group::1.kind::f16 [%0], %1, %2, %3, {%5, %5, %5, %5}, p;\n\t}"
        :: "r"(d), "l"(a), "l"(b), "r"(idesc), "r"(en), "r"(0u) : "memory");
}
#else
__device__ __forceinline__ void ldmx4(u32& r0, u32& r1, u32& r2, u32& r3, unsigned a){
    asm volatile("ldmatrix.sync.aligned.m8n8.x4.shared.b16 {%0,%1,%2,%3}, [%4];"
                 : "=r"(r0), "=r"(r1), "=r"(r2), "=r"(r3) : "r"(a));
}
__device__ __forceinline__ void mma16816(float* c, const u32* a, u32 b0, u32 b1){
    asm volatile(
        "mma.sync.aligned.m16n8k16.row.col.f32.bf16.bf16.f32 "
        "{%0,%1,%2,%3}, {%4,%5,%6,%7}, {%8,%9}, {%0,%1,%2,%3};"
        : "+f"(c[0]), "+f"(c[1]), "+f"(c[2]), "+f"(c[3])
        : "r"(a[0]), "r"(a[1]), "r"(a[2]), "r"(a[3]), "r"(b0), "r"(b1));
}
#endif

// ---------------------------------------------------------------------------
// Generic GEMM:  D[128 x BN] = A[128,K] . B[BN,K]^T   (BN = 128 or 256)
// DT: 1=bf16, 0=fp16 operands.  APASS: 2 = A hi/lo (3-pass), 1 = A single.
// Epilogue modes:
//   0: fp32 row-major + bias          1: bf16 hi/lo head-split + bias (staged)
//   2: fp16 hi/lo V-transpose [bsh][d][l] + bias
// ---------------------------------------------------------------------------
template<int BN, int DT, int APASS>
__global__ void __launch_bounds__(256) gemm_any(
    const u16* __restrict__ Ahi, const u16* __restrict__ Alo, size_t aZ,
    const u16* __restrict__ Bhi, const u16* __restrict__ Blo, size_t bZ,
    int K, int mode,
    float* __restrict__ outF, u16* __restrict__ oHi, u16* __restrict__ oLo,
    const float* __restrict__ aux)
{
    extern __shared__ char smem[];
    const int tid  = threadIdx.x;
    const int w    = tid >> 5;
    const int lane = tid & 31;
    const int m0   = blockIdx.y * 128;
    const int n0   = blockIdx.x * BN;
    const int z    = blockIdx.z;

    const u16* Ah = Ahi + (size_t)z * aZ;
    const u16* Al = (APASS == 2) ? (Alo + (size_t)z * aZ) : Ahi;
    const u16* Bh = Bhi + (size_t)z * bZ;
    const u16* Bl = Blo + (size_t)z * bZ;

#if HAS_TCGEN05
    constexpr int ABYT  = 128 * 128;
    constexpr int BBYT  = BN * 128;
    constexpr int BOFF  = APASS * ABYT;
    constexpr int STAGE = APASS * ABYT + 2 * BBYT;
    constexpr u32 IDESC =
        (1u << 4) | ((u32)DT << 7) | ((u32)DT << 10)
        | ((u32)(BN / 8) << 17) | (8u << 24);
    constexpr int TCOLS = BN;

    const unsigned sb   = smem_u32p(smem);
    const unsigned mb0  = sb + 8;
    const unsigned mb1  = sb + 16;
    const unsigned buf0 = sb + 1024;

    if (w == 0){ TC_ALLOC(sb, TCOLS); }
    if (tid == 0){ MBAR_INIT(mb0, 1); MBAR_INIT(mb1, 1); }
    __syncthreads();
    unsigned tmem;
    asm volatile("ld.shared.b32 %0, [%1];" : "=r"(tmem) : "r"(sb));

    const int NS = K >> 6;

    auto load_stage = [&](int s){
        const unsigned bb = buf0 + (unsigned)(s & 1) * STAGE;
        const int k0 = s << 6;
#pragma unroll
        for (int it = 0; it < 4; it++){
            int idx = tid + it * 256;
            int r = idx >> 3, c = idx & 7;
            int off = r * 128 + c * 16;
            unsigned sw = (unsigned)(off ^ ((off >> 3) & 0x70));
            size_t g = (size_t)(m0 + r) * K + k0 + c * 8;
            cpa16(bb + sw, Ah + g);
            if (APASS == 2) cpa16(bb + ABYT + sw, Al + g);
        }
#pragma unroll
        for (int it = 0; it < (BN * 8) / 256; it++){
            int idx = tid + it * 256;
            int r = idx >> 3, c = idx & 7;
            int off = r * 128 + c * 16;
            unsigned sw = (unsigned)(off ^ ((off >> 3) & 0x70));
            size_t g = (size_t)(n0 + r) * K + k0 + c * 8;
            cpa16(bb + BOFF + sw,        Bh + g);
            cpa16(bb + BOFF + BBYT + sw, Bl + g);
        }
        CPA_COMMIT();
    };

    load_stage(0);
    if (NS > 1) load_stage(1);
    unsigned ph0 = 0, ph1 = 0;

    for (int s = 0; s < NS; s++){
        if (s == NS - 1) cpa_wait<0>(); else cpa_wait<1>();
        __syncthreads();

        if (w == 0 && elect1()){
            FENCE_ASYNC();
            const unsigned bb = buf0 + (unsigned)(s & 1) * STAGE;
            u64 ah = mk_desc(bb);
            u64 al = mk_desc(bb + ABYT);
            u64 bh = mk_desc(bb + BOFF);
            u64 bl = mk_desc(bb + BOFF + BBYT);
#pragma unroll
            for (int ks = 0; ks < 4; ks++)
                mma_ss(tmem, ah + 2 * ks, bh + 2 * ks, IDESC,
                       (s > 0 || ks > 0) ? 1u : 0u);
#pragma unroll
            for (int ks = 0; ks < 4; ks++)
                mma_ss(tmem, ah + 2 * ks, bl + 2 * ks, IDESC, 1u);
            if (APASS == 2){
#pragma unroll
                for (int ks = 0; ks < 4; ks++)
                    mma_ss(tmem, al + 2 * ks, bh + 2 * ks, IDESC, 1u);
            }
            TC_COMMIT((s & 1) ? mb1 : mb0);
        }

        if (s + 2 < NS){
            if (s & 1){ mbar_wait(mb1, ph1); ph1 ^= 1; }
            else      { mbar_wait(mb0, ph0); ph0 ^= 1; }
            load_stage(s + 2);
        }
    }
    if ((NS - 1) & 1) mbar_wait(mb1, ph1);
    else              mbar_wait(mb0, ph0);
    TC_FENCE_AFTER();

    // ---- epilogue: warp covers rows sub*32..+32, cols (w>>2)*(BN/2) in 64-chunks
    const int sub = w & 3;
    const int row0 = m0 + sub * 32;
    const int row  = row0 + lane;
    u32* sbuf = (u32*)(smem + 1024) + (size_t)w * (32 * 33);

#pragma unroll
    for (int cc = 0; cc < BN / 128; cc++){
        const int cb = (w >> 2) * (BN / 2) + cc * 64;
        u32 dr[64];
        TC_LD32(dr,      tmem + cb);
        TC_LD32(dr + 32, tmem + cb + 32);
        TC_WAITLD();
        TC_FENCE_BEFORE();

        if (mode == 0){
            float* dst = outF + (size_t)row * 1024 + n0 + cb;
            const float* bias = aux + n0 + cb;
#pragma unroll
            for (int j = 0; j < 16; j++){
                float4 o;
                o.x = __uint_as_float(dr[j*4+0]) + bias[j*4+0];
                o.y = __uint_as_float(dr[j*4+1]) + bias[j*4+1];
                o.z = __uint_as_float(dr[j*4+2]) + bias[j*4+2];
                o.w = __uint_as_float(dr[j*4+3]) + bias[j*4+3];
                *(float4*)(dst + j*4) = o;
            }
        } else if (mode == 1){
            const float* bias = aux + n0 + cb;
            const int h = (n0 + cb) >> 6;
            u32 hiw[32], low[32];
#pragma unroll
            for (int j = 0; j < 32; j++){
                float va = __uint_as_float(dr[2*j])   + bias[2*j];
                float vb = __uint_as_float(dr[2*j+1]) + bias[2*j+1];
                hiw[j] = pack2(va, vb);
                low[j] = pack2(va - b2f(f2b(va)), vb - b2f(f2b(vb)));
            }
#pragma unroll
            for (int j = 0; j < 32; j++) sbuf[lane * 33 + j] = hiw[j];
            __syncwarp();
#pragma unroll
            for (int i = 0; i < 32; i++){
                int r = row0 + i, bs = r >> 10, l = r & 1023;
                size_t wb = (((size_t)(bs * 16 + h)) << 15) + ((size_t)l << 5);
                ((u32*)oHi)[wb + lane] = sbuf[i * 33 + lane];
            }
            __syncwarp();
#pragma unroll
            for (int j = 0; j < 32; j++) sbuf[lane * 33 + j] = low[j];
            __syncwarp();
#pragma unroll
            for (int i = 0; i < 32; i++){
                int r = row0 + i, bs = r >> 10, l = r & 1023;
                size_t wb = (((size_t)(bs * 16 + h)) << 15) + ((size_t)l << 5);
                ((u32*)oLo)[wb + lane] = sbuf[i * 33 + lane];
            }
        } else { // mode 2
            const int bs = row >> 10, l = row & 1023;
            const int h  = (n0 + cb) >> 6;
            const size_t base = ((size_t)(bs * 16 + h) * 64) * 1024 + l;
            const float* bias = aux + n0 + cb;
#pragma unroll
            for (int j = 0; j < 64; j++){
                float va = __uint_as_float(dr[j]) + bias[j];
                u16 hh = f2h(va);
                oHi[base + (size_t)j * 1024] = hh;
                oLo[base + (size_t)j * 1024] = f2h(va - h2f(hh));
            }
        }
        __syncwarp();
    }
    __syncthreads();
    if (tid == 0){ MBAR_INVAL(mb0); MBAR_INVAL(mb1); }
    __syncthreads();
    if (w == 0) TC_DEALLOC(tmem, TCOLS);

#else
    // ---------- mma.sync fallback (compile-only; driver picks sm_103a) -----
    constexpr int WGM = 2, WGN = 4, PITCH = 40;
    constexpr int ASZ = 128 * PITCH;
    constexpr int BSZ = BN * PITCH;
    constexpr int STAGE = 2 * ASZ + 2 * BSZ;
    constexpr int WTM = 128 / WGM;
    constexpr int WTN = BN / WGN;
    constexpr int MT = WTM / 16;
    constexpr int NT16 = WTN / 16;

    const unsigned sbase = smem_u32p(smem);
    const int wm = (w / WGN) * WTM;
    const int wn = (w % WGN) * WTN;
    const int lrow = (lane & 7) + ((lane >> 3) & 1) * 8;
    const int lcol = (lane >> 4) * 8;

    float acc[MT][NT16 * 2][4];
#pragma unroll
    for (int i = 0; i < MT; i++)
#pragma unroll
        for (int j = 0; j < NT16 * 2; j++)
#pragma unroll
            for (int t = 0; t < 4; t++) acc[i][j][t] = 0.f;

    auto load_stage = [&](int s){
        const int k0 = s << 5;
        const unsigned sd = sbase + (unsigned)((s & 1) * STAGE) * 2u;
#pragma unroll
        for (int it = 0; it < 2; it++){
            int idx = tid + it * 256;
            int r = idx >> 2, c = idx & 3;
            size_t g = (size_t)(m0 + r) * K + k0 + c * 8;
            unsigned d = sd + (unsigned)(r * PITCH + c * 8) * 2u;
            cpa16(d, Ah + g);
            cpa16(d + ASZ * 2, Al + g);
        }
#pragma unroll
        for (int it = 0; it < (BN * 4) / 256; it++){
            int idx = tid + it * 256;
            int r = idx >> 2, c = idx & 3;
            size_t g = (size_t)(n0 + r) * K + k0 + c * 8;
            unsigned d = sd + (unsigned)(2 * ASZ + r * PITCH + c * 8) * 2u;
            cpa16(d, Bh + g);
            cpa16(d + BSZ * 2, Bl + g);
        }
        CPA_COMMIT();
    };

    const int NS = K >> 5;
    load_stage(0);

    for (int s = 0; s < NS; s++){
        if (s + 1 < NS){ load_stage(s + 1); cpa_wait<1>(); }
        else           { cpa_wait<0>(); }
        __syncthreads();

        const unsigned sd = sbase + (unsigned)((s & 1) * STAGE) * 2u;
#pragma unroll
        for (int k16 = 0; k16 < 2; k16++){
            const int kc = k16 * 16 + lcol;
            u32 ah[MT][4], al[MT][4], bh[NT16][4], bl[NT16][4];
#pragma unroll
            for (int mt = 0; mt < MT; mt++){
                unsigned a = sd + (unsigned)((wm + mt * 16 + lrow) * PITCH + kc) * 2u;
                ldmx4(ah[mt][0], ah[mt][1], ah[mt][2], ah[mt][3], a);
                ldmx4(al[mt][0], al[mt][1], al[mt][2], al[mt][3], a + ASZ * 2);
            }
#pragma unroll
            for (int nt = 0; nt < NT16; nt++){
                unsigned a = sd + (unsigned)(2 * ASZ + (wn + nt * 16 + lrow) * PITCH + kc) * 2u;
                ldmx4(bh[nt][0], bh[nt][1], bh[nt][2], bh[nt][3], a);
                ldmx4(bl[nt][0], bl[nt][1], bl[nt][2], bl[nt][3], a + BSZ * 2);
            }
#pragma unroll
            for (int mt = 0; mt < MT; mt++)
#pragma unroll
                for (int nt = 0; nt < NT16; nt++){
                    mma16816(acc[mt][2*nt],   ah[mt], bh[nt][0], bh[nt][2]);
                    mma16816(acc[mt][2*nt+1], ah[mt], bh[nt][1], bh[nt][3]);
                    mma16816(acc[mt][2*nt],   ah[mt], bl[nt][0], bl[nt][2]);
                    mma16816(acc[mt][2*nt+1], ah[mt], bl[nt][1], bl[nt][3]);
                    if (APASS == 2){
                        mma16816(acc[mt][2*nt],   al[mt], bh[nt][0], bh[nt][2]);
                        mma16816(acc[mt][2*nt+1], al[mt], bh[nt][1], bh[nt][3]);
                    }
                }
        }
        __syncthreads();
    }

    auto store_pair = [&](int row, int col, float va, float vb){
        if (mode == 0){
            float2 o; o.x = va + aux[col]; o.y = vb + aux[col + 1];
            *(float2*)(outF + (size_t)row * 1024 + col) = o;
        } else if (mode == 1){
            va += aux[col]; vb += aux[col + 1];
            int bs = row >> 10, l = row & 1023, h = col >> 6, d = col & 63;
            size_t idx = (((size_t)(bs * 16 + h)) << 16) + ((size_t)l << 6) + d;
            *(u32*)(oHi + idx) = pack2(va, vb);
            *(u32*)(oLo + idx) = pack2(va - b2f(f2b(va)), vb - b2f(f2b(vb)));
        } else if (mode == 2){
            va += aux[col]; vb += aux[col + 1];
            int bs = row >> 10, l = row & 1023, h = col >> 6, d = col & 63;
            size_t base = ((size_t)(bs * 16 + h) * 64 + d) * 1024 + l;
            u16 h0 = f2h(va), h1 = f2h(vb);
            oHi[base] = h0;        oHi[base + 1024] = h1;
            oLo[base] = f2h(va - h2f(h0));
            oLo[base + 1024] = f2h(vb - h2f(h1));
        }
    };

#pragma unroll
    for (int mt = 0; mt < MT; mt++)
#pragma unroll
        for (int nt8 = 0; nt8 < NT16 * 2; nt8++){
            int r0 = m0 + wm + mt * 16 + (lane >> 2);
            int c0 = n0 + wn + nt8 * 8 + (lane & 3) * 2;
            store_pair(r0,     c0, acc[mt][nt8][0], acc[mt][nt8][1]);
            store_pair(r0 + 8, c0, acc[mt][nt8][2], acc[mt][nt8][3]);
        }
#endif
}

// ---------------------------------------------------------------------------
// Fused QK kernel, software-pipelined: per CTA (q-tile 128, z), 8 k-tiles.
// 4 K smem buffers, D double-buffered in TMEM (cols 0-127 / 128-255) so the
// epilogue of tile kt-1 overlaps the MMA of tile kt.
// Writes fp16 probs (exp, mask bits) and full row sums to g_rsum.
// ---------------------------------------------------------------------------
__global__ void __launch_bounds__(256) qk_tc(
    const u16* __restrict__ qhH, const u16* __restrict__ qhL,
    const u16* __restrict__ khH, const u16* __restrict__ khL)
{
    extern __shared__ char smem[];
    const int tid  = threadIdx.x;
    const int w    = tid >> 5;
    const int lane = tid & 31;
    const int m0   = blockIdx.x * 128;
    const int z    = blockIdx.y;
    const int bs   = z >> 4;

    const u16* Qh = qhH + (size_t)z * 65536;
    const u16* Ql = qhL + (size_t)z * 65536;
    const u16* Kh = khH + (size_t)z * 65536;
    const u16* Kl = khL + (size_t)z * 65536;

#if HAS_TCGEN05
    constexpr u32 IDESC =
        (1u << 4) | (1u << 7) | (1u << 10) | (16u << 17) | (8u << 24);
    constexpr unsigned SB_OFF = 1024 + 32768 + 4 * 32768;   // 164864

    const unsigned sb   = smem_u32p(smem);
    const unsigned mb0  = sb + 8;
    const unsigned mb1  = sb + 16;
    const unsigned qbuf = sb + 1024;          // Qhi 16K + Qlo 16K
    const unsigned kbuf = qbuf + 32768;       // 4 x (Khi 16K + Klo 16K)

    if (w == 0){ TC_ALLOC(sb, 256); }
    if (tid == 0){ MBAR_INIT(mb0, 1); MBAR_INIT(mb1, 1); }
    __syncthreads();
    unsigned tmem;
    asm volatile("ld.shared.b32 %0, [%1];" : "=r"(tmem) : "r"(sb));

    auto loadK = [&](int kt){
        const unsigned bb = kbuf + (unsigned)(kt & 3) * 32768;
#pragma unroll
        for (int it = 0; it < 4; it++){
            int idx = tid + it * 256;
            int r = idx >> 3, c = idx & 7;
            int off = r * 128 + c * 16;
            unsigned sw = (unsigned)(off ^ ((off >> 3) & 0x70));
            size_t g = (size_t)(kt * 128 + r) * 64 + c * 8;
            cpa16(bb + sw,         Kh + g);
            cpa16(bb + 16384 + sw, Kl + g);
        }
        CPA_COMMIT();
    };

    // group 0: Q + K0; groups 1,2: K1, K2
    {
#pragma unroll
        for (int it = 0; it < 4; it++){
            int idx = tid + it * 256;
            int r = idx >> 3, c = idx & 7;
            int off = r * 128 + c * 16;
            unsigned sw = (unsigned)(off ^ ((off >> 3) & 0x70));
            size_t g = (size_t)(m0 + r) * 64 + c * 8;
            cpa16(qbuf + sw,         Qh + g);
            cpa16(qbuf + 16384 + sw, Ql + g);
        }
#pragma unroll
        for (int it = 0; it < 4; it++){
            int idx = tid + it * 256;
            int r = idx >> 3, c = idx & 7;
            int off = r * 128 + c * 16;
            unsigned sw = (unsigned)(off ^ ((off >> 3) & 0x70));
            size_t g = (size_t)r * 64 + c * 8;
            cpa16(kbuf + sw,         Kh + g);
            cpa16(kbuf + 16384 + sw, Kl + g);
        }
        CPA_COMMIT();
        loadK(1);
        loadK(2);
    }

    const int sub = w & 3;
    const int cb  = (w >> 2) * 64;
    const int row0 = m0 + sub * 32;
    const int row  = row0 + lane;
    u32* sbuf = (u32*)(smem + SB_OFF) + (size_t)w * (32 * 33);
    float rs = 0.f;
    unsigned ph0 = 0, ph1 = 0;

    auto epilogue = [&](int j){
        u32 dr[64];
        const unsigned dt = tmem + (unsigned)(j & 1) * 128 + cb;
        TC_LD32(dr,      dt);
        TC_LD32(dr + 32, dt + 32);
        TC_WAITLD();
        TC_FENCE_BEFORE();

        const int c0 = j * 128 + cb;
        const size_t widx = ((size_t)bs << 15) + ((size_t)row << 5) + (c0 >> 5);
        const u32 w0 = g_mbits[widx];
        const u32 w1 = g_mbits[widx + 1];

        float part = 0.f;
        u32 pw[32];
#pragma unroll
        for (int jj = 0; jj < 32; jj++){
            int c = 2 * jj;
            u32 wa  = (c < 32) ? w0 : w1;
            u32 wbq = (c + 1 < 32) ? w0 : w1;
            float ea = ((wa >> (c & 31)) & 1) ? 0.f
                     : __expf(__uint_as_float(dr[2*jj]) * 0.125f);
            float eb = ((wbq >> ((c + 1) & 31)) & 1) ? 0.f
                     : __expf(__uint_as_float(dr[2*jj+1]) * 0.125f);
            part += ea + eb;
            pw[jj] = pack2h(ea, eb);
        }
        rs += part;
#pragma unroll
        for (int jj = 0; jj < 32; jj++) sbuf[lane * 33 + jj] = pw[jj];
        __syncwarp();
#pragma unroll
        for (int i = 0; i < 32; i++){
            size_t wb = ((size_t)z << 19) + ((size_t)(row0 + i) << 9)
                      + (size_t)(c0 >> 1);
            ((u32*)g_p)[wb + lane] = sbuf[i * 33 + lane];
        }
        __syncwarp();
    };

    for (int kt = 0; kt < 8; kt++){
        if (kt <= 5) cpa_wait<2>();
        else if (kt == 6) cpa_wait<1>();
        else cpa_wait<0>();
        __syncthreads();                 // buf kt visible; epilogue kt-2 done

        if (w == 0 && elect1()){
            FENCE_ASYNC();
            u64 qd  = mk_desc(qbuf);
            u64 qld = mk_desc(qbuf + 16384);
            const unsigned bb = kbuf + (unsigned)(kt & 3) * 32768;
            u64 kd  = mk_desc(bb);
            u64 kld = mk_desc(bb + 16384);
            const unsigned dst = tmem + (unsigned)(kt & 1) * 128;
#pragma unroll
            for (int ks = 0; ks < 4; ks++)
                mma_ss(dst, qd + 2 * ks, kd + 2 * ks, IDESC, ks > 0 ? 1u : 0u);
#pragma unroll
            for (int ks = 0; ks < 4; ks++)
                mma_ss(dst, qd + 2 * ks, kld + 2 * ks, IDESC, 1u);
#pragma unroll
            for (int ks = 0; ks < 4; ks++)
                mma_ss(dst, qld + 2 * ks, kd + 2 * ks, IDESC, 1u);
            TC_COMMIT((kt & 1) ? mb1 : mb0);
        }

        if (kt > 0){                     // overlap: epilogue kt-1 vs MMA kt
            if ((kt - 1) & 1){ mbar_wait(mb1, ph1); ph1 ^= 1; }
            else             { mbar_wait(mb0, ph0); ph0 ^= 1; }
            TC_FENCE_AFTER();
            epilogue(kt - 1);
            if (kt + 3 < 8) loadK(kt + 3);   // buf (kt-1)&3, freed by the wait
        } else {
            loadK(3);                        // buf 3 is fresh
        }
    }
    mbar_wait(mb1, ph1);                 // kt=7
    TC_FENCE_AFTER();
    epilogue(7);

    // combine the two column-half partial sums and write g_rsum
    __syncthreads();
    float* fs = (float*)(smem + SB_OFF);
    fs[(w >> 2) * 128 + sub * 32 + lane] = rs;
    __syncthreads();
    if (w < 4){
        int rl = w * 32 + lane;
        g_rsum[(size_t)z * 1024 + m0 + rl] = fs[rl] + fs[128 + rl];
    }
    __syncthreads();
    if (tid == 0){ MBAR_INVAL(mb0); MBAR_INVAL(mb1); }
    __syncthreads();
    if (w == 0) TC_DEALLOC(tmem, 256);

#else
    for (int idx = tid; idx < 128 * 1024; idx += 256){
        int r = m0 + (idx >> 10);
        int c = idx & 1023;
        u32 wm_ = g_mbits[((size_t)bs << 15) + ((size_t)r << 5) + (c >> 5)];
        float p = 0.f;
        if (!((wm_ >> (c & 31)) & 1)){
            float s = 0.f;
            for (int d = 0; d < 64; d++){
                float qv = b2f(Qh[(size_t)r * 64 + d]) + b2f(Ql[(size_t)r * 64 + d]);
                float kv = b2f(Kh[(size_t)c * 64 + d]) + b2f(Kl[(size_t)c * 64 + d]);
                s += qv * kv;
            }
            p = __expf(s * 0.125f);
        }
        g_p[((size_t)z << 20) + ((size_t)r << 10) + c] = f2h(p);
        atomicAdd(&g_rsum[(size_t)z * 1024 + r], p);
    }
#endif
}

// ---------------------------------------------------------------------------
// Fused PV + head-mean (unchanged from R12): grid (8 q-tiles, 16 bs, 2 halves).
// ---------------------------------------------------------------------------
__global__ void __launch_bounds__(256) pv_tc(
    float* __restrict__ attn0, float* __restrict__ attn1)
{
    extern __shared__ char smem[];
    const int tid  = threadIdx.x;
    const int w    = tid >> 5;
    const int lane = tid & 31;
    const int m0   = blockIdx.x * 128;
    const int bs   = blockIdx.y;
    const int half = blockIdx.z;
    const int zb   = bs * 16 + half * 8;

#if HAS_TCGEN05
    constexpr u32 IDESC = (1u << 4) | (8u << 17) | (8u << 24);

    const unsigned sb   = smem_u32p(smem);
    const unsigned mb0  = sb + 8;
    const unsigned mb1  = sb + 16;
    const unsigned buf0 = sb + 1024;

    if (w == 0){ TC_ALLOC(sb, 512); }
    if (tid == 0){ MBAR_INIT(mb0, 1); MBAR_INIT(mb1, 1); }
    __syncthreads();
    unsigned tmem;
    asm volatile("ld.shared.b32 %0, [%1];" : "=r"(tmem) : "r"(sb));

    auto load_stage = [&](int s){
        const int h = s & 7, kc = s >> 3;
        const int z = zb + h;
        const unsigned bb = buf0 + (unsigned)(s & 1) * 32768;
#pragma unroll
        for (int it = 0; it < 4; it++){
            int idx = tid + it * 256;
            int r = idx >> 3, c = idx & 7;
            int off = r * 128 + c * 16;
            unsigned sw = (unsigned)(off ^ ((off >> 3) & 0x70));
            const u16* src = g_p + ((size_t)z << 20)
                           + (size_t)(m0 + r) * 1024 + kc * 64 + c * 8;
            cpa16(bb + sw, src);
        }
#pragma unroll
        for (int it = 0; it < 2; it++){
            int idx = tid + it * 256;
            int r = idx >> 3, c = idx & 7;
            int off = r * 128 + c * 16;
            unsigned sw = (unsigned)(off ^ ((off >> 3) & 0x70));
            size_t g = (size_t)z * 65536 + (size_t)r * 1024 + kc * 64 + c * 8;
            cpa16(bb + 16384 + sw, g_vt_hi + g);
            cpa16(bb + 24576 + sw, g_vt_lo + g);
        }
        CPA_COMMIT();
    };

    const int ar = tid >> 1;
    const int ac = (tid & 1) * 32;
    float rv8[8];
#pragma unroll
    for (int h = 0; h < 8; h++)
        rv8[h] = g_rinv[(size_t)(zb + h) * 1024 + m0 + ar];
    float aacc[32];
#pragma unroll
    for (int j = 0; j < 32; j++) aacc[j] = 0.f;

    load_stage(0);
    load_stage(1);
    unsigned ph0 = 0, ph1 = 0;

    for (int s = 0; s < 128; s++){
        if (s == 127) cpa_wait<0>(); else cpa_wait<1>();
        __syncthreads();

        const int h = s & 7, kc = s >> 3;
        const unsigned bb = buf0 + (unsigned)(s & 1) * 32768;

        if (w == 0 && elect1()){
            FENCE_ASYNC();
            u64 pd = mk_desc(bb);
            u64 vh = mk_desc(bb + 16384);
            u64 vl = mk_desc(bb + 24576);
            const unsigned dst = tmem + (unsigned)h * 64;
#pragma unroll
            for (int ks = 0; ks < 4; ks++)
                mma_ss(dst, pd + 2 * ks, vh + 2 * ks, IDESC,
                       (kc > 0 || ks > 0) ? 1u : 0u);
#pragma unroll
            for (int ks = 0; ks < 4; ks++)
                mma_ss(dst, pd + 2 * ks, vl + 2 * ks, IDESC, 1u);
            TC_COMMIT((s & 1) ? mb1 : mb0);
        }

        {
            const float rv = rv8[h];
#pragma unroll
            for (int g = 0; g < 4; g++){
                int off = ar * 128 + (ac + g * 8) * 2;
                unsigned sw = (unsigned)(off ^ ((off >> 3) & 0x70));
                u32 x0, x1, x2, x3;
                asm volatile("ld.shared.v4.u32 {%0,%1,%2,%3}, [%4];"
                             : "=r"(x0), "=r"(x1), "=r"(x2), "=r"(x3)
                             : "r"(bb + sw));
                aacc[g*8+0] += h2f((u16)x0) * rv;
                aacc[g*8+1] += h2f((u16)(x0 >> 16)) * rv;
                aacc[g*8+2] += h2f((u16)x1) * rv;
                aacc[g*8+3] += h2f((u16)(x1 >> 16)) * rv;
                aacc[g*8+4] += h2f((u16)x2) * rv;
                aacc[g*8+5] += h2f((u16)(x2 >> 16)) * rv;
                aacc[g*8+6] += h2f((u16)x3) * rv;
                aacc[g*8+7] += h2f((u16)(x3 >> 16)) * rv;
            }
        }
        if (h == 7){
            float* dst = (half ? attn1 : attn0)
                       + ((size_t)bs << 20) + ((size_t)(m0 + ar) << 10)
                       + kc * 64 + ac;
#pragma unroll
            for (int j4 = 0; j4 < 8; j4++){
                float4 o;
                o.x = aacc[j4*4+0] * 0.0625f;
                o.y = aacc[j4*4+1] * 0.0625f;
                o.z = aacc[j4*4+2] * 0.0625f;
                o.w = aacc[j4*4+3] * 0.0625f;
                *(float4*)(dst + j4 * 4) = o;
            }
#pragma unroll
            for (int j = 0; j < 32; j++) aacc[j] = 0.f;
        }
        __syncthreads();

        if (s + 2 < 128){
            if (s & 1){ mbar_wait(mb1, ph1); ph1 ^= 1; }
            else      { mbar_wait(mb0, ph0); ph0 ^= 1; }
            load_stage(s + 2);
        }
    }
    mbar_wait(mb0, ph0);
    mbar_wait(mb1, ph1);
    TC_FENCE_AFTER();

    const int sub = w & 3;
    const int row0 = m0 + sub * 32;
    const int row  = row0 + lane;
    u32* sbuf = (u32*)(smem + 1024) + (size_t)w * (32 * 33);

#pragma unroll
    for (int it = 0; it < 4; it++){
        const int h = (w >> 2) * 4 + it;
        u32 dr[64];
        TC_LD32(dr,      tmem + h * 64);
        TC_LD32(dr + 32, tmem + h * 64 + 32);
        TC_WAITLD();
        TC_FENCE_BEFORE();
        const float inv = g_rinv[(size_t)(zb + h) * 1024 + row];
        const int hg = half * 8 + h;
        u32 hiw[32], low[32];
#pragma unroll
        for (int j = 0; j < 32; j++){
            float va = __uint_as_float(dr[2*j])   * inv;
            float vb = __uint_as_float(dr[2*j+1]) * inv;
            hiw[j] = pack2(va, vb);
            low[j] = pack2(va - b2f(f2b(va)), vb - b2f(f2b(vb)));
        }
#pragma unroll
        for (int j = 0; j < 32; j++) sbuf[lane * 33 + j] = hiw[j];
        __syncwarp();
#pragma unroll
        for (int i = 0; i < 32; i++){
            size_t wb = (((size_t)(bs * 1024 + row0 + i)) << 9) + (size_t)hg * 32;
            ((u32*)g_ctx_hi)[wb + lane] = sbuf[i * 33 + lane];
        }
        __syncwarp();
#pragma unroll
        for (int j = 0; j < 32; j++) sbuf[lane * 33 + j] = low[j];
        __syncwarp();
#pragma unroll
        for (int i = 0; i < 32; i++){
            size_t wb = (((size_t)(bs * 1024 + row0 + i)) << 9) + (size_t)hg * 32;
            ((u32*)g_ctx_lo)[wb + lane] = sbuf[i * 33 + lane];
        }
        __syncwarp();
    }
    __syncthreads();
    if (tid == 0){ MBAR_INVAL(mb0); MBAR_INVAL(mb1); }
    __syncthreads();
    if (w == 0) TC_DEALLOC(tmem, 512);

#else
    for (int h = 0; h < 8; h++){
        const int z = zb + h;
        for (int idx = tid; idx < 128 * 64; idx += 256){
            int r = idx >> 6, d = idx & 63;
            float acc = 0.f;
            for (int k = 0; k < 1024; k++)
                acc += h2f(g_p[((size_t)z << 20) + (size_t)(m0 + r) * 1024 + k]) *
                       (h2f(g_vt_hi[(size_t)z * 65536 + (size_t)d * 1024 + k]) +
                        h2f(g_vt_lo[(size_t)z * 65536 + (size_t)d * 1024 + k]));
            float inv = g_rinv[(size_t)z * 1024 + m0 + r];
            float va = acc * inv;
            size_t o = (((size_t)(bs * 1024 + m0 + r)) << 10) + (half * 8 + h) * 64 + d;
            u16 hh = f2b(va);
            g_ctx_hi[o] = hh;
            g_ctx_lo[o] = f2b(va - b2f(hh));
        }
    }
    for (int idx = tid; idx < 128 * 1024; idx += 256){
        int r = idx >> 10, k = idx & 1023;
        float s = 0.f;
        for (int h = 0; h < 8; h++){
            const int z = zb + h;
            s += h2f(g_p[((size_t)z << 20) + (size_t)(m0 + r) * 1024 + k]) *
                 g_rinv[(size_t)z * 1024 + m0 + r];
        }
        (half ? attn1 : attn0)[((size_t)bs << 20) + ((size_t)(m0 + r) << 10) + k]
            = s * 0.0625f;
    }
#endif
}

// ---------------------------------------------------------------------------
__global__ __launch_bounds__(256) void combine_attn(float* __restrict__ am)
{
    const int i = blockIdx.x * 256 + threadIdx.x;
    float4 a = ((float4*)am)[i];
    float4 b = ((const float4*)g_attn2)[i];
    a.x += b.x; a.y += b.y; a.z += b.z; a.w += b.w;
    ((float4*)am)[i] = a;
}

// ---------------------------------------------------------------------------
__global__ __launch_bounds__(256) void mask_bits_kernel(const float* __restrict__ mask)
{
    const int warpid = (blockIdx.x * 256 + threadIdx.x) >> 5;
    const int lane = threadIdx.x & 31;
    const size_t base = (size_t)warpid * 1024;
#pragma unroll
    for (int b = 0; b < 32; b++){
        float v = mask[base + b * 32 + lane];
        u32 bits = __ballot_sync(0xFFFFFFFFu, v > 0.5f);
        if (lane == b) g_mbits[base / 32 + b] = bits;
    }
}

__global__ __launch_bounds__(256) void zero_rsum()
{
    const int i = blockIdx.x * 256 + threadIdx.x;
    ((float4*)g_rsum)[i] = make_float4(0.f, 0.f, 0.f, 0.f);
}

__global__ __launch_bounds__(256) void invert_rsum()
{
    const int i = blockIdx.x * 256 + threadIdx.x;
    g_rinv[i] = __frcp_rn(g_rsum[i]);
}

// ---------------------------------------------------------------------------
__global__ __launch_bounds__(256) void conv_act(
    const float* __restrict__ in, u16* __restrict__ hi, u16* __restrict__ lo)
{
    const int i = blockIdx.x * 256 + threadIdx.x;
    float4 v = ((const float4*)in)[i];
    u32 h0 = pack2(v.x, v.y), h1 = pack2(v.z, v.w);
    ((u32*)hi)[i * 2]     = h0;
    ((u32*)hi)[i * 2 + 1] = h1;
    ((u32*)lo)[i * 2]     = pack2(v.x - b2f((u16)h0), v.y - b2f((u16)(h0 >> 16)));
    ((u32*)lo)[i * 2 + 1] = pack2(v.z - b2f((u16)h1), v.w - b2f((u16)(h1 >> 16)));
}

// ---------------------------------------------------------------------------
__global__ __launch_bounds__(256) void conv_wT(
    const float* __restrict__ W, u16* __restrict__ hi, u16* __restrict__ lo)
{
    __shared__ float tile[32][33];
    const int tx = threadIdx.x, ty = threadIdx.y;
    const int kb = blockIdx.y * 32, nb = blockIdx.x * 32;
#pragma unroll
    for (int i = 0; i < 4; i++)
        tile[ty + i * 8][tx] = W[(size_t)(kb + ty + i * 8) * 1024 + nb + tx];
    __syncthreads();
#pragma unroll
    for (int i = 0; i < 4; i++){
        int n = nb + ty + i * 8, k = kb + tx;
        float v = tile[tx][ty + i * 8];
        u16 h = f2b(v);
        hi[(size_t)n * 1024 + k] = h;
        lo[(size_t)n * 1024 + k] = f2b(v - b2f(h));
    }
}

// ---------------------------------------------------------------------------
extern "C" void kernel_launch(void* const* d_in, const int* in_sizes, int n_in,
                              void* d_out, int out_size)
{
    const float* q    = (const float*)d_in[0];
    const float* k    = (const float*)d_in[1];
    const float* v    = (const float*)d_in[2];
    const float* mask = (const float*)d_in[3];
    const float* wq   = (const float*)d_in[4];
    const float* bq   = (const float*)d_in[5];
    const float* wk   = (const float*)d_in[6];
    const float* bk   = (const float*)d_in[7];
    const float* wv   = (const float*)d_in[8];
    const float* bv   = (const float*)d_in[9];
    const float* wo   = (const float*)d_in[10];
    const float* bo   = (const float*)d_in[11];

    float* out       = (float*)d_out;
    float* attn_mean = out + 16777216;

    u16 *wtH, *wtL, *aH, *aL, *qhH, *qhL, *khH, *khL, *vtH, *vtL, *cxH, *cxL;
    float* a2;
    cudaGetSymbolAddress((void**)&wtH, g_wt_hi);
    cudaGetSymbolAddress((void**)&wtL, g_wt_lo);
    cudaGetSymbolAddress((void**)&aH,  g_a_hi);
    cudaGetSymbolAddress((void**)&aL,  g_a_lo);
    cudaGetSymbolAddress((void**)&qhH, g_qh_hi);
    cudaGetSymbolAddress((void**)&qhL, g_qh_lo);
    cudaGetSymbolAddress((void**)&khH, g_kh_hi);
    cudaGetSymbolAddress((void**)&khL, g_kh_lo);
    cudaGetSymbolAddress((void**)&vtH, g_vt_hi);
    cudaGetSymbolAddress((void**)&vtL, g_vt_lo);
    cudaGetSymbolAddress((void**)&cxH, g_ctx_hi);
    cudaGetSymbolAddress((void**)&cxL, g_ctx_lo);
    cudaGetSymbolAddress((void**)&a2,  g_attn2);

    constexpr int SMEM_BIG = 1024 + 2 * (2 * 128 * 128 + 2 * 256 * 128); // 197632
    constexpr int SMEM_QK  = 1024 + 32768 + 4 * 32768 + 33792;           // 198656
    constexpr int SMEM_PV  = 1024 + 2 * 32768;                           //  66560
    cudaFuncSetAttribute(gemm_any<256,1,2>,
                         cudaFuncAttributeMaxDynamicSharedMemorySize, SMEM_BIG);
    cudaFuncSetAttribute(qk_tc,
                         cudaFuncAttributeMaxDynamicSharedMemorySize, SMEM_QK);
    cudaFuncSetAttribute(pv_tc,
                         cudaFuncAttributeMaxDynamicSharedMemorySize, SMEM_PV);

    dim3 wtg(32, 32);
    dim3 wtb(32, 8);
    conv_wT<<<wtg, wtb>>>(wq, wtH + 0u,       wtL + 0u);
    conv_wT<<<wtg, wtb>>>(wk, wtH + 1048576u, wtL + 1048576u);
    conv_wT<<<wtg, wtb>>>(wv, wtH + 2097152u, wtL + 2097152u);
    conv_wT<<<wtg, wtb>>>(wo, wtH + 3145728u, wtL + 3145728u);
    mask_bits_kernel<<<2048, 256>>>(mask);
    zero_rsum<<<256, 256>>>();

    dim3 projGrid(4, 128, 1);    // BN=256

    conv_act<<<16384, 256>>>(q, aH, aL);
    gemm_any<256,1,2><<<projGrid, 256, SMEM_BIG>>>(
        aH, aL, 0, wtH + 0u, wtL + 0u, 0, 1024, 1, nullptr, qhH, qhL, bq);
    conv_act<<<16384, 256>>>(k, aH, aL);
    gemm_any<256,1,2><<<projGrid, 256, SMEM_BIG>>>(
        aH, aL, 0, wtH + 1048576u, wtL + 1048576u, 0, 1024, 1, nullptr, khH, khL, bk);
    conv_act<<<16384, 256>>>(v, aH, aL);
    gemm_any<256,1,2><<<projGrid, 256, SMEM_BIG>>>(
        aH, aL, 0, wtH + 2097152u, wtL + 2097152u, 0, 1024, 2, nullptr, vtH, vtL, bv);

    // fused QK (pipelined): probs + row sums
    qk_tc<<<dim3(8, 256), 256, SMEM_QK>>>(qhH, qhL, khH, khL);
    invert_rsum<<<1024, 256>>>();

    // fused PV + head-mean partials
    pv_tc<<<dim3(8, 16, 2), 256, SMEM_PV>>>(attn_mean, a2);
    combine_attn<<<16384, 256>>>(attn_mean);

    // out projection (BN=256)
    gemm_any<256,1,2><<<projGrid, 256, SMEM_BIG>>>(
        cxH, cxL, 0, wtH + 3145728u, wtL + 3145728u, 0, 1024, 0, out, nullptr, nullptr, bo);
}

// round 14
// speedup vs baseline: 2.6909x; 1.0282x over previous
#include <cuda_runtime.h>
#include <cuda_bf16.h>
#include <cuda_fp16.h>

typedef unsigned short u16;
typedef unsigned int   u32;
typedef unsigned long long u64;

#if defined(__CUDA_ARCH_FEAT_SM103_ALL) || defined(__CUDA_ARCH_FEAT_SM100_ALL)
#define HAS_TCGEN05 1
#else
#define HAS_TCGEN05 0
#endif

// ---------------- device scratch (allocation-free rule) --------------------
__device__ u16 g_wt_hi[4u*1024u*1024u];   // 4 weights, transposed [n][k] bf16
__device__ u16 g_wt_lo[4u*1024u*1024u];
__device__ u16 g_a_hi[16777216];          // activation staging bf16 (reused)
__device__ u16 g_a_lo[16777216];
__device__ u16 g_qh_hi[16777216];         // [bsh][l][64] bf16
__device__ u16 g_qh_lo[16777216];
__device__ u16 g_kh_hi[16777216];
__device__ u16 g_kh_lo[16777216];
__device__ u16 g_vt_hi[16777216];         // [bsh][d=64][l=1024] fp16
__device__ u16 g_vt_lo[16777216];
__device__ u16 g_p[268435456];            // unnormalized exp probs fp16
__device__ u32 g_mbits[524288];           // mask bitmask: [bs][row][32 words]
__device__ float g_rsum[262144];          // [bsh][row] row sums
__device__ float g_rinv[262144];          // [bsh][row] 1/rowsum
__device__ u16 g_ctx_hi[16777216];        // merged [bs*L+q][1024] bf16
__device__ u16 g_ctx_lo[16777216];
__device__ float g_attn2[16777216];       // head-mean partial (heads 8-15)

// ---------------- helpers --------------------------------------------------
__device__ __forceinline__ u16 f2b(float x){
    return __bfloat16_as_ushort(__float2bfloat16_rn(x));
}
__device__ __forceinline__ float b2f(u16 u){
    return __bfloat162float(__ushort_as_bfloat16(u));
}
__device__ __forceinline__ u32 pack2(float a, float b){
    return (u32)f2b(a) | ((u32)f2b(b) << 16);
}
__device__ __forceinline__ u16 f2h(float x){
    return __half_as_ushort(__float2half_rn(x));
}
__device__ __forceinline__ float h2f(u16 u){
    return __half2float(__ushort_as_half(u));
}
__device__ __forceinline__ u32 pack2h(float a, float b){
    return (u32)f2h(a) | ((u32)f2h(b) << 16);
}
__device__ __forceinline__ unsigned smem_u32p(const void* p){
    unsigned a;
    asm("{ .reg .u64 t; cvta.to.shared.u64 t, %1; cvt.u32.u64 %0, t; }"
        : "=r"(a) : "l"(p));
    return a;
}
__device__ __forceinline__ void cpa16(unsigned dst, const void* src){
    asm volatile("cp.async.cg.shared.global [%0], [%1], 16;" :: "r"(dst), "l"(src));
}
#define CPA_COMMIT() asm volatile("cp.async.commit_group;" ::: "memory")
template<int N> __device__ __forceinline__ void cpa_wait(){
    asm volatile("cp.async.wait_group %0;" :: "n"(N) : "memory");
}

#if HAS_TCGEN05
__device__ __forceinline__ unsigned elect1(){
    unsigned p;
    asm volatile("{ .reg .pred P; elect.sync _|P, 0xFFFFFFFF; selp.b32 %0, 1, 0, P; }"
                 : "=r"(p));
    return p;
}
#define MBAR_INIT(a, c) \
    asm volatile("mbarrier.init.shared.b64 [%0], %1;" :: "r"(a), "r"(c) : "memory")
#define MBAR_INVAL(a) \
    asm volatile("mbarrier.inval.shared.b64 [%0];" :: "r"(a) : "memory")
__device__ __forceinline__ void mbar_wait(unsigned a, unsigned ph){
    asm volatile(
        "{\n\t.reg .pred P;\n"
        "W%=:\n\t"
        "mbarrier.try_wait.parity.acquire.cta.shared::cta.b64 P, [%0], %1, 0x989680;\n\t"
        "@P bra D%=;\n\t"
        "bra W%=;\n"
        "D%=:\n\t}"
        :: "r"(a), "r"(ph) : "memory");
}
#define TC_ALLOC(sa, n) \
    asm volatile("tcgen05.alloc.cta_group::1.sync.aligned.shared::cta.b32 [%0], %1;" \
                 :: "r"(sa), "r"(n) : "memory")
#define TC_DEALLOC(t, n) \
    asm volatile("tcgen05.dealloc.cta_group::1.sync.aligned.b32 %0, %1;" :: "r"(t), "r"(n))
#define TC_COMMIT(mb) \
    asm volatile("tcgen05.commit.cta_group::1.mbarrier::arrive::one.shared::cluster.b64 [%0];" \
                 :: "r"(mb) : "memory")
#define TC_FENCE_AFTER()  asm volatile("tcgen05.fence::after_thread_sync;" ::: "memory")
#define TC_FENCE_BEFORE() asm volatile("tcgen05.fence::before_thread_sync;" ::: "memory")
#define TC_WAITLD()       asm volatile("tcgen05.wait::ld.sync.aligned;" ::: "memory")
#define FENCE_ASYNC()     asm volatile("fence.proxy.async.shared::cta;" ::: "memory")

#define TC_LD32(r, addr) \
    asm volatile( \
        "tcgen05.ld.sync.aligned.32x32b.x32.b32 " \
        "{%0, %1, %2, %3, %4, %5, %6, %7, " \
        " %8, %9, %10, %11, %12, %13, %14, %15, " \
        " %16, %17, %18, %19, %20, %21, %22, %23, " \
        " %24, %25, %26, %27, %28, %29, %30, %31}, [%32];" \
        : "=r"((r)[0]),  "=r"((r)[1]),  "=r"((r)[2]),  "=r"((r)[3]), \
          "=r"((r)[4]),  "=r"((r)[5]),  "=r"((r)[6]),  "=r"((r)[7]), \
          "=r"((r)[8]),  "=r"((r)[9]),  "=r"((r)[10]), "=r"((r)[11]), \
          "=r"((r)[12]), "=r"((r)[13]), "=r"((r)[14]), "=r"((r)[15]), \
          "=r"((r)[16]), "=r"((r)[17]), "=r"((r)[18]), "=r"((r)[19]), \
          "=r"((r)[20]), "=r"((r)[21]), "=r"((r)[22]), "=r"((r)[23]), \
          "=r"((r)[24]), "=r"((r)[25]), "=r"((r)[26]), "=r"((r)[27]), \
          "=r"((r)[28]), "=r"((r)[29]), "=r"((r)[30]), "=r"((r)[31]) \
        : "r"(addr))

// SW128 K-major descriptor (LBO=1, SBO=64, version=1, layout=SW128)
__device__ __forceinline__ u64 mk_desc(unsigned addr){
    const u64 base = (2ull << 61) | (1ull << 46) | (64ull << 32) | (1ull << 16);
    return base | ((u64)(addr >> 4) & 0x3FFFull);
}
__device__ __forceinline__ void mma_ss(unsigned d, u64 a, u64 b, u32 idesc, u32 en){
    asm volatile(
        "{\n\t.reg .pred p;\n\t"
        "setp.ne.u32 p, %4, 0;\n\t"
        "tcgen05.mma.cta_group::1.kind::f16 [%0], %1, %2, %3, {%5, %5, %5, %5}, p;\n\t}"
        :: "r"(d), "l"(a), "l"(b), "r"(idesc), "r"(en), "r"(0u) : "memory");
}
#else
__device__ __forceinline__ void ldmx4(u32& r0, u32& r1, u32& r2, u32& r3, unsigned a){
    asm volatile("ldmatrix.sync.aligned.m8n8.x4.shared.b16 {%0,%1,%2,%3}, [%4];"
                 : "=r"(r0), "=r"(r1), "=r"(r2), "=r"(r3) : "r"(a));
}
__device__ __forceinline__ void mma16816(float* c, const u32* a, u32 b0, u32 b1){
    asm volatile(
        "mma.sync.aligned.m16n8k16.row.col.f32.bf16.bf16.f32 "
        "{%0,%1,%2,%3}, {%4,%5,%6,%7}, {%8,%9}, {%0,%1,%2,%3};"
        : "+f"(c[0]), "+f"(c[1]), "+f"(c[2]), "+f"(c[3])
        : "r"(a[0]), "r"(a[1]), "r"(a[2]), "r"(a[3]), "r"(b0), "r"(b1));
}
#endif

// ---------------------------------------------------------------------------
// Generic GEMM:  D[128 x BN] = A[128,K] . B[BN,K]^T   (BN = 128 or 256)
// DT: 1=bf16, 0=fp16 operands.  APASS: 2 = A hi/lo (3-pass), 1 = A single.
// Epilogue modes:
//   0: fp32 row-major + bias          1: bf16 hi/lo head-split + bias (staged)
//   2: fp16 hi/lo V-transpose [bsh][d][l] + bias
// ---------------------------------------------------------------------------
template<int BN, int DT, int APASS>
__global__ void __launch_bounds__(256) gemm_any(
    const u16* __restrict__ Ahi, const u16* __restrict__ Alo, size_t aZ,
    const u16* __restrict__ Bhi, const u16* __restrict__ Blo, size_t bZ,
    int K, int mode,
    float* __restrict__ outF, u16* __restrict__ oHi, u16* __restrict__ oLo,
    const float* __restrict__ aux)
{
    extern __shared__ char smem[];
    const int tid  = threadIdx.x;
    const int w    = tid >> 5;
    const int lane = tid & 31;
    const int m0   = blockIdx.y * 128;
    const int n0   = blockIdx.x * BN;
    const int z    = blockIdx.z;

    const u16* Ah = Ahi + (size_t)z * aZ;
    const u16* Al = (APASS == 2) ? (Alo + (size_t)z * aZ) : Ahi;
    const u16* Bh = Bhi + (size_t)z * bZ;
    const u16* Bl = Blo + (size_t)z * bZ;

#if HAS_TCGEN05
    constexpr int ABYT  = 128 * 128;
    constexpr int BBYT  = BN * 128;
    constexpr int BOFF  = APASS * ABYT;
    constexpr int STAGE = APASS * ABYT + 2 * BBYT;
    constexpr u32 IDESC =
        (1u << 4) | ((u32)DT << 7) | ((u32)DT << 10)
        | ((u32)(BN / 8) << 17) | (8u << 24);
    constexpr int TCOLS = BN;

    const unsigned sb   = smem_u32p(smem);
    const unsigned mb0  = sb + 8;
    const unsigned mb1  = sb + 16;
    const unsigned buf0 = sb + 1024;

    if (w == 0){ TC_ALLOC(sb, TCOLS); }
    if (tid == 0){ MBAR_INIT(mb0, 1); MBAR_INIT(mb1, 1); }
    __syncthreads();
    unsigned tmem;
    asm volatile("ld.shared.b32 %0, [%1];" : "=r"(tmem) : "r"(sb));

    const int NS = K >> 6;

    auto load_stage = [&](int s){
        const unsigned bb = buf0 + (unsigned)(s & 1) * STAGE;
        const int k0 = s << 6;
#pragma unroll
        for (int it = 0; it < 4; it++){
            int idx = tid + it * 256;
            int r = idx >> 3, c = idx & 7;
            int off = r * 128 + c * 16;
            unsigned sw = (unsigned)(off ^ ((off >> 3) & 0x70));
            size_t g = (size_t)(m0 + r) * K + k0 + c * 8;
            cpa16(bb + sw, Ah + g);
            if (APASS == 2) cpa16(bb + ABYT + sw, Al + g);
        }
#pragma unroll
        for (int it = 0; it < (BN * 8) / 256; it++){
            int idx = tid + it * 256;
            int r = idx >> 3, c = idx & 7;
            int off = r * 128 + c * 16;
            unsigned sw = (unsigned)(off ^ ((off >> 3) & 0x70));
            size_t g = (size_t)(n0 + r) * K + k0 + c * 8;
            cpa16(bb + BOFF + sw,        Bh + g);
            cpa16(bb + BOFF + BBYT + sw, Bl + g);
        }
        CPA_COMMIT();
    };

    load_stage(0);
    if (NS > 1) load_stage(1);
    unsigned ph0 = 0, ph1 = 0;

    for (int s = 0; s < NS; s++){
        if (s == NS - 1) cpa_wait<0>(); else cpa_wait<1>();
        __syncthreads();

        if (w == 0 && elect1()){
            FENCE_ASYNC();
            const unsigned bb = buf0 + (unsigned)(s & 1) * STAGE;
            u64 ah = mk_desc(bb);
            u64 al = mk_desc(bb + ABYT);
            u64 bh = mk_desc(bb + BOFF);
            u64 bl = mk_desc(bb + BOFF + BBYT);
#pragma unroll
            for (int ks = 0; ks < 4; ks++)
                mma_ss(tmem, ah + 2 * ks, bh + 2 * ks, IDESC,
                       (s > 0 || ks > 0) ? 1u : 0u);
#pragma unroll
            for (int ks = 0; ks < 4; ks++)
                mma_ss(tmem, ah + 2 * ks, bl + 2 * ks, IDESC, 1u);
            if (APASS == 2){
#pragma unroll
                for (int ks = 0; ks < 4; ks++)
                    mma_ss(tmem, al + 2 * ks, bh + 2 * ks, IDESC, 1u);
            }
            TC_COMMIT((s & 1) ? mb1 : mb0);
        }

        if (s + 2 < NS){
            if (s & 1){ mbar_wait(mb1, ph1); ph1 ^= 1; }
            else      { mbar_wait(mb0, ph0); ph0 ^= 1; }
            load_stage(s + 2);
        }
    }
    if ((NS - 1) & 1) mbar_wait(mb1, ph1);
    else              mbar_wait(mb0, ph0);
    TC_FENCE_AFTER();

    // ---- epilogue: warp covers rows sub*32..+32, cols (w>>2)*(BN/2) in 64-chunks
    const int sub = w & 3;
    const int row0 = m0 + sub * 32;
    const int row  = row0 + lane;
    u32* sbuf = (u32*)(smem + 1024) + (size_t)w * (32 * 33);

#pragma unroll
    for (int cc = 0; cc < BN / 128; cc++){
        const int cb = (w >> 2) * (BN / 2) + cc * 64;
        u32 dr[64];
        TC_LD32(dr,      tmem + cb);
        TC_LD32(dr + 32, tmem + cb + 32);
        TC_WAITLD();
        TC_FENCE_BEFORE();

        if (mode == 0){
            float* dst = outF + (size_t)row * 1024 + n0 + cb;
            const float* bias = aux + n0 + cb;
#pragma unroll
            for (int j = 0; j < 16; j++){
                float4 o;
                o.x = __uint_as_float(dr[j*4+0]) + bias[j*4+0];
                o.y = __uint_as_float(dr[j*4+1]) + bias[j*4+1];
                o.z = __uint_as_float(dr[j*4+2]) + bias[j*4+2];
                o.w = __uint_as_float(dr[j*4+3]) + bias[j*4+3];
                *(float4*)(dst + j*4) = o;
            }
        } else if (mode == 1){
            const float* bias = aux + n0 + cb;
            const int h = (n0 + cb) >> 6;
            u32 hiw[32], low[32];
#pragma unroll
            for (int j = 0; j < 32; j++){
                float va = __uint_as_float(dr[2*j])   + bias[2*j];
                float vb = __uint_as_float(dr[2*j+1]) + bias[2*j+1];
                hiw[j] = pack2(va, vb);
                low[j] = pack2(va - b2f(f2b(va)), vb - b2f(f2b(vb)));
            }
#pragma unroll
            for (int j = 0; j < 32; j++) sbuf[lane * 33 + j] = hiw[j];
            __syncwarp();
#pragma unroll
            for (int i = 0; i < 32; i++){
                int r = row0 + i, bs = r >> 10, l = r & 1023;
                size_t wb = (((size_t)(bs * 16 + h)) << 15) + ((size_t)l << 5);
                ((u32*)oHi)[wb + lane] = sbuf[i * 33 + lane];
            }
            __syncwarp();
#pragma unroll
            for (int j = 0; j < 32; j++) sbuf[lane * 33 + j] = low[j];
            __syncwarp();
#pragma unroll
            for (int i = 0; i < 32; i++){
                int r = row0 + i, bs = r >> 10, l = r & 1023;
                size_t wb = (((size_t)(bs * 16 + h)) << 15) + ((size_t)l << 5);
                ((u32*)oLo)[wb + lane] = sbuf[i * 33 + lane];
            }
        } else { // mode 2
            const int bs = row >> 10, l = row & 1023;
            const int h  = (n0 + cb) >> 6;
            const size_t base = ((size_t)(bs * 16 + h) * 64) * 1024 + l;
            const float* bias = aux + n0 + cb;
#pragma unroll
            for (int j = 0; j < 64; j++){
                float va = __uint_as_float(dr[j]) + bias[j];
                u16 hh = f2h(va);
                oHi[base + (size_t)j * 1024] = hh;
                oLo[base + (size_t)j * 1024] = f2h(va - h2f(hh));
            }
        }
        __syncwarp();
    }
    __syncthreads();
    if (tid == 0){ MBAR_INVAL(mb0); MBAR_INVAL(mb1); }
    __syncthreads();
    if (w == 0) TC_DEALLOC(tmem, TCOLS);

#else
    // ---------- mma.sync fallback (compile-only; driver picks sm_103a) -----
    constexpr int WGM = 2, WGN = 4, PITCH = 40;
    constexpr int ASZ = 128 * PITCH;
    constexpr int BSZ = BN * PITCH;
    constexpr int STAGE = 2 * ASZ + 2 * BSZ;
    constexpr int WTM = 128 / WGM;
    constexpr int WTN = BN / WGN;
    constexpr int MT = WTM / 16;
    constexpr int NT16 = WTN / 16;

    const unsigned sbase = smem_u32p(smem);
    const int wm = (w / WGN) * WTM;
    const int wn = (w % WGN) * WTN;
    const int lrow = (lane & 7) + ((lane >> 3) & 1) * 8;
    const int lcol = (lane >> 4) * 8;

    float acc[MT][NT16 * 2][4];
#pragma unroll
    for (int i = 0; i < MT; i++)
#pragma unroll
        for (int j = 0; j < NT16 * 2; j++)
#pragma unroll
            for (int t = 0; t < 4; t++) acc[i][j][t] = 0.f;

    auto load_stage = [&](int s){
        const int k0 = s << 5;
        const unsigned sd = sbase + (unsigned)((s & 1) * STAGE) * 2u;
#pragma unroll
        for (int it = 0; it < 2; it++){
            int idx = tid + it * 256;
            int r = idx >> 2, c = idx & 3;
            size_t g = (size_t)(m0 + r) * K + k0 + c * 8;
            unsigned d = sd + (unsigned)(r * PITCH + c * 8) * 2u;
            cpa16(d, Ah + g);
            cpa16(d + ASZ * 2, Al + g);
        }
#pragma unroll
        for (int it = 0; it < (BN * 4) / 256; it++){
            int idx = tid + it * 256;
            int r = idx >> 2, c = idx & 3;
            size_t g = (size_t)(n0 + r) * K + k0 + c * 8;
            unsigned d = sd + (unsigned)(2 * ASZ + r * PITCH + c * 8) * 2u;
            cpa16(d, Bh + g);
            cpa16(d + BSZ * 2, Bl + g);
        }
        CPA_COMMIT();
    };

    const int NS = K >> 5;
    load_stage(0);

    for (int s = 0; s < NS; s++){
        if (s + 1 < NS){ load_stage(s + 1); cpa_wait<1>(); }
        else           { cpa_wait<0>(); }
        __syncthreads();

        const unsigned sd = sbase + (unsigned)((s & 1) * STAGE) * 2u;
#pragma unroll
        for (int k16 = 0; k16 < 2; k16++){
            const int kc = k16 * 16 + lcol;
            u32 ah[MT][4], al[MT][4], bh[NT16][4], bl[NT16][4];
#pragma unroll
            for (int mt = 0; mt < MT; mt++){
                unsigned a = sd + (unsigned)((wm + mt * 16 + lrow) * PITCH + kc) * 2u;
                ldmx4(ah[mt][0], ah[mt][1], ah[mt][2], ah[mt][3], a);
                ldmx4(al[mt][0], al[mt][1], al[mt][2], al[mt][3], a + ASZ * 2);
            }
#pragma unroll
            for (int nt = 0; nt < NT16; nt++){
                unsigned a = sd + (unsigned)(2 * ASZ + (wn + nt * 16 + lrow) * PITCH + kc) * 2u;
                ldmx4(bh[nt][0], bh[nt][1], bh[nt][2], bh[nt][3], a);
                ldmx4(bl[nt][0], bl[nt][1], bl[nt][2], bl[nt][3], a + BSZ * 2);
            }
#pragma unroll
            for (int mt = 0; mt < MT; mt++)
#pragma unroll
                for (int nt = 0; nt < NT16; nt++){
                    mma16816(acc[mt][2*nt],   ah[mt], bh[nt][0], bh[nt][2]);
                    mma16816(acc[mt][2*nt+1], ah[mt], bh[nt][1], bh[nt][3]);
                    mma16816(acc[mt][2*nt],   ah[mt], bl[nt][0], bl[nt][2]);
                    mma16816(acc[mt][2*nt+1], ah[mt], bl[nt][1], bl[nt][3]);
                    if (APASS == 2){
                        mma16816(acc[mt][2*nt],   al[mt], bh[nt][0], bh[nt][2]);
                        mma16816(acc[mt][2*nt+1], al[mt], bh[nt][1], bh[nt][3]);
                    }
                }
        }
        __syncthreads();
    }

    auto store_pair = [&](int row, int col, float va, float vb){
        if (mode == 0){
            float2 o; o.x = va + aux[col]; o.y = vb + aux[col + 1];
            *(float2*)(outF + (size_t)row * 1024 + col) = o;
        } else if (mode == 1){
            va += aux[col]; vb += aux[col + 1];
            int bs = row >> 10, l = row & 1023, h = col >> 6, d = col & 63;
            size_t idx = (((size_t)(bs * 16 + h)) << 16) + ((size_t)l << 6) + d;
            *(u32*)(oHi + idx) = pack2(va, vb);
            *(u32*)(oLo + idx) = pack2(va - b2f(f2b(va)), vb - b2f(f2b(vb)));
        } else if (mode == 2){
            va += aux[col]; vb += aux[col + 1];
            int bs = row >> 10, l = row & 1023, h = col >> 6, d = col & 63;
            size_t base = ((size_t)(bs * 16 + h) * 64 + d) * 1024 + l;
            u16 h0 = f2h(va), h1 = f2h(vb);
            oHi[base] = h0;        oHi[base + 1024] = h1;
            oLo[base] = f2h(va - h2f(h0));
            oLo[base + 1024] = f2h(vb - h2f(h1));
        }
    };

#pragma unroll
    for (int mt = 0; mt < MT; mt++)
#pragma unroll
        for (int nt8 = 0; nt8 < NT16 * 2; nt8++){
            int r0 = m0 + wm + mt * 16 + (lane >> 2);
            int c0 = n0 + wn + nt8 * 8 + (lane & 3) * 2;
            store_pair(r0,     c0, acc[mt][nt8][0], acc[mt][nt8][1]);
            store_pair(r0 + 8, c0, acc[mt][nt8][2], acc[mt][nt8][3]);
        }
#endif
}

// ---------------------------------------------------------------------------
// Fused QK kernel, software-pipelined (unchanged from R13).
// ---------------------------------------------------------------------------
__global__ void __launch_bounds__(256) qk_tc(
    const u16* __restrict__ qhH, const u16* __restrict__ qhL,
    const u16* __restrict__ khH, const u16* __restrict__ khL)
{
    extern __shared__ char smem[];
    const int tid  = threadIdx.x;
    const int w    = tid >> 5;
    const int lane = tid & 31;
    const int m0   = blockIdx.x * 128;
    const int z    = blockIdx.y;
    const int bs   = z >> 4;

    const u16* Qh = qhH + (size_t)z * 65536;
    const u16* Ql = qhL + (size_t)z * 65536;
    const u16* Kh = khH + (size_t)z * 65536;
    const u16* Kl = khL + (size_t)z * 65536;

#if HAS_TCGEN05
    constexpr u32 IDESC =
        (1u << 4) | (1u << 7) | (1u << 10) | (16u << 17) | (8u << 24);
    constexpr unsigned SB_OFF = 1024 + 32768 + 4 * 32768;   // 164864

    const unsigned sb   = smem_u32p(smem);
    const unsigned mb0  = sb + 8;
    const unsigned mb1  = sb + 16;
    const unsigned qbuf = sb + 1024;          // Qhi 16K + Qlo 16K
    const unsigned kbuf = qbuf + 32768;       // 4 x (Khi 16K + Klo 16K)

    if (w == 0){ TC_ALLOC(sb, 256); }
    if (tid == 0){ MBAR_INIT(mb0, 1); MBAR_INIT(mb1, 1); }
    __syncthreads();
    unsigned tmem;
    asm volatile("ld.shared.b32 %0, [%1];" : "=r"(tmem) : "r"(sb));

    auto loadK = [&](int kt){
        const unsigned bb = kbuf + (unsigned)(kt & 3) * 32768;
#pragma unroll
        for (int it = 0; it < 4; it++){
            int idx = tid + it * 256;
            int r = idx >> 3, c = idx & 7;
            int off = r * 128 + c * 16;
            unsigned sw = (unsigned)(off ^ ((off >> 3) & 0x70));
            size_t g = (size_t)(kt * 128 + r) * 64 + c * 8;
            cpa16(bb + sw,         Kh + g);
            cpa16(bb + 16384 + sw, Kl + g);
        }
        CPA_COMMIT();
    };

    // group 0: Q + K0; groups 1,2: K1, K2
    {
#pragma unroll
        for (int it = 0; it < 4; it++){
            int idx = tid + it * 256;
            int r = idx >> 3, c = idx & 7;
            int off = r * 128 + c * 16;
            unsigned sw = (unsigned)(off ^ ((off >> 3) & 0x70));
            size_t g = (size_t)(m0 + r) * 64 + c * 8;
            cpa16(qbuf + sw,         Qh + g);
            cpa16(qbuf + 16384 + sw, Ql + g);
        }
#pragma unroll
        for (int it = 0; it < 4; it++){
            int idx = tid + it * 256;
            int r = idx >> 3, c = idx & 7;
            int off = r * 128 + c * 16;
            unsigned sw = (unsigned)(off ^ ((off >> 3) & 0x70));
            size_t g = (size_t)r * 64 + c * 8;
            cpa16(kbuf + sw,         Kh + g);
            cpa16(kbuf + 16384 + sw, Kl + g);
        }
        CPA_COMMIT();
        loadK(1);
        loadK(2);
    }

    const int sub = w & 3;
    const int cb  = (w >> 2) * 64;
    const int row0 = m0 + sub * 32;
    const int row  = row0 + lane;
    u32* sbuf = (u32*)(smem + SB_OFF) + (size_t)w * (32 * 33);
    float rs = 0.f;
    unsigned ph0 = 0, ph1 = 0;

    auto epilogue = [&](int j){
        u32 dr[64];
        const unsigned dt = tmem + (unsigned)(j & 1) * 128 + cb;
        TC_LD32(dr,      dt);
        TC_LD32(dr + 32, dt + 32);
        TC_WAITLD();
        TC_FENCE_BEFORE();

        const int c0 = j * 128 + cb;
        const size_t widx = ((size_t)bs << 15) + ((size_t)row << 5) + (c0 >> 5);
        const u32 w0 = g_mbits[widx];
        const u32 w1 = g_mbits[widx + 1];

        float part = 0.f;
        u32 pw[32];
#pragma unroll
        for (int jj = 0; jj < 32; jj++){
            int c = 2 * jj;
            u32 wa  = (c < 32) ? w0 : w1;
            u32 wbq = (c + 1 < 32) ? w0 : w1;
            float ea = ((wa >> (c & 31)) & 1) ? 0.f
                     : __expf(__uint_as_float(dr[2*jj]) * 0.125f);
            float eb = ((wbq >> ((c + 1) & 31)) & 1) ? 0.f
                     : __expf(__uint_as_float(dr[2*jj+1]) * 0.125f);
            part += ea + eb;
            pw[jj] = pack2h(ea, eb);
        }
        rs += part;
#pragma unroll
        for (int jj = 0; jj < 32; jj++) sbuf[lane * 33 + jj] = pw[jj];
        __syncwarp();
#pragma unroll
        for (int i = 0; i < 32; i++){
            size_t wb = ((size_t)z << 19) + ((size_t)(row0 + i) << 9)
                      + (size_t)(c0 >> 1);
            ((u32*)g_p)[wb + lane] = sbuf[i * 33 + lane];
        }
        __syncwarp();
    };

    for (int kt = 0; kt < 8; kt++){
        if (kt <= 5) cpa_wait<2>();
        else if (kt == 6) cpa_wait<1>();
        else cpa_wait<0>();
        __syncthreads();                 // buf kt visible; epilogue kt-2 done

        if (w == 0 && elect1()){
            FENCE_ASYNC();
            u64 qd  = mk_desc(qbuf);
            u64 qld = mk_desc(qbuf + 16384);
            const unsigned bb = kbuf + (unsigned)(kt & 3) * 32768;
            u64 kd  = mk_desc(bb);
            u64 kld = mk_desc(bb + 16384);
            const unsigned dst = tmem + (unsigned)(kt & 1) * 128;
#pragma unroll
            for (int ks = 0; ks < 4; ks++)
                mma_ss(dst, qd + 2 * ks, kd + 2 * ks, IDESC, ks > 0 ? 1u : 0u);
#pragma unroll
            for (int ks = 0; ks < 4; ks++)
                mma_ss(dst, qd + 2 * ks, kld + 2 * ks, IDESC, 1u);
#pragma unroll
            for (int ks = 0; ks < 4; ks++)
                mma_ss(dst, qld + 2 * ks, kd + 2 * ks, IDESC, 1u);
            TC_COMMIT((kt & 1) ? mb1 : mb0);
        }

        if (kt > 0){                     // overlap: epilogue kt-1 vs MMA kt
            if ((kt - 1) & 1){ mbar_wait(mb1, ph1); ph1 ^= 1; }
            else             { mbar_wait(mb0, ph0); ph0 ^= 1; }
            TC_FENCE_AFTER();
            epilogue(kt - 1);
            if (kt + 3 < 8) loadK(kt + 3);   // buf (kt-1)&3, freed by the wait
        } else {
            loadK(3);                        // buf 3 is fresh
        }
    }
    mbar_wait(mb1, ph1);                 // kt=7
    TC_FENCE_AFTER();
    epilogue(7);

    // combine the two column-half partial sums and write g_rsum
    __syncthreads();
    float* fs = (float*)(smem + SB_OFF);
    fs[(w >> 2) * 128 + sub * 32 + lane] = rs;
    __syncthreads();
    if (w < 4){
        int rl = w * 32 + lane;
        g_rsum[(size_t)z * 1024 + m0 + rl] = fs[rl] + fs[128 + rl];
    }
    __syncthreads();
    if (tid == 0){ MBAR_INVAL(mb0); MBAR_INVAL(mb1); }
    __syncthreads();
    if (w == 0) TC_DEALLOC(tmem, 256);

#else
    for (int idx = tid; idx < 128 * 1024; idx += 256){
        int r = m0 + (idx >> 10);
        int c = idx & 1023;
        u32 wm_ = g_mbits[((size_t)bs << 15) + ((size_t)r << 5) + (c >> 5)];
        float p = 0.f;
        if (!((wm_ >> (c & 31)) & 1)){
            float s = 0.f;
            for (int d = 0; d < 64; d++){
                float qv = b2f(Qh[(size_t)r * 64 + d]) + b2f(Ql[(size_t)r * 64 + d]);
                float kv = b2f(Kh[(size_t)c * 64 + d]) + b2f(Kl[(size_t)c * 64 + d]);
                s += qv * kv;
            }
            p = __expf(s * 0.125f);
        }
        g_p[((size_t)z << 20) + ((size_t)r << 10) + c] = f2h(p);
        atomicAdd(&g_rsum[(size_t)z * 1024 + r], p);
    }
#endif
}

// ---------------------------------------------------------------------------
// Fused PV + head-mean, 4-buffer pipelined: grid (8 q-tiles, 16 bs, 2 halves).
// Stage s: wait load s; MMA s (TMEM cols (s&7)*64); head-mean from smem
// (overlaps MMA); wait mbar s-1; prefetch s+3 into buf (s-1)&3.
// ---------------------------------------------------------------------------
__global__ void __launch_bounds__(256) pv_tc(
    float* __restrict__ attn0, float* __restrict__ attn1)
{
    extern __shared__ char smem[];
    const int tid  = threadIdx.x;
    const int w    = tid >> 5;
    const int lane = tid & 31;
    const int m0   = blockIdx.x * 128;
    const int bs   = blockIdx.y;
    const int half = blockIdx.z;
    const int zb   = bs * 16 + half * 8;

#if HAS_TCGEN05
    constexpr u32 IDESC = (1u << 4) | (8u << 17) | (8u << 24);
    constexpr unsigned SB_OFF = 1024 + 4 * 32768;     // 132096

    const unsigned sb   = smem_u32p(smem);
    const unsigned mb0  = sb + 8;
    const unsigned mb1  = sb + 16;
    const unsigned buf0 = sb + 1024;                  // 4 x 32 KB stages

    if (w == 0){ TC_ALLOC(sb, 512); }
    if (tid == 0){ MBAR_INIT(mb0, 1); MBAR_INIT(mb1, 1); }
    __syncthreads();
    unsigned tmem;
    asm volatile("ld.shared.b32 %0, [%1];" : "=r"(tmem) : "r"(sb));

    auto load_stage = [&](int s){
        const int h = s & 7, kc = s >> 3;
        const int z = zb + h;
        const unsigned bb = buf0 + (unsigned)(s & 3) * 32768;
#pragma unroll
        for (int it = 0; it < 4; it++){        // p: 128 rows x 128B
            int idx = tid + it * 256;
            int r = idx >> 3, c = idx & 7;
            int off = r * 128 + c * 16;
            unsigned sw = (unsigned)(off ^ ((off >> 3) & 0x70));
            const u16* src = g_p + ((size_t)z << 20)
                           + (size_t)(m0 + r) * 1024 + kc * 64 + c * 8;
            cpa16(bb + sw, src);
        }
#pragma unroll
        for (int it = 0; it < 2; it++){        // V hi/lo: 64 rows x 128B
            int idx = tid + it * 256;
            int r = idx >> 3, c = idx & 7;
            int off = r * 128 + c * 16;
            unsigned sw = (unsigned)(off ^ ((off >> 3) & 0x70));
            size_t g = (size_t)z * 65536 + (size_t)r * 1024 + kc * 64 + c * 8;
            cpa16(bb + 16384 + sw, g_vt_hi + g);
            cpa16(bb + 24576 + sw, g_vt_lo + g);
        }
        CPA_COMMIT();
    };

    const int ar = tid >> 1;
    const int ac = (tid & 1) * 32;
    float rv8[8];
#pragma unroll
    for (int h = 0; h < 8; h++)
        rv8[h] = g_rinv[(size_t)(zb + h) * 1024 + m0 + ar];
    float aacc[32];
#pragma unroll
    for (int j = 0; j < 32; j++) aacc[j] = 0.f;

    load_stage(0);
    load_stage(1);
    load_stage(2);
    unsigned ph0 = 0, ph1 = 0;

    for (int s = 0; s < 128; s++){
        if (s <= 125) cpa_wait<2>();
        else if (s == 126) cpa_wait<1>();
        else cpa_wait<0>();
        __syncthreads();                 // buf s visible; reads of buf s-1 done

        const int h = s & 7, kc = s >> 3;
        const unsigned bb = buf0 + (unsigned)(s & 3) * 32768;

        if (w == 0 && elect1()){
            FENCE_ASYNC();
            u64 pd = mk_desc(bb);
            u64 vh = mk_desc(bb + 16384);
            u64 vl = mk_desc(bb + 24576);
            const unsigned dst = tmem + (unsigned)h * 64;
#pragma unroll
            for (int ks = 0; ks < 4; ks++)
                mma_ss(dst, pd + 2 * ks, vh + 2 * ks, IDESC,
                       (kc > 0 || ks > 0) ? 1u : 0u);
#pragma unroll
            for (int ks = 0; ks < 4; ks++)
                mma_ss(dst, pd + 2 * ks, vl + 2 * ks, IDESC, 1u);
            TC_COMMIT((s & 1) ? mb1 : mb0);
        }

        // head-mean accumulation from the smem p tile (overlaps MMA)
        {
            const float rv = rv8[h];
#pragma unroll
            for (int g = 0; g < 4; g++){
                int off = ar * 128 + (ac + g * 8) * 2;
                unsigned sw = (unsigned)(off ^ ((off >> 3) & 0x70));
                u32 x0, x1, x2, x3;
                asm volatile("ld.shared.v4.u32 {%0,%1,%2,%3}, [%4];"
                             : "=r"(x0), "=r"(x1), "=r"(x2), "=r"(x3)
                             : "r"(bb + sw));
                aacc[g*8+0] += h2f((u16)x0) * rv;
                aacc[g*8+1] += h2f((u16)(x0 >> 16)) * rv;
                aacc[g*8+2] += h2f((u16)x1) * rv;
                aacc[g*8+3] += h2f((u16)(x1 >> 16)) * rv;
                aacc[g*8+4] += h2f((u16)x2) * rv;
                aacc[g*8+5] += h2f((u16)(x2 >> 16)) * rv;
                aacc[g*8+6] += h2f((u16)x3) * rv;
                aacc[g*8+7] += h2f((u16)(x3 >> 16)) * rv;
            }
        }
        if (h == 7){
            float* dst = (half ? attn1 : attn0)
                       + ((size_t)bs << 20) + ((size_t)(m0 + ar) << 10)
                       + kc * 64 + ac;
#pragma unroll
            for (int j4 = 0; j4 < 8; j4++){
                float4 o;
                o.x = aacc[j4*4+0] * 0.0625f;
                o.y = aacc[j4*4+1] * 0.0625f;
                o.z = aacc[j4*4+2] * 0.0625f;
                o.w = aacc[j4*4+3] * 0.0625f;
                *(float4*)(dst + j4 * 4) = o;
            }
#pragma unroll
            for (int j = 0; j < 32; j++) aacc[j] = 0.f;
        }

        if (s > 0){                      // frees buf (s-1)&3 for prefetch
            if ((s - 1) & 1){ mbar_wait(mb1, ph1); ph1 ^= 1; }
            else            { mbar_wait(mb0, ph0); ph0 ^= 1; }
        }
        if (s + 3 < 128) load_stage(s + 3);
    }
    mbar_wait(mb1, ph1);                 // s=127
    TC_FENCE_AFTER();

    // ctx epilogue: 8 heads, two warp-groups handle 4 each
    const int sub = w & 3;
    const int row0 = m0 + sub * 32;
    const int row  = row0 + lane;
    u32* sbuf = (u32*)(smem + SB_OFF) + (size_t)w * (32 * 33);

#pragma unroll
    for (int it = 0; it < 4; it++){
        const int h = (w >> 2) * 4 + it;
        u32 dr[64];
        TC_LD32(dr,      tmem + h * 64);
        TC_LD32(dr + 32, tmem + h * 64 + 32);
        TC_WAITLD();
        TC_FENCE_BEFORE();
        const float inv = g_rinv[(size_t)(zb + h) * 1024 + row];
        const int hg = half * 8 + h;
        u32 hiw[32], low[32];
#pragma unroll
        for (int j = 0; j < 32; j++){
            float va = __uint_as_float(dr[2*j])   * inv;
            float vb = __uint_as_float(dr[2*j+1]) * inv;
            hiw[j] = pack2(va, vb);
            low[j] = pack2(va - b2f(f2b(va)), vb - b2f(f2b(vb)));
        }
#pragma unroll
        for (int j = 0; j < 32; j++) sbuf[lane * 33 + j] = hiw[j];
        __syncwarp();
#pragma unroll
        for (int i = 0; i < 32; i++){
            size_t wb = (((size_t)(bs * 1024 + row0 + i)) << 9) + (size_t)hg * 32;
            ((u32*)g_ctx_hi)[wb + lane] = sbuf[i * 33 + lane];
        }
        __syncwarp();
#pragma unroll
        for (int j = 0; j < 32; j++) sbuf[lane * 33 + j] = low[j];
        __syncwarp();
#pragma unroll
        for (int i = 0; i < 32; i++){
            size_t wb = (((size_t)(bs * 1024 + row0 + i)) << 9) + (size_t)hg * 32;
            ((u32*)g_ctx_lo)[wb + lane] = sbuf[i * 33 + lane];
        }
        __syncwarp();
    }
    __syncthreads();
    if (tid == 0){ MBAR_INVAL(mb0); MBAR_INVAL(mb1); }
    __syncthreads();
    if (w == 0) TC_DEALLOC(tmem, 512);

#else
    for (int h = 0; h < 8; h++){
        const int z = zb + h;
        for (int idx = tid; idx < 128 * 64; idx += 256){
            int r = idx >> 6, d = idx & 63;
            float acc = 0.f;
            for (int k = 0; k < 1024; k++)
                acc += h2f(g_p[((size_t)z << 20) + (size_t)(m0 + r) * 1024 + k]) *
                       (h2f(g_vt_hi[(size_t)z * 65536 + (size_t)d * 1024 + k]) +
                        h2f(g_vt_lo[(size_t)z * 65536 + (size_t)d * 1024 + k]));
            float inv = g_rinv[(size_t)z * 1024 + m0 + r];
            float va = acc * inv;
            size_t o = (((size_t)(bs * 1024 + m0 + r)) << 10) + (half * 8 + h) * 64 + d;
            u16 hh = f2b(va);
            g_ctx_hi[o] = hh;
            g_ctx_lo[o] = f2b(va - b2f(hh));
        }
    }
    for (int idx = tid; idx < 128 * 1024; idx += 256){
        int r = idx >> 10, k = idx & 1023;
        float s = 0.f;
        for (int h = 0; h < 8; h++){
            const int z = zb + h;
            s += h2f(g_p[((size_t)z << 20) + (size_t)(m0 + r) * 1024 + k]) *
                 g_rinv[(size_t)z * 1024 + m0 + r];
        }
        (half ? attn1 : attn0)[((size_t)bs << 20) + ((size_t)(m0 + r) << 10) + k]
            = s * 0.0625f;
    }
#endif
}

// ---------------------------------------------------------------------------
__global__ __launch_bounds__(256) void combine_attn(float* __restrict__ am)
{
    const int i = blockIdx.x * 256 + threadIdx.x;
    float4 a = ((float4*)am)[i];
    float4 b = ((const float4*)g_attn2)[i];
    a.x += b.x; a.y += b.y; a.z += b.z; a.w += b.w;
    ((float4*)am)[i] = a;
}

// ---------------------------------------------------------------------------
__global__ __launch_bounds__(256) void mask_bits_kernel(const float* __restrict__ mask)
{
    const int warpid = (blockIdx.x * 256 + threadIdx.x) >> 5;
    const int lane = threadIdx.x & 31;
    const size_t base = (size_t)warpid * 1024;
#pragma unroll
    for (int b = 0; b < 32; b++){
        float v = mask[base + b * 32 + lane];
        u32 bits = __ballot_sync(0xFFFFFFFFu, v > 0.5f);
        if (lane == b) g_mbits[base / 32 + b] = bits;
    }
}

__global__ __launch_bounds__(256) void zero_rsum()
{
    const int i = blockIdx.x * 256 + threadIdx.x;
    ((float4*)g_rsum)[i] = make_float4(0.f, 0.f, 0.f, 0.f);
}

__global__ __launch_bounds__(256) void invert_rsum()
{
    const int i = blockIdx.x * 256 + threadIdx.x;
    g_rinv[i] = __frcp_rn(g_rsum[i]);
}

// ---------------------------------------------------------------------------
__global__ __launch_bounds__(256) void conv_act(
    const float* __restrict__ in, u16* __restrict__ hi, u16* __restrict__ lo)
{
    const int i = blockIdx.x * 256 + threadIdx.x;
    float4 v = ((const float4*)in)[i];
    u32 h0 = pack2(v.x, v.y), h1 = pack2(v.z, v.w);
    ((u32*)hi)[i * 2]     = h0;
    ((u32*)hi)[i * 2 + 1] = h1;
    ((u32*)lo)[i * 2]     = pack2(v.x - b2f((u16)h0), v.y - b2f((u16)(h0 >> 16)));
    ((u32*)lo)[i * 2 + 1] = pack2(v.z - b2f((u16)h1), v.w - b2f((u16)(h1 >> 16)));
}

// ---------------------------------------------------------------------------
__global__ __launch_bounds__(256) void conv_wT(
    const float* __restrict__ W, u16* __restrict__ hi, u16* __restrict__ lo)
{
    __shared__ float tile[32][33];
    const int tx = threadIdx.x, ty = threadIdx.y;
    const int kb = blockIdx.y * 32, nb = blockIdx.x * 32;
#pragma unroll
    for (int i = 0; i < 4; i++)
        tile[ty + i * 8][tx] = W[(size_t)(kb + ty + i * 8) * 1024 + nb + tx];
    __syncthreads();
#pragma unroll
    for (int i = 0; i < 4; i++){
        int n = nb + ty + i * 8, k = kb + tx;
        float v = tile[tx][ty + i * 8];
        u16 h = f2b(v);
        hi[(size_t)n * 1024 + k] = h;
        lo[(size_t)n * 1024 + k] = f2b(v - b2f(h));
    }
}

// ---------------------------------------------------------------------------
extern "C" void kernel_launch(void* const* d_in, const int* in_sizes, int n_in,
                              void* d_out, int out_size)
{
    const float* q    = (const float*)d_in[0];
    const float* k    = (const float*)d_in[1];
    const float* v    = (const float*)d_in[2];
    const float* mask = (const float*)d_in[3];
    const float* wq   = (const float*)d_in[4];
    const float* bq   = (const float*)d_in[5];
    const float* wk   = (const float*)d_in[6];
    const float* bk   = (const float*)d_in[7];
    const float* wv   = (const float*)d_in[8];
    const float* bv   = (const float*)d_in[9];
    const float* wo   = (const float*)d_in[10];
    const float* bo   = (const float*)d_in[11];

    float* out       = (float*)d_out;
    float* attn_mean = out + 16777216;

    u16 *wtH, *wtL, *aH, *aL, *qhH, *qhL, *khH, *khL, *vtH, *vtL, *cxH, *cxL;
    float* a2;
    cudaGetSymbolAddress((void**)&wtH, g_wt_hi);
    cudaGetSymbolAddress((void**)&wtL, g_wt_lo);
    cudaGetSymbolAddress((void**)&aH,  g_a_hi);
    cudaGetSymbolAddress((void**)&aL,  g_a_lo);
    cudaGetSymbolAddress((void**)&qhH, g_qh_hi);
    cudaGetSymbolAddress((void**)&qhL, g_qh_lo);
    cudaGetSymbolAddress((void**)&khH, g_kh_hi);
    cudaGetSymbolAddress((void**)&khL, g_kh_lo);
    cudaGetSymbolAddress((void**)&vtH, g_vt_hi);
    cudaGetSymbolAddress((void**)&vtL, g_vt_lo);
    cudaGetSymbolAddress((void**)&cxH, g_ctx_hi);
    cudaGetSymbolAddress((void**)&cxL, g_ctx_lo);
    cudaGetSymbolAddress((void**)&a2,  g_attn2);

    constexpr int SMEM_BIG = 1024 + 2 * (2 * 128 * 128 + 2 * 256 * 128); // 197632
    constexpr int SMEM_QK  = 1024 + 32768 + 4 * 32768 + 33792;           // 198656
    constexpr int SMEM_PV  = 1024 + 4 * 32768 + 33792;                   // 165888
    cudaFuncSetAttribute(gemm_any<256,1,2>,
                         cudaFuncAttributeMaxDynamicSharedMemorySize, SMEM_BIG);
    cudaFuncSetAttribute(qk_tc,
                         cudaFuncAttributeMaxDynamicSharedMemorySize, SMEM_QK);
    cudaFuncSetAttribute(pv_tc,
                         cudaFuncAttributeMaxDynamicSharedMemorySize, SMEM_PV);

    dim3 wtg(32, 32);
    dim3 wtb(32, 8);
    conv_wT<<<wtg, wtb>>>(wq, wtH + 0u,       wtL + 0u);
    conv_wT<<<wtg, wtb>>>(wk, wtH + 1048576u, wtL + 1048576u);
    conv_wT<<<wtg, wtb>>>(wv, wtH + 2097152u, wtL + 2097152u);
    conv_wT<<<wtg, wtb>>>(wo, wtH + 3145728u, wtL + 3145728u);
    mask_bits_kernel<<<2048, 256>>>(mask);
    zero_rsum<<<256, 256>>>();

    dim3 projGrid(4, 128, 1);    // BN=256

    conv_act<<<16384, 256>>>(q, aH, aL);
    gemm_any<256,1,2><<<projGrid, 256, SMEM_BIG>>>(
        aH, aL, 0, wtH + 0u, wtL + 0u, 0, 1024, 1, nullptr, qhH, qhL, bq);
    conv_act<<<16384, 256>>>(k, aH, aL);
    gemm_any<256,1,2><<<projGrid, 256, SMEM_BIG>>>(
        aH, aL, 0, wtH + 1048576u, wtL + 1048576u, 0, 1024, 1, nullptr, khH, khL, bk);
    conv_act<<<16384, 256>>>(v, aH, aL);
    gemm_any<256,1,2><<<projGrid, 256, SMEM_BIG>>>(
        aH, aL, 0, wtH + 2097152u, wtL + 2097152u, 0, 1024, 2, nullptr, vtH, vtL, bv);

    // fused QK (pipelined): probs + row sums
    qk_tc<<<dim3(8, 256), 256, SMEM_QK>>>(qhH, qhL, khH, khL);
    invert_rsum<<<1024, 256>>>();

    // fused PV + head-mean partials (4-buffer pipeline)
    pv_tc<<<dim3(8, 16, 2), 256, SMEM_PV>>>(attn_mean, a2);
    combine_attn<<<16384, 256>>>(attn_mean);

    // out projection (BN=256)
    gemm_any<256,1,2><<<projGrid, 256, SMEM_BIG>>>(
        cxH, cxL, 0, wtH + 3145728u, wtL + 3145728u, 0, 1024, 0, out, nullptr, nullptr, bo);
}